// round 2
// baseline (speedup 1.0000x reference)
#include <cuda_runtime.h>
#include <cstdint>

// Problem constants
#define BATCH 512
#define NOISE 100
#define EMBD  50
#define NCLS  10
// stage sizes
#define IN1   306          // 256 + 50
#define C1    256
#define C2    128

// ---------------- scratch (static __device__; no allocations allowed) -------
__device__ __align__(16) float g_act0[BATCH * 49 * IN1];    // [b][pos7x7][306]
__device__ __align__(16) float g_act1[BATCH * 49 * C1];     // [b][pos7x7][256]
__device__ __align__(16) float g_act2[BATCH * 196 * C2];    // [b][pos14x14][128]

__device__ __forceinline__ float lrelu(float x) { return x >= 0.f ? x : 0.3f * x; }

// =====================================================================
// Kernel A: x = concat(noise, emb[label]) @ Wd ; BN ; LReLU -> act0[:, :, 0:256]
// grid (49, 64), 256 threads. Block = one output "position" p (256 features) x 8 samples.
// =====================================================================
__global__ __launch_bounds__(256) void k_dense(
    const float* __restrict__ noise, const int* __restrict__ labels,
    const float* __restrict__ emb,   const float* __restrict__ Wd,
    const float* __restrict__ bn_g,  const float* __restrict__ bn_b,
    const float* __restrict__ bn_m,  const float* __restrict__ bn_v)
{
    __shared__ float xs[8 * 152];
    const int t  = threadIdx.x;
    const int bx = blockIdx.x;           // 0..48 -> position p
    const int b0 = blockIdx.y * 8;       // sample group

    for (int idx = t; idx < 8 * 150; idx += 256) {
        int s = idx / 150, k = idx - s * 150;
        int bb = b0 + s;
        float val = (k < NOISE) ? noise[bb * NOISE + k]
                                : emb[labels[bb] * EMBD + (k - NOISE)];
        xs[s * 152 + k] = val;
    }
    __syncthreads();

    const int j = bx * 256 + t;          // feature index 0..12543
    float acc[8];
#pragma unroll
    for (int s = 0; s < 8; s++) acc[s] = 0.f;

    for (int k = 0; k < 150; k++) {
        float w = Wd[k * 12544 + j];
#pragma unroll
        for (int s = 0; s < 8; s++) acc[s] += xs[s * 152 + k] * w;
    }

    const float sc = rsqrtf(bn_v[j] + 1e-3f) * bn_g[j];
    const float mm = bn_m[j];
    const float bb = bn_b[j];
#pragma unroll
    for (int s = 0; s < 8; s++) {
        float y = lrelu((acc[s] - mm) * sc + bb);
        g_act0[(size_t)(b0 + s) * (49 * IN1) + bx * IN1 + t] = y;
    }
}

// =====================================================================
// Kernel A2: broadcast label embedding into act0 channels 256..305
// =====================================================================
__global__ __launch_bounds__(256) void k_embfill(
    const int* __restrict__ labels, const float* __restrict__ emb)
{
    const int b = blockIdx.x;
    const int c = labels[b];
    for (int idx = threadIdx.x; idx < 49 * EMBD; idx += 256) {
        int p = idx / EMBD, e = idx - p * EMBD;
        g_act0[(size_t)b * (49 * IN1) + p * IN1 + 256 + e] = emb[c * EMBD + e];
    }
}

// =====================================================================
// Kernel B: ConvT1 (5x5, stride1 SAME == plain 5x5 correlation, pad 2), BN, LReLU
// One block per sample. Input tile transposed into smem [306][11*11] zero-padded.
// Thread tile: 4 co (tx 0..63) x up to 13 positions (ty 0..3).
// =====================================================================
#define B_IN_SH   (IN1 * 121)            // 306 x (11x11) = 37026 floats
#define B_IN_PAD  37028                  // round up to 16B boundary for float4 weights
#define B_KC      18                     // 306 = 17 * 18
#define B_W_SH    (B_KC * C1)

__global__ __launch_bounds__(256) void k_conv1(
    const int* __restrict__ labels, const float* __restrict__ K1,
    const float* __restrict__ G1,   const float* __restrict__ B1,
    const float* __restrict__ M1,   const float* __restrict__ V1)
{
    extern __shared__ float sm[];
    float* in_sh = sm;               // [306][121]
    float* w_sh  = sm + B_IN_PAD;    // [18][256], 16B-aligned
    const int b = blockIdx.x;
    const int t = threadIdx.x;
    const int c = labels[b];
    const float* K1c = K1 + (size_t)c * 25 * IN1 * C1;

    for (int i = t; i < B_IN_SH; i += 256) in_sh[i] = 0.f;
    __syncthreads();
    const float* a0 = g_act0 + (size_t)b * (49 * IN1);
    for (int idx = t; idx < 49 * IN1; idx += 256) {
        int p = idx / IN1, ch = idx - p * IN1;
        int i = p / 7, j = p - i * 7;
        in_sh[ch * 121 + (i + 2) * 11 + (j + 2)] = a0[idx];
    }

    const int tx = t & 63;           // co group: co = tx*4
    const int ty = t >> 6;           // 0..3
    const int pbase = (ty == 0) ? 0 : (13 + 12 * (ty - 1));   // 0,13,25,37
    int idxp[13];
#pragma unroll
    for (int r = 0; r < 13; r++) {
        int p = pbase + r;
        if (p > 48) idxp[r] = 0;     // dummy: reads stay in-bounds, result discarded
        else { int i = p / 7, j = p - i * 7; idxp[r] = i * 11 + j; }
    }

    float4 acc[13];
#pragma unroll
    for (int r = 0; r < 13; r++) acc[r] = make_float4(0.f, 0.f, 0.f, 0.f);

    float4* w4 = (float4*)w_sh;
    for (int dd = 0; dd < 25; dd++) {
        const int off = (dd / 5) * 11 + (dd % 5);
        for (int cc = 0; cc < 17; cc++) {
            __syncthreads();
            const float4* src = (const float4*)(K1c + (size_t)(dd * IN1 + cc * B_KC) * C1);
            for (int q = t; q < B_KC * 64; q += 256) w4[q] = src[q];
            __syncthreads();
#pragma unroll
            for (int kk = 0; kk < B_KC; kk++) {
                const float* ip = in_sh + (cc * B_KC + kk) * 121 + off;
                float4 w = w4[kk * 64 + tx];
#pragma unroll
                for (int r = 0; r < 13; r++) {
                    float a = ip[idxp[r]];
                    acc[r].x += a * w.x; acc[r].y += a * w.y;
                    acc[r].z += a * w.z; acc[r].w += a * w.w;
                }
            }
        }
    }

    const int co = tx * 4;
    float4 gg = *(const float4*)(G1 + c * C1 + co);
    float4 bb = *(const float4*)(B1 + c * C1 + co);
    float4 mm = *(const float4*)(M1 + c * C1 + co);
    float4 vv = *(const float4*)(V1 + c * C1 + co);
    float4 sc;
    sc.x = rsqrtf(vv.x + 1e-3f) * gg.x; sc.y = rsqrtf(vv.y + 1e-3f) * gg.y;
    sc.z = rsqrtf(vv.z + 1e-3f) * gg.z; sc.w = rsqrtf(vv.w + 1e-3f) * gg.w;
    float* a1 = g_act1 + (size_t)b * (49 * C1);
#pragma unroll
    for (int r = 0; r < 13; r++) {
        int p = pbase + r;
        if (p <= 48) {
            float4 y;
            y.x = lrelu((acc[r].x - mm.x) * sc.x + bb.x);
            y.y = lrelu((acc[r].y - mm.y) * sc.y + bb.y);
            y.z = lrelu((acc[r].z - mm.z) * sc.z + bb.z);
            y.w = lrelu((acc[r].w - mm.w) * sc.w + bb.w);
            *(float4*)(a1 + p * C1 + co) = y;
        }
    }
}

// =====================================================================
// Kernel C: ConvT2 (5x5, stride2 SAME), BN, LReLU -> act2 [b][14x14][128]
// Per-tap decomposition: out(2a+pi, 2b'+pj) uses in(a+si, b'+sj), si=(ddi>>1)-1.
// Input tile [256][9*9] zero-padded. Thread tile: 4 co (tx 0..31) x 7 pos (ty 0..7).
// =====================================================================
#define C_IN_SH (C1 * 81)       // 20736 floats (16B multiple)
#define C_KC    32              // 256 = 8 * 32
#define C_W_SH  (C_KC * C2)

__global__ __launch_bounds__(256) void k_conv2(
    const int* __restrict__ labels, const float* __restrict__ K2,
    const float* __restrict__ G2,   const float* __restrict__ B2,
    const float* __restrict__ M2,   const float* __restrict__ V2)
{
    extern __shared__ float sm[];
    float* in_sh = sm;               // [256][81]
    float* w_sh  = sm + C_IN_SH;     // [32][128]
    const int b = blockIdx.x;
    const int t = threadIdx.x;
    const int c = labels[b];
    const float* K2c = K2 + (size_t)c * 25 * C1 * C2;

    for (int i = t; i < C_IN_SH; i += 256) in_sh[i] = 0.f;
    __syncthreads();
    const float* a1 = g_act1 + (size_t)b * (49 * C1);
    for (int idx = t; idx < 49 * C1; idx += 256) {
        int p = idx >> 8, ch = idx & 255;
        int i = p / 7, j = p - i * 7;
        in_sh[ch * 81 + (i + 1) * 9 + (j + 1)] = a1[idx];
    }

    const int tx = t & 31;           // co = tx*4
    const int ty = t >> 5;           // 0..7
    const int co = tx * 4;
    int idxp[7];
#pragma unroll
    for (int r = 0; r < 7; r++) {
        int p = r * 8 + ty;
        if (p > 48) idxp[r] = 40;    // safe interior dummy
        else { int a = p / 7, bb2 = p - a * 7; idxp[r] = (a + 1) * 9 + (bb2 + 1); }
    }

    float4 gg = *(const float4*)(G2 + c * C2 + co);
    float4 bb = *(const float4*)(B2 + c * C2 + co);
    float4 mm = *(const float4*)(M2 + c * C2 + co);
    float4 vv = *(const float4*)(V2 + c * C2 + co);
    float4 sc;
    sc.x = rsqrtf(vv.x + 1e-3f) * gg.x; sc.y = rsqrtf(vv.y + 1e-3f) * gg.y;
    sc.z = rsqrtf(vv.z + 1e-3f) * gg.z; sc.w = rsqrtf(vv.w + 1e-3f) * gg.w;
    float* a2 = g_act2 + (size_t)b * (196 * C2);
    float4* w4 = (float4*)w_sh;

    for (int pi = 0; pi < 2; pi++) {
        for (int pj = 0; pj < 2; pj++) {
            float4 acc[7];
#pragma unroll
            for (int r = 0; r < 7; r++) acc[r] = make_float4(0.f, 0.f, 0.f, 0.f);
            const int ni = (pi == 0) ? 2 : 3;   // pi=0 -> dd odd {1,3}; pi=1 -> {0,2,4}
            const int nj = (pj == 0) ? 2 : 3;
            for (int ui = 0; ui < ni; ui++) {
                const int ddi = (pi == 0) ? (1 + 2 * ui) : (2 * ui);
                const int si = (ddi >> 1) - 1;
                for (int uj = 0; uj < nj; uj++) {
                    const int ddj = (pj == 0) ? (1 + 2 * uj) : (2 * uj);
                    const int sj = (ddj >> 1) - 1;
                    const int off = si * 9 + sj;
                    const int dd = ddi * 5 + ddj;
                    for (int cc = 0; cc < 8; cc++) {
                        __syncthreads();
                        const float4* src = (const float4*)(K2c + (size_t)(dd * C1 + cc * C_KC) * C2);
                        for (int q = t; q < C_KC * 32; q += 256) w4[q] = src[q];
                        __syncthreads();
#pragma unroll
                        for (int kk = 0; kk < C_KC; kk++) {
                            const float* ip = in_sh + (cc * C_KC + kk) * 81 + off;
                            float4 w = w4[kk * 32 + tx];
#pragma unroll
                            for (int r = 0; r < 7; r++) {
                                float a = ip[idxp[r]];
                                acc[r].x += a * w.x; acc[r].y += a * w.y;
                                acc[r].z += a * w.z; acc[r].w += a * w.w;
                            }
                        }
                    }
                }
            }
#pragma unroll
            for (int r = 0; r < 7; r++) {
                int p = r * 8 + ty;
                if (p <= 48) {
                    int a = p / 7, bb2 = p - a * 7;
                    int oi = 2 * a + pi, oj = 2 * bb2 + pj;
                    float4 y;
                    y.x = lrelu((acc[r].x - mm.x) * sc.x + bb.x);
                    y.y = lrelu((acc[r].y - mm.y) * sc.y + bb.y);
                    y.z = lrelu((acc[r].z - mm.z) * sc.z + bb.z);
                    y.w = lrelu((acc[r].w - mm.w) * sc.w + bb.w);
                    *(float4*)(a2 + (oi * 14 + oj) * C2 + co) = y;
                }
            }
        }
    }
}

// =====================================================================
// Kernel D: ConvT3 (5x5, stride2 SAME, 128->1), tanh -> out [b][28][28][1]
// =====================================================================
#define D_IN_SH (196 * C2)      // 25088 floats (16B multiple)
#define D_W_SH  (25 * C2)

__global__ __launch_bounds__(256) void k_conv3(
    const int* __restrict__ labels, const float* __restrict__ K3,
    float* __restrict__ out)
{
    extern __shared__ float sm[];
    float4* in4 = (float4*)sm;                 // [196*32]
    float4* w4s = (float4*)(sm + D_IN_SH);     // [25*32]
    const int b = blockIdx.x;
    const int t = threadIdx.x;
    const int c = labels[b];

    const float4* a2 = (const float4*)(g_act2 + (size_t)b * (196 * C2));
    for (int q = t; q < 196 * 32; q += 256) in4[q] = a2[q];
    const float4* k4 = (const float4*)(K3 + (size_t)c * 25 * C2);
    for (int q = t; q < 25 * 32; q += 256) w4s[q] = k4[q];
    __syncthreads();

    for (int px = t; px < 784; px += 256) {
        const int oi = px / 28, oj = px - oi * 28;
        float acc = 0.f;
        for (int ddi = (oi & 1) ? 0 : 1; ddi < 5; ddi += 2) {
            int ii = (oi + ddi - 3) >> 1;           // even value -> exact
            if ((unsigned)ii >= 14u) continue;
            for (int ddj = (oj & 1) ? 0 : 1; ddj < 5; ddj += 2) {
                int jj = (oj + ddj - 3) >> 1;
                if ((unsigned)jj >= 14u) continue;
                const float4* ip = in4 + (ii * 14 + jj) * 32;
                const float4* wp = w4s + (ddi * 5 + ddj) * 32;
#pragma unroll 8
                for (int q = 0; q < 32; q++) {
                    float4 a = ip[q], w = wp[q];
                    acc += a.x * w.x + a.y * w.y + a.z * w.z + a.w * w.w;
                }
            }
        }
        out[(size_t)b * 784 + px] = tanhf(acc);
    }
}

// =====================================================================
extern "C" void kernel_launch(void* const* d_in, const int* in_sizes, int n_in,
                              void* d_out, int out_size)
{
    const float* noise = (const float*)d_in[0];
    const int*   labels= (const int*)  d_in[1];
    const float* emb   = (const float*)d_in[2];
    const float* Wd    = (const float*)d_in[3];
    const float* bn1g  = (const float*)d_in[4];
    const float* bn1b  = (const float*)d_in[5];
    const float* bn1m  = (const float*)d_in[6];
    const float* bn1v  = (const float*)d_in[7];
    const float* K1    = (const float*)d_in[8];
    const float* G1    = (const float*)d_in[9];
    const float* B1    = (const float*)d_in[10];
    const float* M1    = (const float*)d_in[11];
    const float* V1    = (const float*)d_in[12];
    const float* K2    = (const float*)d_in[13];
    const float* G2    = (const float*)d_in[14];
    const float* B2    = (const float*)d_in[15];
    const float* M2    = (const float*)d_in[16];
    const float* V2    = (const float*)d_in[17];
    const float* K3    = (const float*)d_in[18];
    float* out = (float*)d_out;

    const int smB = (B_IN_PAD + B_W_SH) * 4;
    const int smC = (C_IN_SH + C_W_SH) * 4;
    const int smD = (D_IN_SH + D_W_SH) * 4;
    cudaFuncSetAttribute(k_conv1, cudaFuncAttributeMaxDynamicSharedMemorySize, smB);
    cudaFuncSetAttribute(k_conv2, cudaFuncAttributeMaxDynamicSharedMemorySize, smC);
    cudaFuncSetAttribute(k_conv3, cudaFuncAttributeMaxDynamicSharedMemorySize, smD);

    k_dense<<<dim3(49, 64), 256>>>(noise, labels, emb, Wd, bn1g, bn1b, bn1m, bn1v);
    k_embfill<<<BATCH, 256>>>(labels, emb);
    k_conv1<<<BATCH, 256, smB>>>(labels, K1, G1, B1, M1, V1);
    k_conv2<<<BATCH, 256, smC>>>(labels, K2, G2, B2, M2, V2);
    k_conv3<<<BATCH, 256, smD>>>(labels, K3, out);
}

// round 3
// speedup vs baseline: 1.1682x; 1.1682x over previous
#include <cuda_runtime.h>
#include <cstdint>

#define BATCH 512
#define NOISE 100
#define EMBD  50
#define NCLS  10
#define IN1   306
#define C1    256
#define C2    128

typedef unsigned long long ull;

// ---------------- scratch ----------------
__device__ __align__(16) float g_act0[BATCH * 49 * IN1];
__device__ __align__(16) float g_act1[BATCH * 49 * C1];
__device__ __align__(16) float g_act2[BATCH * 196 * C2];

__device__ __forceinline__ float lrelu(float x) { return x >= 0.f ? x : 0.3f * x; }

// ---------------- f32x2 helpers ----------------
__device__ __forceinline__ ull splat2(float a) {
    ull d; unsigned ai = __float_as_uint(a);
    asm("mov.b64 %0, {%1, %1};" : "=l"(d) : "r"(ai));
    return d;
}
__device__ __forceinline__ void ffma2(ull& c, ull a, ull b) {
    asm("fma.rn.f32x2 %0, %1, %2, %3;" : "=l"(c) : "l"(a), "l"(b), "l"(c));
}
__device__ __forceinline__ float2 unpk(ull v) {
    unsigned lo, hi;
    asm("mov.b64 {%0, %1}, %2;" : "=r"(lo), "=r"(hi) : "l"(v));
    return make_float2(__uint_as_float(lo), __uint_as_float(hi));
}

// ---------------- cp.async helpers ----------------
__device__ __forceinline__ void stage_async(float* dst, const float* src, int t, int n_f4, int nthr) {
    uint32_t s0 = (uint32_t)__cvta_generic_to_shared(dst);
    for (int q = t; q < n_f4; q += nthr) {
        asm volatile("cp.async.cg.shared.global [%0], [%1], 16;"
                     :: "r"(s0 + q * 16), "l"(src + q * 4) : "memory");
    }
}
#define CP_COMMIT() asm volatile("cp.async.commit_group;" ::: "memory")
#define CP_WAIT1()  asm volatile("cp.async.wait_group 1;" ::: "memory")
#define CP_WAIT0()  asm volatile("cp.async.wait_group 0;" ::: "memory")

// =====================================================================
// Kernel A: dense + BN + LReLU -> act0[:, :, 0:256]
// =====================================================================
__global__ __launch_bounds__(256) void k_dense(
    const float* __restrict__ noise, const int* __restrict__ labels,
    const float* __restrict__ emb,   const float* __restrict__ Wd,
    const float* __restrict__ bn_g,  const float* __restrict__ bn_b,
    const float* __restrict__ bn_m,  const float* __restrict__ bn_v)
{
    __shared__ float xs[8 * 152];
    const int t  = threadIdx.x;
    const int bx = blockIdx.x;
    const int b0 = blockIdx.y * 8;

    for (int idx = t; idx < 8 * 150; idx += 256) {
        int s = idx / 150, k = idx - s * 150;
        int bb = b0 + s;
        float val = (k < NOISE) ? noise[bb * NOISE + k]
                                : emb[labels[bb] * EMBD + (k - NOISE)];
        xs[s * 152 + k] = val;
    }
    __syncthreads();

    const int j = bx * 256 + t;
    float acc[8];
#pragma unroll
    for (int s = 0; s < 8; s++) acc[s] = 0.f;

    for (int k = 0; k < 150; k++) {
        float w = Wd[k * 12544 + j];
#pragma unroll
        for (int s = 0; s < 8; s++) acc[s] += xs[s * 152 + k] * w;
    }

    const float sc = rsqrtf(bn_v[j] + 1e-3f) * bn_g[j];
    const float mm = bn_m[j];
    const float bb = bn_b[j];
#pragma unroll
    for (int s = 0; s < 8; s++) {
        float y = lrelu((acc[s] - mm) * sc + bb);
        g_act0[(size_t)(b0 + s) * (49 * IN1) + bx * IN1 + t] = y;
    }
}

__global__ __launch_bounds__(256) void k_embfill(
    const int* __restrict__ labels, const float* __restrict__ emb)
{
    const int b = blockIdx.x;
    const int c = labels[b];
    for (int idx = threadIdx.x; idx < 49 * EMBD; idx += 256) {
        int p = idx / EMBD, e = idx - p * EMBD;
        g_act0[(size_t)b * (49 * IN1) + p * IN1 + 256 + e] = emb[c * EMBD + e];
    }
}

// =====================================================================
// Kernel B: ConvT1 (5x5 s1 SAME), BN, LReLU.  512 thr/CTA.
// in_sh [306][50] (col 49 = zero sentinel), weights double-buffered 18x256.
// Warp-groups ty=0..6 handle output rows ty (7 cols each); ty==7 helps staging only.
// =====================================================================
#define B_CH   50
#define B_INSH (IN1 * B_CH)        // 15300 floats
#define B_KC   18
#define B_WCH  (B_KC * C1)         // 4608 floats

__global__ __launch_bounds__(512) void k_conv1(
    const int* __restrict__ labels, const float* __restrict__ K1,
    const float* __restrict__ G1,   const float* __restrict__ B1,
    const float* __restrict__ M1,   const float* __restrict__ V1)
{
    extern __shared__ float sm[];
    float* in_sh = sm;                  // [306][50]
    float* w_sh  = sm + B_INSH;         // 2 x [18][256]
    const int b = blockIdx.x;
    const int t = threadIdx.x;
    const int c = labels[b];
    const float* K1c = K1 + (size_t)c * 25 * IN1 * C1;

    for (int i = t; i < B_INSH; i += 512) in_sh[i] = 0.f;
    __syncthreads();
    const float* a0 = g_act0 + (size_t)b * (49 * IN1);
    for (int idx = t; idx < 49 * IN1; idx += 512) {
        int p = idx / IN1, ch = idx - p * IN1;
        in_sh[ch * B_CH + p] = a0[idx];
    }

    const int tx = t & 63;              // co = tx*4
    const int ty = t >> 6;              // 0..7
    const bool active = (ty < 7);

    ull acc01[7], acc23[7];
#pragma unroll
    for (int r = 0; r < 7; r++) { acc01[r] = 0ull; acc23[r] = 0ull; }

    int ddi = 0, ddj = 0;
    for (int dd = 0; dd < 25; dd++) {
        const int ii = ty + ddi - 2;
        const bool rowok = active && ((unsigned)ii < 7u);
        int idxe[7];
#pragma unroll
        for (int r = 0; r < 7; r++) {
            int jj = r + ddj - 2;
            idxe[r] = ((unsigned)jj < 7u) ? (ii * 7 + jj) : 49;
        }
        const float* Kdd = K1c + (size_t)dd * IN1 * C1;

        stage_async(w_sh, Kdd, t, B_WCH / 4, 512);
        CP_COMMIT();
        for (int cc = 0; cc < 17; cc++) {
            if (cc + 1 < 17) {
                stage_async(w_sh + ((cc + 1) & 1) * B_WCH, Kdd + (cc + 1) * B_KC * C1,
                            t, B_WCH / 4, 512);
                CP_COMMIT();
                CP_WAIT1();
            } else {
                CP_WAIT0();
            }
            __syncthreads();
            if (rowok) {
                const float* inb = in_sh + cc * B_KC * B_CH;
                const float* wb  = w_sh + (cc & 1) * B_WCH + tx * 4;
#pragma unroll
                for (int kk = 0; kk < B_KC; kk++) {
                    const float* ip = inb + kk * B_CH;
                    ull w01 = *(const ull*)(wb + kk * C1);
                    ull w23 = *(const ull*)(wb + kk * C1 + 2);
#pragma unroll
                    for (int r = 0; r < 7; r++) {
                        ull a = splat2(ip[idxe[r]]);
                        ffma2(acc01[r], a, w01);
                        ffma2(acc23[r], a, w23);
                    }
                }
            }
            __syncthreads();
        }
        if (++ddj == 5) { ddj = 0; ++ddi; }
    }

    if (active) {
        const int co = tx * 4;
        float4 gg = *(const float4*)(G1 + c * C1 + co);
        float4 bb = *(const float4*)(B1 + c * C1 + co);
        float4 mm = *(const float4*)(M1 + c * C1 + co);
        float4 vv = *(const float4*)(V1 + c * C1 + co);
        float4 sc;
        sc.x = rsqrtf(vv.x + 1e-3f) * gg.x; sc.y = rsqrtf(vv.y + 1e-3f) * gg.y;
        sc.z = rsqrtf(vv.z + 1e-3f) * gg.z; sc.w = rsqrtf(vv.w + 1e-3f) * gg.w;
        float* a1 = g_act1 + (size_t)b * (49 * C1);
#pragma unroll
        for (int r = 0; r < 7; r++) {
            int p = ty * 7 + r;
            float2 v01 = unpk(acc01[r]);
            float2 v23 = unpk(acc23[r]);
            float4 y;
            y.x = lrelu((v01.x - mm.x) * sc.x + bb.x);
            y.y = lrelu((v01.y - mm.y) * sc.y + bb.y);
            y.z = lrelu((v23.x - mm.z) * sc.z + bb.z);
            y.w = lrelu((v23.y - mm.w) * sc.w + bb.w);
            *(float4*)(a1 + p * C1 + co) = y;
        }
    }
}

// =====================================================================
// Kernel C: ConvT2 (5x5 s2 SAME), BN, LReLU. 512 thr/CTA, 2 CTAs/SM.
// in_sh [256][50] sentinel. tx=0..31 (co=tx*4), g=0..15; pos p=r*16+g,
// r<3 for all warps, r=3 only for g==0 (49 exact, zero waste).
// =====================================================================
#define C2CH   50
#define C_INSH (C1 * C2CH)          // 12800 floats
#define C_KC   32
#define C_WCH  (C_KC * C2)          // 4096 floats

__global__ __launch_bounds__(512, 2) void k_conv2(
    const int* __restrict__ labels, const float* __restrict__ K2,
    const float* __restrict__ G2,   const float* __restrict__ B2,
    const float* __restrict__ M2,   const float* __restrict__ V2)
{
    extern __shared__ float sm[];
    float* in_sh = sm;                  // [256][50]
    float* w_sh  = sm + C_INSH;         // 2 x [32][128]
    const int b = blockIdx.x;
    const int t = threadIdx.x;
    const int c = labels[b];
    const float* K2c = K2 + (size_t)c * 25 * C1 * C2;

    for (int i = t; i < C_INSH; i += 512) in_sh[i] = 0.f;
    __syncthreads();
    const float* a1 = g_act1 + (size_t)b * (49 * C1);
    for (int idx = t; idx < 49 * C1; idx += 512) {
        int p = idx >> 8, ch = idx & 255;
        in_sh[ch * C2CH + p] = a1[idx];
    }

    const int tx = t & 31;              // co = tx*4
    const int g  = t >> 5;              // 0..15
    const bool g0 = (g == 0);
    const int co = tx * 4;

    float4 gg = *(const float4*)(G2 + c * C2 + co);
    float4 bb = *(const float4*)(B2 + c * C2 + co);
    float4 mm = *(const float4*)(M2 + c * C2 + co);
    float4 vv = *(const float4*)(V2 + c * C2 + co);
    float4 sc;
    sc.x = rsqrtf(vv.x + 1e-3f) * gg.x; sc.y = rsqrtf(vv.y + 1e-3f) * gg.y;
    sc.z = rsqrtf(vv.z + 1e-3f) * gg.z; sc.w = rsqrtf(vv.w + 1e-3f) * gg.w;
    float* a2 = g_act2 + (size_t)b * (196 * C2);

    for (int pi = 0; pi < 2; pi++) {
        for (int pj = 0; pj < 2; pj++) {
            ull acc01[4], acc23[4];
#pragma unroll
            for (int r = 0; r < 4; r++) { acc01[r] = 0ull; acc23[r] = 0ull; }
            const int ni = (pi == 0) ? 2 : 3;
            const int nj = (pj == 0) ? 2 : 3;
            for (int ui = 0; ui < ni; ui++) {
                const int ddi = (pi == 0) ? (1 + 2 * ui) : (2 * ui);
                const int si = (ddi >> 1) - 1;
                for (int uj = 0; uj < nj; uj++) {
                    const int ddj = (pj == 0) ? (1 + 2 * uj) : (2 * uj);
                    const int sj = (ddj >> 1) - 1;
                    const int dd = ddi * 5 + ddj;
                    int idxe[4];
#pragma unroll
                    for (int r = 0; r < 4; r++) {
                        int p = r * 16 + g;
                        if (p > 48) { idxe[r] = 49; continue; }
                        int i = p / 7, j = p - i * 7;
                        int ii = i + si, jj = j + sj;
                        idxe[r] = ((unsigned)ii < 7u && (unsigned)jj < 7u) ? (ii * 7 + jj) : 49;
                    }
                    const float* Kdd = K2c + (size_t)dd * C1 * C2;

                    stage_async(w_sh, Kdd, t, C_WCH / 4, 512);
                    CP_COMMIT();
                    for (int cc = 0; cc < 8; cc++) {
                        if (cc + 1 < 8) {
                            stage_async(w_sh + ((cc + 1) & 1) * C_WCH,
                                        Kdd + (cc + 1) * C_KC * C2, t, C_WCH / 4, 512);
                            CP_COMMIT();
                            CP_WAIT1();
                        } else {
                            CP_WAIT0();
                        }
                        __syncthreads();
                        {
                            const float* inb = in_sh + cc * C_KC * C2CH;
                            const float* wb  = w_sh + (cc & 1) * C_WCH + tx * 4;
#pragma unroll
                            for (int kk = 0; kk < C_KC; kk++) {
                                const float* ip = inb + kk * C2CH;
                                ull w01 = *(const ull*)(wb + kk * C2);
                                ull w23 = *(const ull*)(wb + kk * C2 + 2);
#pragma unroll
                                for (int r = 0; r < 3; r++) {
                                    ull a = splat2(ip[idxe[r]]);
                                    ffma2(acc01[r], a, w01);
                                    ffma2(acc23[r], a, w23);
                                }
                            }
                            if (g0) {
#pragma unroll
                                for (int kk = 0; kk < C_KC; kk++) {
                                    const float* ip = inb + kk * C2CH;
                                    ull w01 = *(const ull*)(wb + kk * C2);
                                    ull w23 = *(const ull*)(wb + kk * C2 + 2);
                                    ull a = splat2(ip[idxe[3]]);
                                    ffma2(acc01[3], a, w01);
                                    ffma2(acc23[3], a, w23);
                                }
                            }
                        }
                        __syncthreads();
                    }
                }
            }
            const int rmax = g0 ? 4 : 3;
            for (int r = 0; r < rmax; r++) {
                int p = r * 16 + g;
                int i = p / 7, j = p - i * 7;
                int oi = 2 * i + pi, oj = 2 * j + pj;
                float2 v01 = unpk(acc01[r]);
                float2 v23 = unpk(acc23[r]);
                float4 y;
                y.x = lrelu((v01.x - mm.x) * sc.x + bb.x);
                y.y = lrelu((v01.y - mm.y) * sc.y + bb.y);
                y.z = lrelu((v23.x - mm.z) * sc.z + bb.z);
                y.w = lrelu((v23.y - mm.w) * sc.w + bb.w);
                *(float4*)(a2 + (oi * 14 + oj) * C2 + co) = y;
            }
        }
    }
}

// =====================================================================
// Kernel D: ConvT3 (5x5 s2, 128->1), tanh
// =====================================================================
#define D_IN_SH (196 * C2)
#define D_W_SH  (25 * C2)

__global__ __launch_bounds__(256) void k_conv3(
    const int* __restrict__ labels, const float* __restrict__ K3,
    float* __restrict__ out)
{
    extern __shared__ float sm[];
    float4* in4 = (float4*)sm;
    float4* w4s = (float4*)(sm + D_IN_SH);
    const int b = blockIdx.x;
    const int t = threadIdx.x;
    const int c = labels[b];

    const float4* a2 = (const float4*)(g_act2 + (size_t)b * (196 * C2));
    for (int q = t; q < 196 * 32; q += 256) in4[q] = a2[q];
    const float4* k4 = (const float4*)(K3 + (size_t)c * 25 * C2);
    for (int q = t; q < 25 * 32; q += 256) w4s[q] = k4[q];
    __syncthreads();

    for (int px = t; px < 784; px += 256) {
        const int oi = px / 28, oj = px - oi * 28;
        float acc = 0.f;
        for (int ddi = (oi & 1) ? 0 : 1; ddi < 5; ddi += 2) {
            int ii = (oi + ddi - 3) >> 1;
            if ((unsigned)ii >= 14u) continue;
            for (int ddj = (oj & 1) ? 0 : 1; ddj < 5; ddj += 2) {
                int jj = (oj + ddj - 3) >> 1;
                if ((unsigned)jj >= 14u) continue;
                const float4* ip = in4 + (ii * 14 + jj) * 32;
                const float4* wp = w4s + (ddi * 5 + ddj) * 32;
#pragma unroll 8
                for (int q = 0; q < 32; q++) {
                    float4 a = ip[q], w = wp[q];
                    acc += a.x * w.x + a.y * w.y + a.z * w.z + a.w * w.w;
                }
            }
        }
        out[(size_t)b * 784 + px] = tanhf(acc);
    }
}

// =====================================================================
extern "C" void kernel_launch(void* const* d_in, const int* in_sizes, int n_in,
                              void* d_out, int out_size)
{
    const float* noise = (const float*)d_in[0];
    const int*   labels= (const int*)  d_in[1];
    const float* emb   = (const float*)d_in[2];
    const float* Wd    = (const float*)d_in[3];
    const float* bn1g  = (const float*)d_in[4];
    const float* bn1b  = (const float*)d_in[5];
    const float* bn1m  = (const float*)d_in[6];
    const float* bn1v  = (const float*)d_in[7];
    const float* K1    = (const float*)d_in[8];
    const float* G1    = (const float*)d_in[9];
    const float* B1    = (const float*)d_in[10];
    const float* M1    = (const float*)d_in[11];
    const float* V1    = (const float*)d_in[12];
    const float* K2    = (const float*)d_in[13];
    const float* G2    = (const float*)d_in[14];
    const float* B2    = (const float*)d_in[15];
    const float* M2    = (const float*)d_in[16];
    const float* V2    = (const float*)d_in[17];
    const float* K3    = (const float*)d_in[18];
    float* out = (float*)d_out;

    const int smB = (B_INSH + 2 * B_WCH) * 4;      // 98,064 B
    const int smC = (C_INSH + 2 * C_WCH) * 4;      // 83,968 B
    const int smD = (D_IN_SH + D_W_SH) * 4;        // 113,152 B
    cudaFuncSetAttribute(k_conv1, cudaFuncAttributeMaxDynamicSharedMemorySize, smB);
    cudaFuncSetAttribute(k_conv2, cudaFuncAttributeMaxDynamicSharedMemorySize, smC);
    cudaFuncSetAttribute(k_conv3, cudaFuncAttributeMaxDynamicSharedMemorySize, smD);

    k_dense<<<dim3(49, 64), 256>>>(noise, labels, emb, Wd, bn1g, bn1b, bn1m, bn1v);
    k_embfill<<<BATCH, 256>>>(labels, emb);
    k_conv1<<<BATCH, 512, smB>>>(labels, K1, G1, B1, M1, V1);
    k_conv2<<<BATCH, 512, smC>>>(labels, K2, G2, B2, M2, V2);
    k_conv3<<<BATCH, 256, smD>>>(labels, K3, out);
}

// round 4
// speedup vs baseline: 2.2055x; 1.8879x over previous
#include <cuda_runtime.h>
#include <cstdint>

#define BATCH 512
#define NOISE 100
#define EMBD  50
#define NCLS  10
#define C0    256      // conv1 real input channels (emb folded out)
#define C1    256
#define C2    128

typedef unsigned long long ull;

// ---------------- scratch ----------------
__device__ __align__(16) float g_act0[BATCH * 49 * C0];    // [b][pos7x7][256]
__device__ __align__(16) float g_act1[BATCH * 49 * C1];
__device__ __align__(16) float g_act2[BATCH * 196 * C2];
__device__ __align__(16) float g_embf[NCLS * 49 * C1];     // per-class conv1 emb bias field
__device__ int g_perm[BATCH];
__device__ int g_cnt[NCLS];
__device__ int g_off[NCLS];

__device__ __forceinline__ float lrelu(float x) { return x >= 0.f ? x : 0.3f * x; }

__device__ __forceinline__ void ffma2(ull& c, ull a, ull b) {
    asm("fma.rn.f32x2 %0, %1, %2, %3;" : "=l"(c) : "l"(a), "l"(b), "l"(c));
}
__device__ __forceinline__ float2 unpk(ull v) {
    unsigned lo, hi;
    asm("mov.b64 {%0, %1}, %2;" : "=r"(lo), "=r"(hi) : "l"(v));
    return make_float2(__uint_as_float(lo), __uint_as_float(hi));
}

#define CP_COMMIT() asm volatile("cp.async.commit_group;" ::: "memory")
#define CP_WAIT1()  asm volatile("cp.async.wait_group 1;" ::: "memory")
#define CP_WAIT0()  asm volatile("cp.async.wait_group 0;" ::: "memory")

// stage 16 rows x 128 floats, global row stride RS floats (448 threads)
__device__ __forceinline__ void stage_w(float* dst, const float* src, int t, int rs) {
    uint32_t d0 = (uint32_t)__cvta_generic_to_shared(dst);
    for (int q = t; q < 512; q += 448) {
        int r = q >> 5, cv = q & 31;
        asm volatile("cp.async.cg.shared.global [%0], [%1], 16;"
                     :: "r"(d0 + (uint32_t)(r * 128 + cv * 4) * 4u),
                        "l"(src + (size_t)r * rs + cv * 4) : "memory");
    }
}

// ---------------- core FMA stage: 16 k x 14 m x 4 co per thread ----------------
// in_sh packed [s][POS][16ci]; w_sh [16][128]
__device__ __forceinline__ void stage_compute(
    const float* __restrict__ in_sh, const float* __restrict__ wst, int lane,
    ull* __restrict__ a01, ull* __restrict__ a23, int base0, int base1)
{
#pragma unroll
    for (int kp = 0; kp < 8; kp++) {
        const float* wr = wst + kp * 256 + lane * 4;
        ulonglong2 wv0 = *(const ulonglong2*)(wr);        // k=2kp,   co {0,1},{2,3}
        ulonglong2 wv1 = *(const ulonglong2*)(wr + 128);  // k=2kp+1
#pragma unroll
        for (int r = 0; r < 2; r++) {
            const float* ib = in_sh + (r ? base1 : base0) + kp * 2;
#pragma unroll
            for (int jx = 0; jx < 7; jx++) {
                ull av = *(const ull*)(ib + jx * 16);
                unsigned lo, hi;
                asm("mov.b64 {%0, %1}, %2;" : "=r"(lo), "=r"(hi) : "l"(av));
                ull s0, s1;
                asm("mov.b64 %0, {%1, %1};" : "=l"(s0) : "r"(lo));
                asm("mov.b64 %0, {%1, %1};" : "=l"(s1) : "r"(hi));
                int j = r * 7 + jx;
                ffma2(a01[j], s0, wv0.x);
                ffma2(a23[j], s0, wv0.y);
                ffma2(a01[j], s1, wv1.x);
                ffma2(a23[j], s1, wv1.y);
            }
        }
    }
}

// =====================================================================
// bucket samples by class
// =====================================================================
__global__ __launch_bounds__(512) void k_bucket(const int* __restrict__ labels)
{
    __shared__ int scnt[NCLS], scur[NCLS];
    int t = threadIdx.x;
    if (t < NCLS) scnt[t] = 0;
    __syncthreads();
    int c = labels[t];
    atomicAdd(&scnt[c], 1);
    __syncthreads();
    if (t == 0) {
        int run = 0;
        for (int k = 0; k < NCLS; k++) {
            g_off[k] = run; scur[k] = run; g_cnt[k] = scnt[k]; run += scnt[k];
        }
    }
    __syncthreads();
    int pos = atomicAdd(&scur[c], 1);
    g_perm[pos] = t;
}

// =====================================================================
// per-class embedding bias field for conv1: E[c][p][co]
// =====================================================================
__global__ __launch_bounds__(256) void k_embconv(
    const float* __restrict__ K1, const float* __restrict__ emb)
{
    __shared__ float es[EMBD];
    int p = blockIdx.x, c = blockIdx.y, t = threadIdx.x;
    if (t < EMBD) es[t] = emb[c * EMBD + t];
    __syncthreads();
    int i = p / 7, jx = p - 7 * i;
    float acc = 0.f;
    for (int di = 0; di < 5; di++) {
        int ii = i + di - 2; if ((unsigned)ii >= 7u) continue;
        for (int dj = 0; dj < 5; dj++) {
            int jj = jx + dj - 2; if ((unsigned)jj >= 7u) continue;
            const float* kb = K1 + (((size_t)c * 25 + di * 5 + dj) * 306 + 256) * 256 + t;
#pragma unroll 10
            for (int e = 0; e < EMBD; e++) acc += kb[(size_t)e * 256] * es[e];
        }
    }
    g_embf[((size_t)c * 49 + p) * 256 + t] = acc;
}

// =====================================================================
// dense + BN + LReLU -> act0 [b][49][256]
// =====================================================================
__global__ __launch_bounds__(256) void k_dense(
    const float* __restrict__ noise, const int* __restrict__ labels,
    const float* __restrict__ emb,   const float* __restrict__ Wd,
    const float* __restrict__ bn_g,  const float* __restrict__ bn_b,
    const float* __restrict__ bn_m,  const float* __restrict__ bn_v)
{
    __shared__ float xs[8 * 152];
    const int t  = threadIdx.x;
    const int bx = blockIdx.x;
    const int b0 = blockIdx.y * 8;

    for (int idx = t; idx < 8 * 150; idx += 256) {
        int s = idx / 150, k = idx - s * 150;
        int bb = b0 + s;
        float val = (k < NOISE) ? noise[bb * NOISE + k]
                                : emb[labels[bb] * EMBD + (k - NOISE)];
        xs[s * 152 + k] = val;
    }
    __syncthreads();

    const int j = bx * 256 + t;
    float acc[8];
#pragma unroll
    for (int s = 0; s < 8; s++) acc[s] = 0.f;

    for (int k = 0; k < 150; k++) {
        float w = Wd[k * 12544 + j];
#pragma unroll
        for (int s = 0; s < 8; s++) acc[s] += xs[s * 152 + k] * w;
    }

    const float sc = rsqrtf(bn_v[j] + 1e-3f) * bn_g[j];
    const float mm = bn_m[j];
    const float bb = bn_b[j];
#pragma unroll
    for (int s = 0; s < 8; s++) {
        float y = lrelu((acc[s] - mm) * sc + bb);
        g_act0[(size_t)(b0 + s) * (49 * C0) + bx * 256 + t] = y;
    }
}

// =====================================================================
// conv1: 5x5 s1 SAME over 256 ci (emb folded into E), 4 samples/CTA, 128 co tile
// =====================================================================
#define B_INSH (4 * 121 * 16)      // 7744 floats
#define B_WBUF 2048                // 16 x 128

__global__ __launch_bounds__(448, 1) void k_conv1(
    const float* __restrict__ K1,
    const float* __restrict__ G1, const float* __restrict__ B1,
    const float* __restrict__ M1, const float* __restrict__ V1)
{
    extern __shared__ float sm[];
    float* in_sh = sm;                         // [4][121][16]
    float* w_sh  = sm + B_INSH;                // [2][16][128]
    const int c = blockIdx.z;
    const int n_c = g_cnt[c];
    const int stile = blockIdx.x;
    if (stile * 4 >= n_c) return;
    const int co0 = blockIdx.y * 128;
    const int t = threadIdx.x;
    const int lane = t & 31;
    const int mg = t >> 5;                     // 0..13
    const int base = g_off[c];

    int samp[4]; bool sok[4];
#pragma unroll
    for (int s = 0; s < 4; s++) {
        int idx = stile * 4 + s;
        sok[s] = idx < n_c;
        samp[s] = g_perm[base + (idx < n_c ? idx : n_c - 1)];
    }

    const int row0 = 2 * mg, row1 = row0 + 1;
    const int s0 = row0 / 7, i0 = row0 - 7 * s0;
    const int s1 = row1 / 7, i1 = row1 - 7 * s1;

    const float* Kc = K1 + (size_t)c * 25 * 306 * 256;

    for (int q = t; q < B_INSH / 4; q += 448) ((float4*)in_sh)[q] = make_float4(0.f,0.f,0.f,0.f);

    ull a01[14], a23[14];
#pragma unroll
    for (int j = 0; j < 14; j++) { a01[j] = 0ull; a23[j] = 0ull; }

    for (int chunk = 0; chunk < 16; chunk++) {
        const int ci0 = chunk * 16;
        __syncthreads();
        // fill interior: 4 samples x 49 pos x 16 ci
        for (int q = t; q < 784; q += 448) {
            int s = q / 196, r2 = q - s * 196;
            int p = r2 >> 2, k4 = r2 & 3;
            float4 v = *(const float4*)(g_act0 + ((size_t)samp[s] * 49 + p) * 256 + ci0 + k4 * 4);
            int pi_ = p / 7, pj_ = p - 7 * pi_;
            int pos = (2 + pi_) * 11 + 2 + pj_;
            *(float4*)(in_sh + ((s * 121 + pos) << 4) + k4 * 4) = v;
        }
        stage_w(w_sh, Kc + ((size_t)(0 * 306) + ci0) * 256 + co0, t, 256);
        CP_COMMIT();

        int dd = 0;
        for (int di = 0; di < 5; di++) {
            for (int dj = 0; dj < 5; dj++) {
                if (dd < 24) {
                    stage_w(w_sh + ((dd + 1) & 1) * B_WBUF,
                            Kc + ((size_t)(dd + 1) * 306 + ci0) * 256 + co0, t, 256);
                    CP_COMMIT();
                    CP_WAIT1();
                } else {
                    CP_WAIT0();
                }
                __syncthreads();
                int b0 = ((s0 * 121 + (i0 + di) * 11 + dj) << 4);
                int b1 = ((s1 * 121 + (i1 + di) * 11 + dj) << 4);
                stage_compute(in_sh, w_sh + (dd & 1) * B_WBUF, lane, a01, a23, b0, b1);
                __syncthreads();
                dd++;
            }
        }
    }

    // epilogue: + E field, BN, LReLU
    const int cof = co0 + lane * 4;
    float4 gg = *(const float4*)(G1 + c * C1 + cof);
    float4 bb = *(const float4*)(B1 + c * C1 + cof);
    float4 mm = *(const float4*)(M1 + c * C1 + cof);
    float4 vv = *(const float4*)(V1 + c * C1 + cof);
    float4 sc;
    sc.x = rsqrtf(vv.x + 1e-3f) * gg.x; sc.y = rsqrtf(vv.y + 1e-3f) * gg.y;
    sc.z = rsqrtf(vv.z + 1e-3f) * gg.z; sc.w = rsqrtf(vv.w + 1e-3f) * gg.w;

#pragma unroll
    for (int r = 0; r < 2; r++) {
        int rw = 2 * mg + r;
        int s = rw / 7, i = rw - 7 * s;
        if (!sok[s]) continue;
        float* dst = g_act1 + (size_t)samp[s] * (49 * C1);
#pragma unroll
        for (int jx = 0; jx < 7; jx++) {
            int p = i * 7 + jx;
            int j = r * 7 + jx;
            float4 E = *(const float4*)(g_embf + ((size_t)(c * 49 + p) << 8) + cof);
            float2 v01 = unpk(a01[j]);
            float2 v23 = unpk(a23[j]);
            float4 y;
            y.x = lrelu((v01.x + E.x - mm.x) * sc.x + bb.x);
            y.y = lrelu((v01.y + E.y - mm.y) * sc.y + bb.y);
            y.z = lrelu((v23.x + E.z - mm.z) * sc.z + bb.z);
            y.w = lrelu((v23.y + E.w - mm.w) * sc.w + bb.w);
            *(float4*)(dst + p * C1 + cof) = y;
        }
    }
}

// =====================================================================
// conv2: 5x5 s2 SAME (parity decomposition), 4 samples/CTA, 128 co
// =====================================================================
#define C_INSH (4 * 81 * 16)       // 5184 floats
#define C_WBUF 2048

__global__ __launch_bounds__(448, 1) void k_conv2(
    const float* __restrict__ K2,
    const float* __restrict__ G2, const float* __restrict__ B2,
    const float* __restrict__ M2, const float* __restrict__ V2)
{
    extern __shared__ float sm[];
    float* in_sh = sm;                         // [4][81][16]
    float* w_sh  = sm + C_INSH;                // [2][16][128]
    const int c = blockIdx.z;
    const int n_c = g_cnt[c];
    const int stile = blockIdx.x;
    if (stile * 4 >= n_c) return;
    const int t = threadIdx.x;
    const int lane = t & 31;
    const int mg = t >> 5;
    const int base = g_off[c];

    int samp[4]; bool sok[4];
#pragma unroll
    for (int s = 0; s < 4; s++) {
        int idx = stile * 4 + s;
        sok[s] = idx < n_c;
        samp[s] = g_perm[base + (idx < n_c ? idx : n_c - 1)];
    }

    const int row0 = 2 * mg, row1 = row0 + 1;
    const int s0 = row0 / 7, i0 = row0 - 7 * s0;
    const int s1 = row1 / 7, i1 = row1 - 7 * s1;

    const float* Kc = K2 + (size_t)c * 25 * 256 * 128;

    for (int q = t; q < C_INSH / 4; q += 448) ((float4*)in_sh)[q] = make_float4(0.f,0.f,0.f,0.f);

    const int cof = lane * 4;
    float4 gg = *(const float4*)(G2 + c * C2 + cof);
    float4 bb = *(const float4*)(B2 + c * C2 + cof);
    float4 mm = *(const float4*)(M2 + c * C2 + cof);
    float4 vv = *(const float4*)(V2 + c * C2 + cof);
    float4 sc;
    sc.x = rsqrtf(vv.x + 1e-3f) * gg.x; sc.y = rsqrtf(vv.y + 1e-3f) * gg.y;
    sc.z = rsqrtf(vv.z + 1e-3f) * gg.z; sc.w = rsqrtf(vv.w + 1e-3f) * gg.w;

    for (int pp = 0; pp < 4; pp++) {
        const int pi = pp >> 1, pj = pp & 1;
        // tap lists for this parity
        int tdd[9], tsi[9], tsj[9], nt = 0;
        {
            int dis[3], sis[3], njs[3], sjs[3];
            int ni = (pi == 0) ? 2 : 3, nj = (pj == 0) ? 2 : 3;
            for (int u = 0; u < ni; u++) { int d = (pi == 0) ? (1 + 2 * u) : (2 * u); dis[u] = d; sis[u] = (d >> 1) - 1; }
            for (int u = 0; u < nj; u++) { int d = (pj == 0) ? (1 + 2 * u) : (2 * u); njs[u] = d; sjs[u] = (d >> 1) - 1; }
            for (int a = 0; a < ni; a++)
                for (int b = 0; b < nj; b++) {
                    tdd[nt] = dis[a] * 5 + njs[b]; tsi[nt] = sis[a]; tsj[nt] = sjs[b]; nt++;
                }
        }

        ull a01[14], a23[14];
#pragma unroll
        for (int j = 0; j < 14; j++) { a01[j] = 0ull; a23[j] = 0ull; }

        for (int chunk = 0; chunk < 16; chunk++) {
            const int ci0 = chunk * 16;
            __syncthreads();
            for (int q = t; q < 784; q += 448) {
                int s = q / 196, r2 = q - s * 196;
                int p = r2 >> 2, k4 = r2 & 3;
                float4 v = *(const float4*)(g_act1 + ((size_t)samp[s] * 49 + p) * 256 + ci0 + k4 * 4);
                int pi_ = p / 7, pj_ = p - 7 * pi_;
                int pos = (1 + pi_) * 9 + 1 + pj_;
                *(float4*)(in_sh + ((s * 81 + pos) << 4) + k4 * 4) = v;
            }
            stage_w(w_sh, Kc + ((size_t)tdd[0] * 256 + ci0) * 128, t, 128);
            CP_COMMIT();

            for (int tt = 0; tt < nt; tt++) {
                if (tt + 1 < nt) {
                    stage_w(w_sh + ((tt + 1) & 1) * C_WBUF,
                            Kc + ((size_t)tdd[tt + 1] * 256 + ci0) * 128, t, 128);
                    CP_COMMIT();
                    CP_WAIT1();
                } else {
                    CP_WAIT0();
                }
                __syncthreads();
                int si = tsi[tt], sj = tsj[tt];
                int b0 = ((s0 * 81 + (1 + i0 + si) * 9 + 1 + sj) << 4);
                int b1 = ((s1 * 81 + (1 + i1 + si) * 9 + 1 + sj) << 4);
                stage_compute(in_sh, w_sh + (tt & 1) * C_WBUF, lane, a01, a23, b0, b1);
                __syncthreads();
            }
        }

        // epilogue this parity
#pragma unroll
        for (int r = 0; r < 2; r++) {
            int rw = 2 * mg + r;
            int s = rw / 7, i = rw - 7 * s;
            if (!sok[s]) continue;
            float* dst = g_act2 + (size_t)samp[s] * (196 * C2);
#pragma unroll
            for (int jx = 0; jx < 7; jx++) {
                int j = r * 7 + jx;
                int oi = 2 * i + pi, oj = 2 * jx + pj;
                float2 v01 = unpk(a01[j]);
                float2 v23 = unpk(a23[j]);
                float4 y;
                y.x = lrelu((v01.x - mm.x) * sc.x + bb.x);
                y.y = lrelu((v01.y - mm.y) * sc.y + bb.y);
                y.z = lrelu((v23.x - mm.z) * sc.z + bb.z);
                y.w = lrelu((v23.y - mm.w) * sc.w + bb.w);
                *(float4*)(dst + (oi * 14 + oj) * C2 + cof) = y;
            }
        }
    }
}

// =====================================================================
// conv3: 5x5 s2, 128 -> 1, tanh
// =====================================================================
#define D_IN_SH (196 * C2)
#define D_W_SH  (25 * C2)

__global__ __launch_bounds__(256) void k_conv3(
    const int* __restrict__ labels, const float* __restrict__ K3,
    float* __restrict__ out)
{
    extern __shared__ float sm[];
    float4* in4 = (float4*)sm;
    float4* w4s = (float4*)(sm + D_IN_SH);
    const int b = blockIdx.x;
    const int t = threadIdx.x;
    const int c = labels[b];

    const float4* a2 = (const float4*)(g_act2 + (size_t)b * (196 * C2));
    for (int q = t; q < 196 * 32; q += 256) in4[q] = a2[q];
    const float4* k4 = (const float4*)(K3 + (size_t)c * 25 * C2);
    for (int q = t; q < 25 * 32; q += 256) w4s[q] = k4[q];
    __syncthreads();

    for (int px = t; px < 784; px += 256) {
        const int oi = px / 28, oj = px - oi * 28;
        float acc = 0.f;
        for (int ddi = (oi & 1) ? 0 : 1; ddi < 5; ddi += 2) {
            int ii = (oi + ddi - 3) >> 1;
            if ((unsigned)ii >= 14u) continue;
            for (int ddj = (oj & 1) ? 0 : 1; ddj < 5; ddj += 2) {
                int jj = (oj + ddj - 3) >> 1;
                if ((unsigned)jj >= 14u) continue;
                const float4* ip = in4 + (ii * 14 + jj) * 32;
                const float4* wp = w4s + (ddi * 5 + ddj) * 32;
#pragma unroll 8
                for (int q = 0; q < 32; q++) {
                    float4 a = ip[q], w = wp[q];
                    acc += a.x * w.x + a.y * w.y + a.z * w.z + a.w * w.w;
                }
            }
        }
        out[(size_t)b * 784 + px] = tanhf(acc);
    }
}

// =====================================================================
extern "C" void kernel_launch(void* const* d_in, const int* in_sizes, int n_in,
                              void* d_out, int out_size)
{
    const float* noise = (const float*)d_in[0];
    const int*   labels= (const int*)  d_in[1];
    const float* emb   = (const float*)d_in[2];
    const float* Wd    = (const float*)d_in[3];
    const float* bn1g  = (const float*)d_in[4];
    const float* bn1b  = (const float*)d_in[5];
    const float* bn1m  = (const float*)d_in[6];
    const float* bn1v  = (const float*)d_in[7];
    const float* K1    = (const float*)d_in[8];
    const float* G1    = (const float*)d_in[9];
    const float* B1    = (const float*)d_in[10];
    const float* M1    = (const float*)d_in[11];
    const float* V1    = (const float*)d_in[12];
    const float* K2    = (const float*)d_in[13];
    const float* G2    = (const float*)d_in[14];
    const float* B2    = (const float*)d_in[15];
    const float* M2    = (const float*)d_in[16];
    const float* V2    = (const float*)d_in[17];
    const float* K3    = (const float*)d_in[18];
    float* out = (float*)d_out;

    const int smB = (B_INSH + 2 * B_WBUF) * 4;   // 47.5 KB
    const int smC = (C_INSH + 2 * C_WBUF) * 4;   // 37.1 KB
    const int smD = (D_IN_SH + D_W_SH) * 4;      // 113 KB
    cudaFuncSetAttribute(k_conv1, cudaFuncAttributeMaxDynamicSharedMemorySize, smB);
    cudaFuncSetAttribute(k_conv2, cudaFuncAttributeMaxDynamicSharedMemorySize, smC);
    cudaFuncSetAttribute(k_conv3, cudaFuncAttributeMaxDynamicSharedMemorySize, smD);

    k_bucket<<<1, 512>>>(labels);
    k_embconv<<<dim3(49, 10), 256>>>(K1, emb);
    k_dense<<<dim3(49, 64), 256>>>(noise, labels, emb, Wd, bn1g, bn1b, bn1m, bn1v);
    k_conv1<<<dim3(24, 2, 10), 448, smB>>>(K1, G1, B1, M1, V1);
    k_conv2<<<dim3(24, 1, 10), 448, smC>>>(K2, G2, B2, M2, V2);
    k_conv3<<<BATCH, 256, smD>>>(labels, K3, out);
}

// round 5
// speedup vs baseline: 2.5631x; 1.1621x over previous
#include <cuda_runtime.h>
#include <cstdint>

#define BATCH 512
#define NOISE 100
#define EMBD  50
#define NCLS  10
#define C1    256
#define C2    128

typedef unsigned long long ull;

// ---------------- scratch ----------------
__device__ __align__(16) float g_act0[BATCH * 49 * 256];
__device__ __align__(16) float g_act1[BATCH * 49 * C1];
__device__ __align__(16) float g_act2[BATCH * 196 * C2];
__device__ __align__(16) float g_embf[NCLS * 49 * 256];   // per-class conv1 emb bias field
__device__ __align__(16) float g_embw[NCLS * 25 * 256];   // per-class per-tap emb-weighted
__device__ int g_perm[BATCH];
__device__ int g_cnt[NCLS];
__device__ int g_off[NCLS];

__device__ __forceinline__ float lrelu(float x) { return x >= 0.f ? x : 0.3f * x; }

__device__ __forceinline__ ull splat2(float a) {
    ull d; unsigned ai = __float_as_uint(a);
    asm("mov.b64 %0, {%1, %1};" : "=l"(d) : "r"(ai));
    return d;
}
__device__ __forceinline__ void ffma2(ull& c, ull a, ull b) {
    asm("fma.rn.f32x2 %0, %1, %2, %3;" : "=l"(c) : "l"(a), "l"(b), "l"(c));
}
__device__ __forceinline__ float2 unpk(ull v) {
    unsigned lo, hi;
    asm("mov.b64 {%0, %1}, %2;" : "=r"(lo), "=r"(hi) : "l"(v));
    return make_float2(__uint_as_float(lo), __uint_as_float(hi));
}

#define CP_COMMIT() asm volatile("cp.async.commit_group;" ::: "memory")
#define CP_WAIT1()  asm volatile("cp.async.wait_group 1;" ::: "memory")

__device__ __forceinline__ void cp16(uint32_t saddr, const float* g) {
    asm volatile("cp.async.cg.shared.global [%0], [%1], 16;" :: "r"(saddr), "l"(g) : "memory");
}

// stage 16 rows x 128 floats (8KB), global row stride rs floats, 224 threads
__device__ __forceinline__ void stage(uint32_t dsm, const float* src, int rs, int t) {
    for (int q = t; q < 512; q += 224) {
        int r = q >> 5, cv = q & 31;
        cp16(dsm + (uint32_t)q * 16u, src + r * rs + cv * 4);
    }
}

#define INSTRIDE 34        // floats per position (16ci x 2samples + 2 pad)

// core: 16 k-steps x 7 positions x 4 co, inputs f32x2 over sample pair
__device__ __forceinline__ void compute128(
    const float* __restrict__ in_sh, const float* __restrict__ wbuf,
    int lane, int base, ull A[7][4])
{
#pragma unroll
    for (int kk = 0; kk < 16; kk++) {
        float4 w = *(const float4*)(wbuf + kk * 128 + lane * 4);
        ull w0 = splat2(w.x), w1 = splat2(w.y), w2 = splat2(w.z), w3 = splat2(w.w);
#pragma unroll
        for (int jx = 0; jx < 7; jx++) {
            ull a = *(const ull*)(in_sh + base + jx * INSTRIDE + kk * 2);
            ffma2(A[jx][0], a, w0);
            ffma2(A[jx][1], a, w1);
            ffma2(A[jx][2], a, w2);
            ffma2(A[jx][3], a, w3);
        }
    }
}

// =====================================================================
__global__ __launch_bounds__(512) void k_bucket(const int* __restrict__ labels)
{
    __shared__ int scnt[NCLS], scur[NCLS];
    int t = threadIdx.x;
    if (t < NCLS) scnt[t] = 0;
    __syncthreads();
    int c = labels[t];
    atomicAdd(&scnt[c], 1);
    __syncthreads();
    if (t == 0) {
        int run = 0;
        for (int k = 0; k < NCLS; k++) {
            g_off[k] = run; scur[k] = run; g_cnt[k] = scnt[k]; run += scnt[k];
        }
    }
    __syncthreads();
    int pos = atomicAdd(&scur[c], 1);
    g_perm[pos] = t;
}

// =====================================================================
// emb fold: W~[c][tap][co] = sum_e emb[c][e] * K1[c][tap][256+e][co]
// =====================================================================
__global__ __launch_bounds__(256) void k_embw(
    const float* __restrict__ K1, const float* __restrict__ emb)
{
    __shared__ float es[EMBD];
    int tap = blockIdx.x, c = blockIdx.y, t = threadIdx.x;
    if (t < EMBD) es[t] = emb[c * EMBD + t];
    __syncthreads();
    const float* kb = K1 + (((size_t)c * 25 + tap) * 306 + 256) * 256 + t;
    float acc = 0.f;
#pragma unroll 10
    for (int e = 0; e < EMBD; e++) acc += es[e] * kb[(size_t)e * 256];
    g_embw[((size_t)c * 25 + tap) * 256 + t] = acc;
}

// E[c][p][co] = sum over valid taps of W~
__global__ __launch_bounds__(256) void k_embe(const float* dummy)
{
    int p = blockIdx.x, c = blockIdx.y, t = threadIdx.x;
    int i = p / 7, j = p - 7 * i;
    float acc = 0.f;
    for (int di = 0; di < 5; di++) {
        int ii = i + di - 2; if ((unsigned)ii >= 7u) continue;
        for (int dj = 0; dj < 5; dj++) {
            int jj = j + dj - 2; if ((unsigned)jj >= 7u) continue;
            acc += g_embw[((size_t)c * 25 + di * 5 + dj) * 256 + t];
        }
    }
    g_embf[((size_t)c * 49 + p) * 256 + t] = acc;
}

// =====================================================================
// dense + BN + LReLU -> act0 [b][49][256]
// =====================================================================
__global__ __launch_bounds__(256) void k_dense(
    const float* __restrict__ noise, const int* __restrict__ labels,
    const float* __restrict__ emb,   const float* __restrict__ Wd,
    const float* __restrict__ bn_g,  const float* __restrict__ bn_b,
    const float* __restrict__ bn_m,  const float* __restrict__ bn_v)
{
    __shared__ float xs[8 * 152];
    const int t  = threadIdx.x;
    const int bx = blockIdx.x;
    const int b0 = blockIdx.y * 8;

    for (int idx = t; idx < 8 * 150; idx += 256) {
        int s = idx / 150, k = idx - s * 150;
        int bb = b0 + s;
        float val = (k < NOISE) ? noise[bb * NOISE + k]
                                : emb[labels[bb] * EMBD + (k - NOISE)];
        xs[s * 152 + k] = val;
    }
    __syncthreads();

    const int j = bx * 256 + t;
    float acc[8];
#pragma unroll
    for (int s = 0; s < 8; s++) acc[s] = 0.f;
    for (int k = 0; k < 150; k++) {
        float w = Wd[k * 12544 + j];
#pragma unroll
        for (int s = 0; s < 8; s++) acc[s] += xs[s * 152 + k] * w;
    }
    const float sc = rsqrtf(bn_v[j] + 1e-3f) * bn_g[j];
    const float mm = bn_m[j];
    const float bb = bn_b[j];
#pragma unroll
    for (int s = 0; s < 8; s++) {
        float y = lrelu((acc[s] - mm) * sc + bb);
        g_act0[(size_t)(b0 + s) * (49 * 256) + bx * 256 + t] = y;
    }
}

// =====================================================================
// conv1: 5x5 s1 SAME, 256 ci (emb folded), 2 samples (1 pair)/CTA, 128-co tile
// =====================================================================
#define B_INS  (121 * INSTRIDE + 2)     // 4116 floats (16B-aligned end)
#define WBUF   2048                      // 16 x 128 floats

__global__ __launch_bounds__(224, 2) void k_conv1(
    const float* __restrict__ K1,
    const float* __restrict__ G1, const float* __restrict__ B1,
    const float* __restrict__ M1, const float* __restrict__ V1)
{
    __shared__ float in_sh[B_INS];
    __shared__ __align__(16) float w_sh[3 * WBUF];
    const int c = blockIdx.z;
    const int n_c = g_cnt[c];
    const int stile = blockIdx.x;
    if (stile * 2 >= n_c) return;
    const int co0 = blockIdx.y << 7;
    const int t = threadIdx.x, lane = t & 31, wrp = t >> 5;
    const int base0 = g_off[c];
    const int idx1 = min(stile * 2 + 1, n_c - 1);
    const int s0 = g_perm[base0 + stile * 2];
    const int s1 = g_perm[base0 + idx1];
    const bool sok1 = (stile * 2 + 1 < n_c);
    const float* Kc = K1 + (size_t)c * 25 * 306 * 256;

    for (int q = t; q < B_INS; q += 224) in_sh[q] = 0.f;

    ull A[7][4];
#pragma unroll
    for (int j = 0; j < 7; j++)
#pragma unroll
        for (int u = 0; u < 4; u++) A[j][u] = 0ull;

    const uint32_t wsm = (uint32_t)__cvta_generic_to_shared(w_sh);

    for (int chunk = 0; chunk < 16; chunk++) {
        const int ci0 = chunk << 4;
        __syncthreads();
        // refill input interior: 2 samples x 49 pos x 16 ci
        for (int q = t; q < 392; q += 224) {
            int s = (q >= 196) ? 1 : 0;
            int rem = q - (s ? 196 : 0);
            int p = rem >> 2, k4 = rem & 3;
            float4 v = *(const float4*)(g_act0 + ((size_t)(s ? s1 : s0) * 49 + p) * 256 + ci0 + (k4 << 2));
            int pi_ = p / 7, pj_ = p - 7 * pi_;
            float* dst = in_sh + ((2 + pi_) * 11 + 2 + pj_) * INSTRIDE + (k4 << 3) + s;
            dst[0] = v.x; dst[2] = v.y; dst[4] = v.z; dst[6] = v.w;
        }
        // prefetch taps 0,1
        stage(wsm, Kc + (size_t)ci0 * 256 + co0, 256, t);               CP_COMMIT();
        stage(wsm + WBUF * 4, Kc + (size_t)(306 + ci0) * 256 + co0, 256, t); CP_COMMIT();

        for (int dd = 0; dd < 25; dd++) {
            CP_WAIT1();
            __syncthreads();
            if (dd + 2 < 25)
                stage(wsm + (uint32_t)((dd + 2) % 3) * (WBUF * 4),
                      Kc + ((size_t)(dd + 2) * 306 + ci0) * 256 + co0, 256, t);
            CP_COMMIT();
            const int di = dd / 5, dj = dd - 5 * di;
            const int base = ((wrp + di) * 11 + dj) * INSTRIDE;
            compute128(in_sh, w_sh + (dd % 3) * WBUF, lane, base, A);
        }
    }

    // epilogue: + E, BN, LReLU
    const int cof = co0 + (lane << 2);
    float4 gg = *(const float4*)(G1 + c * C1 + cof);
    float4 bb = *(const float4*)(B1 + c * C1 + cof);
    float4 mm = *(const float4*)(M1 + c * C1 + cof);
    float4 vv = *(const float4*)(V1 + c * C1 + cof);
    float4 sc;
    sc.x = rsqrtf(vv.x + 1e-3f) * gg.x; sc.y = rsqrtf(vv.y + 1e-3f) * gg.y;
    sc.z = rsqrtf(vv.z + 1e-3f) * gg.z; sc.w = rsqrtf(vv.w + 1e-3f) * gg.w;
    float* o0 = g_act1 + (size_t)s0 * (49 * C1);
    float* o1 = g_act1 + (size_t)s1 * (49 * C1);
#pragma unroll
    for (int jx = 0; jx < 7; jx++) {
        int p = wrp * 7 + jx;
        float4 E = *(const float4*)(g_embf + ((size_t)c * 49 + p) * 256 + cof);
        float2 v0 = unpk(A[jx][0]), v1 = unpk(A[jx][1]);
        float2 v2 = unpk(A[jx][2]), v3 = unpk(A[jx][3]);
        float4 ya;
        ya.x = lrelu((v0.x + E.x - mm.x) * sc.x + bb.x);
        ya.y = lrelu((v1.x + E.y - mm.y) * sc.y + bb.y);
        ya.z = lrelu((v2.x + E.z - mm.z) * sc.z + bb.z);
        ya.w = lrelu((v3.x + E.w - mm.w) * sc.w + bb.w);
        *(float4*)(o0 + p * C1 + cof) = ya;
        if (sok1) {
            float4 yb;
            yb.x = lrelu((v0.y + E.x - mm.x) * sc.x + bb.x);
            yb.y = lrelu((v1.y + E.y - mm.y) * sc.y + bb.y);
            yb.z = lrelu((v2.y + E.z - mm.z) * sc.z + bb.z);
            yb.w = lrelu((v3.y + E.w - mm.w) * sc.w + bb.w);
            *(float4*)(o1 + p * C1 + cof) = yb;
        }
    }
}

// =====================================================================
// conv2: 5x5 s2 SAME (parity taps), 2 samples/CTA, full 128 co
// =====================================================================
#define C_INS (81 * INSTRIDE + 2)       // 2756 floats

__global__ __launch_bounds__(224, 2) void k_conv2(
    const float* __restrict__ K2,
    const float* __restrict__ G2, const float* __restrict__ B2,
    const float* __restrict__ M2, const float* __restrict__ V2)
{
    __shared__ float in_sh[C_INS];
    __shared__ __align__(16) float w_sh[3 * WBUF];
    const int c = blockIdx.z;
    const int n_c = g_cnt[c];
    const int stile = blockIdx.x;
    if (stile * 2 >= n_c) return;
    const int t = threadIdx.x, lane = t & 31, wrp = t >> 5;
    const int base0 = g_off[c];
    const int idx1 = min(stile * 2 + 1, n_c - 1);
    const int s0 = g_perm[base0 + stile * 2];
    const int s1 = g_perm[base0 + idx1];
    const bool sok1 = (stile * 2 + 1 < n_c);
    const float* Kc = K2 + (size_t)c * 25 * 256 * 128;

    for (int q = t; q < C_INS; q += 224) in_sh[q] = 0.f;

    const int cof = lane << 2;
    float4 gg = *(const float4*)(G2 + c * C2 + cof);
    float4 bb = *(const float4*)(B2 + c * C2 + cof);
    float4 mm = *(const float4*)(M2 + c * C2 + cof);
    float4 vv = *(const float4*)(V2 + c * C2 + cof);
    float4 sc;
    sc.x = rsqrtf(vv.x + 1e-3f) * gg.x; sc.y = rsqrtf(vv.y + 1e-3f) * gg.y;
    sc.z = rsqrtf(vv.z + 1e-3f) * gg.z; sc.w = rsqrtf(vv.w + 1e-3f) * gg.w;
    float* o0 = g_act2 + (size_t)s0 * (196 * C2);
    float* o1 = g_act2 + (size_t)s1 * (196 * C2);
    const uint32_t wsm = (uint32_t)__cvta_generic_to_shared(w_sh);

    for (int pp = 0; pp < 4; pp++) {
        const int pi = pp >> 1, pj = pp & 1;
        int tdd[9], tbase[9], nt = 0;
        {
            int dis[3], sis[3], djs[3], sjs[3];
            int ni = (pi == 0) ? 2 : 3, nj = (pj == 0) ? 2 : 3;
            for (int u = 0; u < ni; u++) { int d = (pi == 0) ? (1 + 2 * u) : (2 * u); dis[u] = d; sis[u] = (d >> 1) - 1; }
            for (int u = 0; u < nj; u++) { int d = (pj == 0) ? (1 + 2 * u) : (2 * u); djs[u] = d; sjs[u] = (d >> 1) - 1; }
            for (int a = 0; a < ni; a++)
                for (int b = 0; b < nj; b++) {
                    tdd[nt] = dis[a] * 5 + djs[b];
                    tbase[nt] = ((1 + wrp + sis[a]) * 9 + 1 + sjs[b]) * INSTRIDE;
                    nt++;
                }
        }

        ull A[7][4];
#pragma unroll
        for (int j = 0; j < 7; j++)
#pragma unroll
            for (int u = 0; u < 4; u++) A[j][u] = 0ull;

        for (int chunk = 0; chunk < 16; chunk++) {
            const int ci0 = chunk << 4;
            __syncthreads();
            for (int q = t; q < 392; q += 224) {
                int s = (q >= 196) ? 1 : 0;
                int rem = q - (s ? 196 : 0);
                int p = rem >> 2, k4 = rem & 3;
                float4 v = *(const float4*)(g_act1 + ((size_t)(s ? s1 : s0) * 49 + p) * 256 + ci0 + (k4 << 2));
                int pi_ = p / 7, pj_ = p - 7 * pi_;
                float* dst = in_sh + ((1 + pi_) * 9 + 1 + pj_) * INSTRIDE + (k4 << 3) + s;
                dst[0] = v.x; dst[2] = v.y; dst[4] = v.z; dst[6] = v.w;
            }
            stage(wsm, Kc + ((size_t)tdd[0] * 256 + ci0) * 128, 128, t);            CP_COMMIT();
            stage(wsm + WBUF * 4, Kc + ((size_t)tdd[1] * 256 + ci0) * 128, 128, t); CP_COMMIT();

            for (int tt = 0; tt < nt; tt++) {
                CP_WAIT1();
                __syncthreads();
                if (tt + 2 < nt)
                    stage(wsm + (uint32_t)((tt + 2) % 3) * (WBUF * 4),
                          Kc + ((size_t)tdd[tt + 2] * 256 + ci0) * 128, 128, t);
                CP_COMMIT();
                compute128(in_sh, w_sh + (tt % 3) * WBUF, lane, tbase[tt], A);
            }
        }

#pragma unroll
        for (int jx = 0; jx < 7; jx++) {
            int oi = 2 * wrp + pi, oj = 2 * jx + pj;
            float2 v0 = unpk(A[jx][0]), v1 = unpk(A[jx][1]);
            float2 v2 = unpk(A[jx][2]), v3 = unpk(A[jx][3]);
            float4 ya;
            ya.x = lrelu((v0.x - mm.x) * sc.x + bb.x);
            ya.y = lrelu((v1.x - mm.y) * sc.y + bb.y);
            ya.z = lrelu((v2.x - mm.z) * sc.z + bb.z);
            ya.w = lrelu((v3.x - mm.w) * sc.w + bb.w);
            *(float4*)(o0 + (oi * 14 + oj) * C2 + cof) = ya;
            if (sok1) {
                float4 yb;
                yb.x = lrelu((v0.y - mm.x) * sc.x + bb.x);
                yb.y = lrelu((v1.y - mm.y) * sc.y + bb.y);
                yb.z = lrelu((v2.y - mm.z) * sc.z + bb.z);
                yb.w = lrelu((v3.y - mm.w) * sc.w + bb.w);
                *(float4*)(o1 + (oi * 14 + oj) * C2 + cof) = yb;
            }
        }
    }
}

// =====================================================================
// conv3: 5x5 s2, 128 -> 1, tanh
// =====================================================================
#define D_IN_SH (196 * C2)
#define D_W_SH  (25 * C2)

__global__ __launch_bounds__(256) void k_conv3(
    const int* __restrict__ labels, const float* __restrict__ K3,
    float* __restrict__ out)
{
    extern __shared__ float sm[];
    float4* in4 = (float4*)sm;
    float4* w4s = (float4*)(sm + D_IN_SH);
    const int b = blockIdx.x;
    const int t = threadIdx.x;
    const int c = labels[b];

    const float4* a2 = (const float4*)(g_act2 + (size_t)b * (196 * C2));
    for (int q = t; q < 196 * 32; q += 256) in4[q] = a2[q];
    const float4* k4 = (const float4*)(K3 + (size_t)c * 25 * C2);
    for (int q = t; q < 25 * 32; q += 256) w4s[q] = k4[q];
    __syncthreads();

    for (int px = t; px < 784; px += 256) {
        const int oi = px / 28, oj = px - oi * 28;
        float acc = 0.f;
        for (int ddi = (oi & 1) ? 0 : 1; ddi < 5; ddi += 2) {
            int ii = (oi + ddi - 3) >> 1;
            if ((unsigned)ii >= 14u) continue;
            for (int ddj = (oj & 1) ? 0 : 1; ddj < 5; ddj += 2) {
                int jj = (oj + ddj - 3) >> 1;
                if ((unsigned)jj >= 14u) continue;
                const float4* ip = in4 + (ii * 14 + jj) * 32;
                const float4* wp = w4s + (ddi * 5 + ddj) * 32;
#pragma unroll 8
                for (int q = 0; q < 32; q++) {
                    float4 a = ip[q], w = wp[q];
                    acc += a.x * w.x + a.y * w.y + a.z * w.z + a.w * w.w;
                }
            }
        }
        out[(size_t)b * 784 + px] = tanhf(acc);
    }
}

// =====================================================================
extern "C" void kernel_launch(void* const* d_in, const int* in_sizes, int n_in,
                              void* d_out, int out_size)
{
    const float* noise = (const float*)d_in[0];
    const int*   labels= (const int*)  d_in[1];
    const float* emb   = (const float*)d_in[2];
    const float* Wd    = (const float*)d_in[3];
    const float* bn1g  = (const float*)d_in[4];
    const float* bn1b  = (const float*)d_in[5];
    const float* bn1m  = (const float*)d_in[6];
    const float* bn1v  = (const float*)d_in[7];
    const float* K1    = (const float*)d_in[8];
    const float* G1    = (const float*)d_in[9];
    const float* B1    = (const float*)d_in[10];
    const float* M1    = (const float*)d_in[11];
    const float* V1    = (const float*)d_in[12];
    const float* K2    = (const float*)d_in[13];
    const float* G2    = (const float*)d_in[14];
    const float* B2    = (const float*)d_in[15];
    const float* M2    = (const float*)d_in[16];
    const float* V2    = (const float*)d_in[17];
    const float* K3    = (const float*)d_in[18];
    float* out = (float*)d_out;

    const int smD = (D_IN_SH + D_W_SH) * 4;
    cudaFuncSetAttribute(k_conv3, cudaFuncAttributeMaxDynamicSharedMemorySize, smD);

    k_bucket<<<1, 512>>>(labels);
    k_embw<<<dim3(25, 10), 256>>>(K1, emb);
    k_embe<<<dim3(49, 10), 256>>>(nullptr);
    k_dense<<<dim3(49, 64), 256>>>(noise, labels, emb, Wd, bn1g, bn1b, bn1m, bn1v);
    k_conv1<<<dim3(64, 2, 10), 224>>>(K1, G1, B1, M1, V1);
    k_conv2<<<dim3(64, 1, 10), 224>>>(K2, G2, B2, M2, V2);
    k_conv3<<<BATCH, 256, smD>>>(labels, K3, out);
}

// round 6
// speedup vs baseline: 2.5648x; 1.0007x over previous
#include <cuda_runtime.h>
#include <cstdint>

#define BATCH 512
#define NOISE 100
#define EMBD  50
#define NCLS  10
#define C1    256
#define C2    128

typedef unsigned long long ull;

// ---------------- scratch ----------------
__device__ __align__(16) float g_act0[BATCH * 49 * 256];
__device__ __align__(16) float g_act1[BATCH * 49 * C1];
__device__ __align__(16) float g_act2[BATCH * 196 * C2];
__device__ __align__(16) float g_embf[NCLS * 49 * 256];   // per-class conv1 emb bias field
__device__ __align__(16) float g_embw[NCLS * 25 * 256];   // per-class per-tap emb-weighted
__device__ int g_perm[BATCH];
__device__ int g_cnt[NCLS];
__device__ int g_off[NCLS];

__device__ __forceinline__ float lrelu(float x) { return x >= 0.f ? x : 0.3f * x; }

__device__ __forceinline__ ull splat2(float a) {
    ull d; unsigned ai = __float_as_uint(a);
    asm("mov.b64 %0, {%1, %1};" : "=l"(d) : "r"(ai));
    return d;
}
__device__ __forceinline__ void ffma2(ull& c, ull a, ull b) {
    asm("fma.rn.f32x2 %0, %1, %2, %3;" : "=l"(c) : "l"(a), "l"(b), "l"(c));
}
__device__ __forceinline__ float2 unpk(ull v) {
    unsigned lo, hi;
    asm("mov.b64 {%0, %1}, %2;" : "=r"(lo), "=r"(hi) : "l"(v));
    return make_float2(__uint_as_float(lo), __uint_as_float(hi));
}

#define CP_COMMIT() asm volatile("cp.async.commit_group;" ::: "memory")
#define CP_WAIT1()  asm volatile("cp.async.wait_group 1;" ::: "memory")

__device__ __forceinline__ void cp16(uint32_t saddr, const float* g) {
    asm volatile("cp.async.cg.shared.global [%0], [%1], 16;" :: "r"(saddr), "l"(g) : "memory");
}

// stage 16 rows x 128 floats (8KB), global row stride rs floats, 224 threads
__device__ __forceinline__ void stage(uint32_t dsm, const float* src, int rs, int t) {
    for (int q = t; q < 512; q += 224) {
        int r = q >> 5, cv = q & 31;
        cp16(dsm + (uint32_t)q * 16u, src + r * rs + cv * 4);
    }
}

#define INSTRIDE 34        // floats per position (16ci x 2samples + 2 pad)

// core: 16 k-steps x 7 positions x 4 co, inputs f32x2 over sample pair
__device__ __forceinline__ void compute128(
    const float* __restrict__ in_sh, const float* __restrict__ wbuf,
    int lane, int base, ull A[7][4])
{
#pragma unroll
    for (int kk = 0; kk < 16; kk++) {
        float4 w = *(const float4*)(wbuf + kk * 128 + lane * 4);
        ull w0 = splat2(w.x), w1 = splat2(w.y), w2 = splat2(w.z), w3 = splat2(w.w);
#pragma unroll
        for (int jx = 0; jx < 7; jx++) {
            ull a = *(const ull*)(in_sh + base + jx * INSTRIDE + kk * 2);
            ffma2(A[jx][0], a, w0);
            ffma2(A[jx][1], a, w1);
            ffma2(A[jx][2], a, w2);
            ffma2(A[jx][3], a, w3);
        }
    }
}

// =====================================================================
__global__ __launch_bounds__(512) void k_bucket(const int* __restrict__ labels)
{
    __shared__ int scnt[NCLS], scur[NCLS];
    int t = threadIdx.x;
    if (t < NCLS) scnt[t] = 0;
    __syncthreads();
    int c = labels[t];
    atomicAdd(&scnt[c], 1);
    __syncthreads();
    if (t == 0) {
        int run = 0;
        for (int k = 0; k < NCLS; k++) {
            g_off[k] = run; scur[k] = run; g_cnt[k] = scnt[k]; run += scnt[k];
        }
    }
    __syncthreads();
    int pos = atomicAdd(&scur[c], 1);
    g_perm[pos] = t;
}

// =====================================================================
// emb fold: W~[c][tap][co] = sum_e emb[c][e] * K1[c][tap][256+e][co]
// =====================================================================
__global__ __launch_bounds__(256) void k_embw(
    const float* __restrict__ K1, const float* __restrict__ emb)
{
    __shared__ float es[EMBD];
    int tap = blockIdx.x, c = blockIdx.y, t = threadIdx.x;
    if (t < EMBD) es[t] = emb[c * EMBD + t];
    __syncthreads();
    const float* kb = K1 + (((size_t)c * 25 + tap) * 306 + 256) * 256 + t;
    float acc = 0.f;
#pragma unroll 10
    for (int e = 0; e < EMBD; e++) acc += es[e] * kb[(size_t)e * 256];
    g_embw[((size_t)c * 25 + tap) * 256 + t] = acc;
}

// E[c][p][co] = sum over valid taps of W~
__global__ __launch_bounds__(256) void k_embe(const float* dummy)
{
    int p = blockIdx.x, c = blockIdx.y, t = threadIdx.x;
    int i = p / 7, j = p - 7 * i;
    float acc = 0.f;
    for (int di = 0; di < 5; di++) {
        int ii = i + di - 2; if ((unsigned)ii >= 7u) continue;
        for (int dj = 0; dj < 5; dj++) {
            int jj = j + dj - 2; if ((unsigned)jj >= 7u) continue;
            acc += g_embw[((size_t)c * 25 + di * 5 + dj) * 256 + t];
        }
    }
    g_embf[((size_t)c * 49 + p) * 256 + t] = acc;
}

// =====================================================================
// dense + BN + LReLU -> act0 [b][49][256]
// =====================================================================
__global__ __launch_bounds__(256) void k_dense(
    const float* __restrict__ noise, const int* __restrict__ labels,
    const float* __restrict__ emb,   const float* __restrict__ Wd,
    const float* __restrict__ bn_g,  const float* __restrict__ bn_b,
    const float* __restrict__ bn_m,  const float* __restrict__ bn_v)
{
    __shared__ float xs[8 * 152];
    const int t  = threadIdx.x;
    const int bx = blockIdx.x;
    const int b0 = blockIdx.y * 8;

    for (int idx = t; idx < 8 * 150; idx += 256) {
        int s = idx / 150, k = idx - s * 150;
        int bb = b0 + s;
        float val = (k < NOISE) ? noise[bb * NOISE + k]
                                : emb[labels[bb] * EMBD + (k - NOISE)];
        xs[s * 152 + k] = val;
    }
    __syncthreads();

    const int j = bx * 256 + t;
    float acc[8];
#pragma unroll
    for (int s = 0; s < 8; s++) acc[s] = 0.f;
    for (int k = 0; k < 150; k++) {
        float w = Wd[k * 12544 + j];
#pragma unroll
        for (int s = 0; s < 8; s++) acc[s] += xs[s * 152 + k] * w;
    }
    const float sc = rsqrtf(bn_v[j] + 1e-3f) * bn_g[j];
    const float mm = bn_m[j];
    const float bb = bn_b[j];
#pragma unroll
    for (int s = 0; s < 8; s++) {
        float y = lrelu((acc[s] - mm) * sc + bb);
        g_act0[(size_t)(b0 + s) * (49 * 256) + bx * 256 + t] = y;
    }
}

// =====================================================================
// conv1: 5x5 s1 SAME, 256 ci (emb folded), 2 samples (1 pair)/CTA, 128-co tile
// =====================================================================
#define B_INS  (121 * INSTRIDE + 2)     // 4116 floats (16B-aligned end)
#define WBUF   2048                      // 16 x 128 floats

__global__ __launch_bounds__(224, 2) void k_conv1(
    const float* __restrict__ K1,
    const float* __restrict__ G1, const float* __restrict__ B1,
    const float* __restrict__ M1, const float* __restrict__ V1)
{
    __shared__ float in_sh[B_INS];
    __shared__ __align__(16) float w_sh[3 * WBUF];
    const int c = blockIdx.z;
    const int n_c = g_cnt[c];
    const int stile = blockIdx.x;
    if (stile * 2 >= n_c) return;
    const int co0 = blockIdx.y << 7;
    const int t = threadIdx.x, lane = t & 31, wrp = t >> 5;
    const int base0 = g_off[c];
    const int idx1 = min(stile * 2 + 1, n_c - 1);
    const int s0 = g_perm[base0 + stile * 2];
    const int s1 = g_perm[base0 + idx1];
    const bool sok1 = (stile * 2 + 1 < n_c);
    const float* Kc = K1 + (size_t)c * 25 * 306 * 256;

    for (int q = t; q < B_INS; q += 224) in_sh[q] = 0.f;

    ull A[7][4];
#pragma unroll
    for (int j = 0; j < 7; j++)
#pragma unroll
        for (int u = 0; u < 4; u++) A[j][u] = 0ull;

    const uint32_t wsm = (uint32_t)__cvta_generic_to_shared(w_sh);

    for (int chunk = 0; chunk < 16; chunk++) {
        const int ci0 = chunk << 4;
        __syncthreads();
        // refill input interior: 2 samples x 49 pos x 16 ci
        for (int q = t; q < 392; q += 224) {
            int s = (q >= 196) ? 1 : 0;
            int rem = q - (s ? 196 : 0);
            int p = rem >> 2, k4 = rem & 3;
            float4 v = *(const float4*)(g_act0 + ((size_t)(s ? s1 : s0) * 49 + p) * 256 + ci0 + (k4 << 2));
            int pi_ = p / 7, pj_ = p - 7 * pi_;
            float* dst = in_sh + ((2 + pi_) * 11 + 2 + pj_) * INSTRIDE + (k4 << 3) + s;
            dst[0] = v.x; dst[2] = v.y; dst[4] = v.z; dst[6] = v.w;
        }
        // prefetch taps 0,1
        stage(wsm, Kc + (size_t)ci0 * 256 + co0, 256, t);               CP_COMMIT();
        stage(wsm + WBUF * 4, Kc + (size_t)(306 + ci0) * 256 + co0, 256, t); CP_COMMIT();

        for (int dd = 0; dd < 25; dd++) {
            CP_WAIT1();
            __syncthreads();
            if (dd + 2 < 25)
                stage(wsm + (uint32_t)((dd + 2) % 3) * (WBUF * 4),
                      Kc + ((size_t)(dd + 2) * 306 + ci0) * 256 + co0, 256, t);
            CP_COMMIT();
            const int di = dd / 5, dj = dd - 5 * di;
            const int base = ((wrp + di) * 11 + dj) * INSTRIDE;
            compute128(in_sh, w_sh + (dd % 3) * WBUF, lane, base, A);
        }
    }

    // epilogue: + E, BN, LReLU
    const int cof = co0 + (lane << 2);
    float4 gg = *(const float4*)(G1 + c * C1 + cof);
    float4 bb = *(const float4*)(B1 + c * C1 + cof);
    float4 mm = *(const float4*)(M1 + c * C1 + cof);
    float4 vv = *(const float4*)(V1 + c * C1 + cof);
    float4 sc;
    sc.x = rsqrtf(vv.x + 1e-3f) * gg.x; sc.y = rsqrtf(vv.y + 1e-3f) * gg.y;
    sc.z = rsqrtf(vv.z + 1e-3f) * gg.z; sc.w = rsqrtf(vv.w + 1e-3f) * gg.w;
    float* o0 = g_act1 + (size_t)s0 * (49 * C1);
    float* o1 = g_act1 + (size_t)s1 * (49 * C1);
#pragma unroll
    for (int jx = 0; jx < 7; jx++) {
        int p = wrp * 7 + jx;
        float4 E = *(const float4*)(g_embf + ((size_t)c * 49 + p) * 256 + cof);
        float2 v0 = unpk(A[jx][0]), v1 = unpk(A[jx][1]);
        float2 v2 = unpk(A[jx][2]), v3 = unpk(A[jx][3]);
        float4 ya;
        ya.x = lrelu((v0.x + E.x - mm.x) * sc.x + bb.x);
        ya.y = lrelu((v1.x + E.y - mm.y) * sc.y + bb.y);
        ya.z = lrelu((v2.x + E.z - mm.z) * sc.z + bb.z);
        ya.w = lrelu((v3.x + E.w - mm.w) * sc.w + bb.w);
        *(float4*)(o0 + p * C1 + cof) = ya;
        if (sok1) {
            float4 yb;
            yb.x = lrelu((v0.y + E.x - mm.x) * sc.x + bb.x);
            yb.y = lrelu((v1.y + E.y - mm.y) * sc.y + bb.y);
            yb.z = lrelu((v2.y + E.z - mm.z) * sc.z + bb.z);
            yb.w = lrelu((v3.y + E.w - mm.w) * sc.w + bb.w);
            *(float4*)(o1 + p * C1 + cof) = yb;
        }
    }
}

// =====================================================================
// conv2: 5x5 s2 SAME (parity taps), 2 samples/CTA, full 128 co
// =====================================================================
#define C_INS (81 * INSTRIDE + 2)       // 2756 floats

__global__ __launch_bounds__(224, 2) void k_conv2(
    const float* __restrict__ K2,
    const float* __restrict__ G2, const float* __restrict__ B2,
    const float* __restrict__ M2, const float* __restrict__ V2)
{
    __shared__ float in_sh[C_INS];
    __shared__ __align__(16) float w_sh[3 * WBUF];
    const int c = blockIdx.z;
    const int n_c = g_cnt[c];
    const int stile = blockIdx.x;
    if (stile * 2 >= n_c) return;
    const int t = threadIdx.x, lane = t & 31, wrp = t >> 5;
    const int base0 = g_off[c];
    const int idx1 = min(stile * 2 + 1, n_c - 1);
    const int s0 = g_perm[base0 + stile * 2];
    const int s1 = g_perm[base0 + idx1];
    const bool sok1 = (stile * 2 + 1 < n_c);
    const float* Kc = K2 + (size_t)c * 25 * 256 * 128;

    for (int q = t; q < C_INS; q += 224) in_sh[q] = 0.f;

    const int cof = lane << 2;
    float4 gg = *(const float4*)(G2 + c * C2 + cof);
    float4 bb = *(const float4*)(B2 + c * C2 + cof);
    float4 mm = *(const float4*)(M2 + c * C2 + cof);
    float4 vv = *(const float4*)(V2 + c * C2 + cof);
    float4 sc;
    sc.x = rsqrtf(vv.x + 1e-3f) * gg.x; sc.y = rsqrtf(vv.y + 1e-3f) * gg.y;
    sc.z = rsqrtf(vv.z + 1e-3f) * gg.z; sc.w = rsqrtf(vv.w + 1e-3f) * gg.w;
    float* o0 = g_act2 + (size_t)s0 * (196 * C2);
    float* o1 = g_act2 + (size_t)s1 * (196 * C2);
    const uint32_t wsm = (uint32_t)__cvta_generic_to_shared(w_sh);

    for (int pp = 0; pp < 4; pp++) {
        const int pi = pp >> 1, pj = pp & 1;
        int tdd[9], tbase[9], nt = 0;
        {
            int dis[3], sis[3], djs[3], sjs[3];
            int ni = (pi == 0) ? 2 : 3, nj = (pj == 0) ? 2 : 3;
            for (int u = 0; u < ni; u++) { int d = (pi == 0) ? (1 + 2 * u) : (2 * u); dis[u] = d; sis[u] = (d >> 1) - 1; }
            for (int u = 0; u < nj; u++) { int d = (pj == 0) ? (1 + 2 * u) : (2 * u); djs[u] = d; sjs[u] = (d >> 1) - 1; }
            for (int a = 0; a < ni; a++)
                for (int b = 0; b < nj; b++) {
                    tdd[nt] = dis[a] * 5 + djs[b];
                    tbase[nt] = ((1 + wrp + sis[a]) * 9 + 1 + sjs[b]) * INSTRIDE;
                    nt++;
                }
        }

        ull A[7][4];
#pragma unroll
        for (int j = 0; j < 7; j++)
#pragma unroll
            for (int u = 0; u < 4; u++) A[j][u] = 0ull;

        for (int chunk = 0; chunk < 16; chunk++) {
            const int ci0 = chunk << 4;
            __syncthreads();
            for (int q = t; q < 392; q += 224) {
                int s = (q >= 196) ? 1 : 0;
                int rem = q - (s ? 196 : 0);
                int p = rem >> 2, k4 = rem & 3;
                float4 v = *(const float4*)(g_act1 + ((size_t)(s ? s1 : s0) * 49 + p) * 256 + ci0 + (k4 << 2));
                int pi_ = p / 7, pj_ = p - 7 * pi_;
                float* dst = in_sh + ((1 + pi_) * 9 + 1 + pj_) * INSTRIDE + (k4 << 3) + s;
                dst[0] = v.x; dst[2] = v.y; dst[4] = v.z; dst[6] = v.w;
            }
            stage(wsm, Kc + ((size_t)tdd[0] * 256 + ci0) * 128, 128, t);            CP_COMMIT();
            stage(wsm + WBUF * 4, Kc + ((size_t)tdd[1] * 256 + ci0) * 128, 128, t); CP_COMMIT();

            for (int tt = 0; tt < nt; tt++) {
                CP_WAIT1();
                __syncthreads();
                if (tt + 2 < nt)
                    stage(wsm + (uint32_t)((tt + 2) % 3) * (WBUF * 4),
                          Kc + ((size_t)tdd[tt + 2] * 256 + ci0) * 128, 128, t);
                CP_COMMIT();
                compute128(in_sh, w_sh + (tt % 3) * WBUF, lane, tbase[tt], A);
            }
        }

#pragma unroll
        for (int jx = 0; jx < 7; jx++) {
            int oi = 2 * wrp + pi, oj = 2 * jx + pj;
            float2 v0 = unpk(A[jx][0]), v1 = unpk(A[jx][1]);
            float2 v2 = unpk(A[jx][2]), v3 = unpk(A[jx][3]);
            float4 ya;
            ya.x = lrelu((v0.x - mm.x) * sc.x + bb.x);
            ya.y = lrelu((v1.x - mm.y) * sc.y + bb.y);
            ya.z = lrelu((v2.x - mm.z) * sc.z + bb.z);
            ya.w = lrelu((v3.x - mm.w) * sc.w + bb.w);
            *(float4*)(o0 + (oi * 14 + oj) * C2 + cof) = ya;
            if (sok1) {
                float4 yb;
                yb.x = lrelu((v0.y - mm.x) * sc.x + bb.x);
                yb.y = lrelu((v1.y - mm.y) * sc.y + bb.y);
                yb.z = lrelu((v2.y - mm.z) * sc.z + bb.z);
                yb.w = lrelu((v3.y - mm.w) * sc.w + bb.w);
                *(float4*)(o1 + (oi * 14 + oj) * C2 + cof) = yb;
            }
        }
    }
}

// =====================================================================
// conv3: 5x5 s2, 128 -> 1, tanh
// =====================================================================
#define D_IN_SH (196 * C2)
#define D_W_SH  (25 * C2)

__global__ __launch_bounds__(256) void k_conv3(
    const int* __restrict__ labels, const float* __restrict__ K3,
    float* __restrict__ out)
{
    extern __shared__ float sm[];
    float4* in4 = (float4*)sm;
    float4* w4s = (float4*)(sm + D_IN_SH);
    const int b = blockIdx.x;
    const int t = threadIdx.x;
    const int c = labels[b];

    const float4* a2 = (const float4*)(g_act2 + (size_t)b * (196 * C2));
    for (int q = t; q < 196 * 32; q += 256) in4[q] = a2[q];
    const float4* k4 = (const float4*)(K3 + (size_t)c * 25 * C2);
    for (int q = t; q < 25 * 32; q += 256) w4s[q] = k4[q];
    __syncthreads();

    for (int px = t; px < 784; px += 256) {
        const int oi = px / 28, oj = px - oi * 28;
        float acc = 0.f;
        for (int ddi = (oi & 1) ? 0 : 1; ddi < 5; ddi += 2) {
            int ii = (oi + ddi - 3) >> 1;
            if ((unsigned)ii >= 14u) continue;
            for (int ddj = (oj & 1) ? 0 : 1; ddj < 5; ddj += 2) {
                int jj = (oj + ddj - 3) >> 1;
                if ((unsigned)jj >= 14u) continue;
                const float4* ip = in4 + (ii * 14 + jj) * 32;
                const float4* wp = w4s + (ddi * 5 + ddj) * 32;
#pragma unroll 8
                for (int q = 0; q < 32; q++) {
                    float4 a = ip[q], w = wp[q];
                    acc += a.x * w.x + a.y * w.y + a.z * w.z + a.w * w.w;
                }
            }
        }
        out[(size_t)b * 784 + px] = tanhf(acc);
    }
}

// =====================================================================
extern "C" void kernel_launch(void* const* d_in, const int* in_sizes, int n_in,
                              void* d_out, int out_size)
{
    const float* noise = (const float*)d_in[0];
    const int*   labels= (const int*)  d_in[1];
    const float* emb   = (const float*)d_in[2];
    const float* Wd    = (const float*)d_in[3];
    const float* bn1g  = (const float*)d_in[4];
    const float* bn1b  = (const float*)d_in[5];
    const float* bn1m  = (const float*)d_in[6];
    const float* bn1v  = (const float*)d_in[7];
    const float* K1    = (const float*)d_in[8];
    const float* G1    = (const float*)d_in[9];
    const float* B1    = (const float*)d_in[10];
    const float* M1    = (const float*)d_in[11];
    const float* V1    = (const float*)d_in[12];
    const float* K2    = (const float*)d_in[13];
    const float* G2    = (const float*)d_in[14];
    const float* B2    = (const float*)d_in[15];
    const float* M2    = (const float*)d_in[16];
    const float* V2    = (const float*)d_in[17];
    const float* K3    = (const float*)d_in[18];
    float* out = (float*)d_out;

    const int smD = (D_IN_SH + D_W_SH) * 4;
    cudaFuncSetAttribute(k_conv3, cudaFuncAttributeMaxDynamicSharedMemorySize, smD);

    k_bucket<<<1, 512>>>(labels);
    k_embw<<<dim3(25, 10), 256>>>(K1, emb);
    k_embe<<<dim3(49, 10), 256>>>(nullptr);
    k_dense<<<dim3(49, 64), 256>>>(noise, labels, emb, Wd, bn1g, bn1b, bn1m, bn1v);
    k_conv1<<<dim3(64, 2, 10), 224>>>(K1, G1, B1, M1, V1);
    k_conv2<<<dim3(64, 1, 10), 224>>>(K2, G2, B2, M2, V2);
    k_conv3<<<BATCH, 256, smD>>>(labels, K3, out);
}

// round 7
// speedup vs baseline: 4.4803x; 1.7468x over previous
#include <cuda_runtime.h>
#include <cuda_fp16.h>
#include <cstdint>

#define BATCH 512
#define NOISE 100
#define EMBD  50
#define NCLS  10
#define C1    256
#define C2    128

// ---------------- scratch ----------------
__device__ __align__(16) __half g_a0h[BATCH * 49 * 256];
__device__ __align__(16) __half g_a0l[BATCH * 49 * 256];
__device__ __align__(16) __half g_a1h[BATCH * 49 * 256];
__device__ __align__(16) __half g_a1l[BATCH * 49 * 256];
__device__ __align__(16) float  g_act2[BATCH * 196 * C2];
__device__ __align__(16) float  g_embf[NCLS * 49 * 256];
__device__ __align__(16) float  g_embw[NCLS * 25 * 256];
// packed weight fragments: [c][chunk16][tap25][ntile][ksub3][lane32] (uint2 = 2 b32 = b-frag)
__device__ __align__(16) uint2  g_W1[(size_t)NCLS * 16 * 25 * 32 * 3 * 32];
__device__ __align__(16) uint2  g_W2[(size_t)NCLS * 16 * 25 * 16 * 3 * 32];
__device__ int g_perm[BATCH];
__device__ int g_cnt[NCLS];
__device__ int g_off[NCLS];

__device__ __forceinline__ float lrelu(float x) { return x >= 0.f ? x : 0.3f * x; }

#define CP_COMMIT() asm volatile("cp.async.commit_group;" ::: "memory")
#define CP_WAIT1()  asm volatile("cp.async.wait_group 1;" ::: "memory")
#define CP_WAIT0()  asm volatile("cp.async.wait_group 0;" ::: "memory")

__device__ __forceinline__ void cp16(uint32_t saddr, const void* g) {
    asm volatile("cp.async.cg.shared.global [%0], [%1], 16;" :: "r"(saddr), "l"(g) : "memory");
}

#define LDSM4(a, addr) asm volatile( \
    "ldmatrix.sync.aligned.m8n8.x4.shared.b16 {%0,%1,%2,%3}, [%4];" \
    : "=r"(a[0]), "=r"(a[1]), "=r"(a[2]), "=r"(a[3]) : "r"(addr))

#define MMA(d, a, b) asm volatile( \
    "mma.sync.aligned.m16n8k16.row.col.f32.f16.f16.f32 " \
    "{%0,%1,%2,%3}, {%4,%5,%6,%7}, {%8,%9}, {%0,%1,%2,%3};" \
    : "+f"(d[0]), "+f"(d[1]), "+f"(d[2]), "+f"(d[3]) \
    : "r"(a[0]), "r"(a[1]), "r"(a[2]), "r"(a[3]), "r"(b.x), "r"(b.y))

// weight stage: 768 uint2 = 6144B = 384 x 16B, 224 threads
__device__ __forceinline__ void stage_w(uint32_t dsm, const uint2* src, int t) {
    for (int q = t; q < 384; q += 224) cp16(dsm + (uint32_t)q * 16u, (const char*)src + q * 16);
}

__device__ __forceinline__ uint32_t packsplit(float x, float y, __half& hx_out, __half& hy_out) {
    __half hx = __float2half(x), hy = __float2half(y);
    hx_out = hx; hy_out = hy;
    __half2 p = __halves2half2(hx, hy);
    return *(uint32_t*)&p;
}

// =====================================================================
__global__ __launch_bounds__(512) void k_bucket(const int* __restrict__ labels)
{
    __shared__ int scnt[NCLS], scur[NCLS];
    int t = threadIdx.x;
    if (t < NCLS) scnt[t] = 0;
    __syncthreads();
    int c = labels[t];
    atomicAdd(&scnt[c], 1);
    __syncthreads();
    if (t == 0) {
        int run = 0;
        for (int k = 0; k < NCLS; k++) { g_off[k] = run; scur[k] = run; g_cnt[k] = scnt[k]; run += scnt[k]; }
    }
    __syncthreads();
    int pos = atomicAdd(&scur[c], 1);
    g_perm[pos] = t;
}

// =====================================================================
// weight packing into b-fragment order with hi/lo split.
// b-frag lane mapping (m16n8k16): n = lane>>2, k0 = (lane&3)*2;
//   reg0 = {B[k0][n], B[k0+1][n]}, reg1 = {B[k0+8][n], B[k0+9][n]}
// ksub0 = hi_w, ksub1 = lo_w, ksub2 = hi_w (A side: hi, hi, lo)
// =====================================================================
__global__ __launch_bounds__(256) void k_packw1(const float* __restrict__ K1)
{
    int tap = blockIdx.x, chunk = blockIdx.y, c = blockIdx.z;
    int t = threadIdx.x, lane = t & 31;
    int k0 = (lane & 3) * 2, nq = lane >> 2;
    for (int nt = t >> 5; nt < 32; nt += 8) {
        int n = nt * 8 + nq;
        const float* src = K1 + (((size_t)c * 25 + tap) * 306 + chunk * 16) * 256 + n;
        float w0 = src[(size_t)(k0 + 0) * 256], w1 = src[(size_t)(k0 + 1) * 256];
        float w8 = src[(size_t)(k0 + 8) * 256], w9 = src[(size_t)(k0 + 9) * 256];
        __half h0, h1, h8, h9;
        uint2 hi; hi.x = packsplit(w0, w1, h0, h1); hi.y = packsplit(w8, w9, h8, h9);
        __half d0, d1, d8, d9;
        uint2 lo; lo.x = packsplit(w0 - __half2float(h0), w1 - __half2float(h1), d0, d1);
        lo.y = packsplit(w8 - __half2float(h8), w9 - __half2float(h9), d8, d9);
        size_t base = ((((size_t)c * 16 + chunk) * 25 + tap) * 32 + nt) * 96 + lane;
        g_W1[base] = hi; g_W1[base + 32] = lo; g_W1[base + 64] = hi;
    }
}

__global__ __launch_bounds__(256) void k_packw2(const float* __restrict__ K2)
{
    int tap = blockIdx.x, chunk = blockIdx.y, c = blockIdx.z;
    int t = threadIdx.x, lane = t & 31;
    int k0 = (lane & 3) * 2, nq = lane >> 2;
    for (int nt = t >> 5; nt < 16; nt += 8) {
        int n = nt * 8 + nq;
        const float* src = K2 + (((size_t)c * 25 + tap) * 256 + chunk * 16) * 128 + n;
        float w0 = src[(size_t)(k0 + 0) * 128], w1 = src[(size_t)(k0 + 1) * 128];
        float w8 = src[(size_t)(k0 + 8) * 128], w9 = src[(size_t)(k0 + 9) * 128];
        __half h0, h1, h8, h9;
        uint2 hi; hi.x = packsplit(w0, w1, h0, h1); hi.y = packsplit(w8, w9, h8, h9);
        __half d0, d1, d8, d9;
        uint2 lo; lo.x = packsplit(w0 - __half2float(h0), w1 - __half2float(h1), d0, d1);
        lo.y = packsplit(w8 - __half2float(h8), w9 - __half2float(h9), d8, d9);
        size_t base = ((((size_t)c * 16 + chunk) * 25 + tap) * 16 + nt) * 96 + lane;
        g_W2[base] = hi; g_W2[base + 32] = lo; g_W2[base + 64] = hi;
    }
}

// =====================================================================
// emb fold (conv1 bias field), fp32
// =====================================================================
__global__ __launch_bounds__(256) void k_embw(
    const float* __restrict__ K1, const float* __restrict__ emb)
{
    __shared__ float es[EMBD];
    int tap = blockIdx.x, c = blockIdx.y, t = threadIdx.x;
    if (t < EMBD) es[t] = emb[c * EMBD + t];
    __syncthreads();
    const float* kb = K1 + (((size_t)c * 25 + tap) * 306 + 256) * 256 + t;
    float acc = 0.f;
#pragma unroll 10
    for (int e = 0; e < EMBD; e++) acc += es[e] * kb[(size_t)e * 256];
    g_embw[((size_t)c * 25 + tap) * 256 + t] = acc;
}

__global__ __launch_bounds__(256) void k_embe(const float* dummy)
{
    int p = blockIdx.x, c = blockIdx.y, t = threadIdx.x;
    int i = p / 7, j = p - 7 * i;
    float acc = 0.f;
    for (int di = 0; di < 5; di++) {
        int ii = i + di - 2; if ((unsigned)ii >= 7u) continue;
        for (int dj = 0; dj < 5; dj++) {
            int jj = j + dj - 2; if ((unsigned)jj >= 7u) continue;
            acc += g_embw[((size_t)c * 25 + di * 5 + dj) * 256 + t];
        }
    }
    g_embf[((size_t)c * 49 + p) * 256 + t] = acc;
}

// =====================================================================
// dense + BN + LReLU -> act0 hi/lo fp16
// =====================================================================
__global__ __launch_bounds__(256) void k_dense(
    const float* __restrict__ noise, const int* __restrict__ labels,
    const float* __restrict__ emb,   const float* __restrict__ Wd,
    const float* __restrict__ bn_g,  const float* __restrict__ bn_b,
    const float* __restrict__ bn_m,  const float* __restrict__ bn_v)
{
    __shared__ float xs[8 * 152];
    const int t  = threadIdx.x;
    const int bx = blockIdx.x;
    const int b0 = blockIdx.y * 8;

    for (int idx = t; idx < 8 * 150; idx += 256) {
        int s = idx / 150, k = idx - s * 150;
        int bb = b0 + s;
        float val = (k < NOISE) ? noise[bb * NOISE + k]
                                : emb[labels[bb] * EMBD + (k - NOISE)];
        xs[s * 152 + k] = val;
    }
    __syncthreads();

    const int j = bx * 256 + t;
    float acc[8];
#pragma unroll
    for (int s = 0; s < 8; s++) acc[s] = 0.f;
    for (int k = 0; k < 150; k++) {
        float w = Wd[k * 12544 + j];
#pragma unroll
        for (int s = 0; s < 8; s++) acc[s] += xs[s * 152 + k] * w;
    }
    const float sc = rsqrtf(bn_v[j] + 1e-3f) * bn_g[j];
    const float mm = bn_m[j];
    const float bb = bn_b[j];
#pragma unroll
    for (int s = 0; s < 8; s++) {
        float y = lrelu((acc[s] - mm) * sc + bb);
        __half h = __float2half(y);
        __half l = __float2half(y - __half2float(h));
        size_t o = (size_t)(b0 + s) * (49 * 256) + j;
        g_a0h[o] = h; g_a0l[o] = l;
    }
}

// =====================================================================
// conv1: implicit GEMM, 4 samples/CTA, 64 co (8 n-tiles), 7 warps.
// A grid: [4 samples][11x11 padded][hi16|lo16], row = 40 fp16, plane = 121*40+8
// =====================================================================
#define SPL1   (121 * 40 + 8)          // 4848 fp16 per sample plane
#define A1_FP  19488                    // fp16 in A region (incl. overflow pad)
#define A1_B   (A1_FP * 2)              // 38976 bytes
#define WSLICE 768                      // uint2 per stage (8nt * 3ksub * 32)

__global__ __launch_bounds__(224, 2) void k_conv1(
    const float* __restrict__ G1, const float* __restrict__ B1,
    const float* __restrict__ M1, const float* __restrict__ V1)
{
    extern __shared__ __align__(16) char smraw[];
    __half* A = (__half*)smraw;
    uint2*  W = (uint2*)(smraw + A1_B);           // 3 ring buffers of WSLICE

    const int c = blockIdx.z;
    const int n_c = g_cnt[c];
    const int stile = blockIdx.x;
    if (stile * 4 >= n_c) return;
    const int by = blockIdx.y;                    // co quarter
    const int co0 = by * 64;
    const int t = threadIdx.x, lane = t & 31, wrp = t >> 5;
    const int base = g_off[c];

    int samp[4]; bool sok[4];
#pragma unroll
    for (int s = 0; s < 4; s++) {
        int idx = stile * 4 + s;
        sok[s] = idx < n_c;
        samp[s] = g_perm[base + (idx < n_c ? idx : n_c - 1)];
    }

    const uint32_t a_u32 = (uint32_t)__cvta_generic_to_shared(A);
    const uint32_t w_u32 = (uint32_t)__cvta_generic_to_shared(W);

    // per-lane ldmatrix bases: m = lane&15 -> jx = m>>2, s = m&3 ; khalf offset
    {
    }
    const int lm = lane & 15;
    const int ljx = lm >> 2, ls = lm & 3;
    const int koff = (lane >> 4) * 8;
    const uint32_t lb0 = a_u32 + (uint32_t)((ls * SPL1 + ljx * 40 + koff) * 2);
    const uint32_t lb1 = a_u32 + (uint32_t)((ls * SPL1 + (ljx + 4) * 40 + koff) * 2);

    // zero A
    for (int q = t; q < A1_FP / 8; q += 224) ((uint4*)A)[q] = make_uint4(0, 0, 0, 0);
    __syncthreads();

    float acc[2][8][4];
#pragma unroll
    for (int mb = 0; mb < 2; mb++)
#pragma unroll
        for (int nt = 0; nt < 8; nt++)
#pragma unroll
            for (int u = 0; u < 4; u++) acc[mb][nt][u] = 0.f;

    const uint2* wbase = g_W1 + (((size_t)c * 16) * 25 * 32 + (size_t)by * 8) * 96;
    // stage src for (chunk, tap): wbase + (chunk*25 + tap) * 32*96

    // refill chunk 0
    {
        const int ci0 = 0;
        for (int q = t; q < 392; q += 224) {
            int which = q >= 196;
            int rem = which ? q - 196 : q;
            int s = rem >> 6;            // not exact; do proper decomposition below
            // proper: rem in 0..195 -> s = rem/49, p = rem%49
            s = rem / 49; int p = rem - s * 49;
            const __half* src = (which ? g_a0l : g_a0h) + ((size_t)samp[s] * 49 + p) * 256 + ci0;
            int pi_ = p / 7, pj_ = p - 7 * pi_;
            __half* dst = A + s * SPL1 + ((2 + pi_) * 11 + 2 + pj_) * 40 + which * 16;
            ((uint4*)dst)[0] = ((const uint4*)src)[0];
            ((uint4*)dst)[1] = ((const uint4*)src)[1];
        }
    }
    __syncthreads();
    stage_w(w_u32, wbase + 0 * (32 * 96), t); CP_COMMIT();
    stage_w(w_u32 + WSLICE * 8, wbase + 1 * (32 * 96), t); CP_COMMIT();

    for (int st = 0; st < 400; st++) {
        const int chunk = st / 25, tap = st - chunk * 25;
        CP_WAIT1();
        __syncthreads();
        if (tap == 0 && st > 0) {
            const int ci0 = chunk * 16;
            for (int q = t; q < 392; q += 224) {
                int which = q >= 196;
                int rem = which ? q - 196 : q;
                int s = rem / 49, p = rem - s * 49;
                const __half* src = (which ? g_a0l : g_a0h) + ((size_t)samp[s] * 49 + p) * 256 + ci0;
                int pi_ = p / 7, pj_ = p - 7 * pi_;
                __half* dst = A + s * SPL1 + ((2 + pi_) * 11 + 2 + pj_) * 40 + which * 16;
                ((uint4*)dst)[0] = ((const uint4*)src)[0];
                ((uint4*)dst)[1] = ((const uint4*)src)[1];
            }
            __syncthreads();
        }
        if (st + 2 < 400) {
            int st2 = st + 2, ch2 = st2 / 25, tp2 = st2 - ch2 * 25;
            stage_w(w_u32 + (uint32_t)(st2 % 3) * (WSLICE * 8),
                    wbase + ((size_t)ch2 * 25 + tp2) * (32 * 96), t);
        }
        CP_COMMIT();

        const int di = tap / 5, dj = tap - 5 * di;
        const uint32_t goff = (uint32_t)(((wrp + di) * 11 + dj) * 80);
        const uint2* wb = W + (st % 3) * WSLICE + lane;
#pragma unroll
        for (int ksub = 0; ksub < 3; ksub++) {
            uint32_t sel = (ksub == 2) ? 32u : 0u;
            uint32_t a0[4], a1[4];
            LDSM4(a0, lb0 + goff + sel);
            LDSM4(a1, lb1 + goff + sel);
            const uint2* wk = wb + ksub * 32;
#pragma unroll
            for (int nt = 0; nt < 8; nt++) {
                uint2 b = wk[nt * 96];
                MMA(acc[0][nt], a0, b);
                MMA(acc[1][nt], a1, b);
            }
        }
    }

    // epilogue: + E, BN, LReLU -> act1 hi/lo
    const int g_ = lane >> 2;
    const int n_ = (lane & 3) * 2;
#pragma unroll
    for (int mb = 0; mb < 2; mb++) {
#pragma unroll
        for (int nt = 0; nt < 8; nt++) {
            int co = co0 + nt * 8 + n_;
            float2 gg = *(const float2*)(G1 + c * 256 + co);
            float2 bb = *(const float2*)(B1 + c * 256 + co);
            float2 mm = *(const float2*)(M1 + c * 256 + co);
            float2 vv = *(const float2*)(V1 + c * 256 + co);
            float sx = rsqrtf(vv.x + 1e-3f) * gg.x;
            float sy = rsqrtf(vv.y + 1e-3f) * gg.y;
#pragma unroll
            for (int h = 0; h < 2; h++) {
                int m = mb * 16 + g_ + h * 8;
                int jx = m >> 2, s = m & 3;
                if (jx < 7 && sok[s]) {
                    int pos = wrp * 7 + jx;
                    float2 E = *(const float2*)(g_embf + ((size_t)c * 49 + pos) * 256 + co);
                    float y0 = lrelu((acc[mb][nt][h * 2 + 0] + E.x - mm.x) * sx + bb.x);
                    float y1 = lrelu((acc[mb][nt][h * 2 + 1] + E.y - mm.y) * sy + bb.y);
                    __half h0 = __float2half(y0), h1 = __float2half(y1);
                    __half l0 = __float2half(y0 - __half2float(h0));
                    __half l1 = __float2half(y1 - __half2float(h1));
                    size_t o = ((size_t)samp[s] * 49 + pos) * 256 + co;
                    *(__half2*)(g_a1h + o) = __halves2half2(h0, h1);
                    *(__half2*)(g_a1l + o) = __halves2half2(l0, l1);
                }
            }
        }
    }
}

// =====================================================================
// conv2: parity-decomposed implicit GEMM, 4 samples/CTA, 64 co
// A grid: [4][9x9 padded][hi16|lo16], plane = 81*40+8
// =====================================================================
#define SPL2   (81 * 40 + 8)           // 3248
#define A2_FP  13072
#define A2_B   (A2_FP * 2)             // 26144 bytes

__global__ __launch_bounds__(224, 2) void k_conv2(
    const float* __restrict__ G2, const float* __restrict__ B2,
    const float* __restrict__ M2, const float* __restrict__ V2)
{
    extern __shared__ __align__(16) char smraw[];
    __half* A = (__half*)smraw;
    uint2*  W = (uint2*)(smraw + A2_B);

    const int c = blockIdx.z;
    const int n_c = g_cnt[c];
    const int stile = blockIdx.x;
    if (stile * 4 >= n_c) return;
    const int by = blockIdx.y;
    const int co0 = by * 64;
    const int t = threadIdx.x, lane = t & 31, wrp = t >> 5;
    const int base = g_off[c];

    int samp[4]; bool sok[4];
#pragma unroll
    for (int s = 0; s < 4; s++) {
        int idx = stile * 4 + s;
        sok[s] = idx < n_c;
        samp[s] = g_perm[base + (idx < n_c ? idx : n_c - 1)];
    }

    const uint32_t a_u32 = (uint32_t)__cvta_generic_to_shared(A);
    const uint32_t w_u32 = (uint32_t)__cvta_generic_to_shared(W);
    const int lm = lane & 15;
    const int ljx = lm >> 2, ls = lm & 3;
    const int koff = (lane >> 4) * 8;
    const uint32_t lb0 = a_u32 + (uint32_t)((ls * SPL2 + ljx * 40 + koff) * 2);
    const uint32_t lb1 = a_u32 + (uint32_t)((ls * SPL2 + (ljx + 4) * 40 + koff) * 2);

    for (int q = t; q < A2_FP / 8; q += 224) ((uint4*)A)[q] = make_uint4(0, 0, 0, 0);

    const uint2* wcls = g_W2 + (((size_t)c * 16) * 25 * 16 + (size_t)by * 8) * 96;
    const int g_ = lane >> 2;
    const int n_ = (lane & 3) * 2;

    for (int pp = 0; pp < 4; pp++) {
        const int pi = pp >> 1, pj = pp & 1;
        int tdd[9], gof[9], nt_taps = 0;
        {
            int ni = (pi == 0) ? 2 : 3, nj = (pj == 0) ? 2 : 3;
            for (int a = 0; a < ni; a++) {
                int ddi = (pi == 0) ? (1 + 2 * a) : (2 * a);
                int si = (ddi >> 1) - 1;
                for (int b2 = 0; b2 < nj; b2++) {
                    int ddj = (pj == 0) ? (1 + 2 * b2) : (2 * b2);
                    int sj = (ddj >> 1) - 1;
                    tdd[nt_taps] = ddi * 5 + ddj;
                    gof[nt_taps] = ((1 + wrp + si) * 9 + 1 + sj) * 80;
                    nt_taps++;
                }
            }
        }
        const int nst = 16 * nt_taps;

        float acc[2][8][4];
#pragma unroll
        for (int mb = 0; mb < 2; mb++)
#pragma unroll
            for (int nt = 0; nt < 8; nt++)
#pragma unroll
                for (int u = 0; u < 4; u++) acc[mb][nt][u] = 0.f;

        // prologue: drain, refill chunk0, prefetch 2 stages
        CP_WAIT0();
        __syncthreads();
        for (int q = t; q < 392; q += 224) {
            int which = q >= 196;
            int rem = which ? q - 196 : q;
            int s = rem / 49, p = rem - s * 49;
            const __half* src = (which ? g_a1l : g_a1h) + ((size_t)samp[s] * 49 + p) * 256;
            int pi_ = p / 7, pj_ = p - 7 * pi_;
            __half* dst = A + s * SPL2 + ((1 + pi_) * 9 + 1 + pj_) * 40 + which * 16;
            ((uint4*)dst)[0] = ((const uint4*)src)[0];
            ((uint4*)dst)[1] = ((const uint4*)src)[1];
        }
        __syncthreads();
        stage_w(w_u32, wcls + (size_t)tdd[0] * (16 * 96), t); CP_COMMIT();
        {
            int st2 = 1, ch = st2 / nt_taps, tt = st2 - ch * nt_taps;
            stage_w(w_u32 + WSLICE * 8, wcls + ((size_t)ch * 25 * 16 + (size_t)tdd[tt] * 16) * 96, t);
            CP_COMMIT();
        }

        for (int st = 0; st < nst; st++) {
            const int chunk = st / nt_taps, tt = st - chunk * nt_taps;
            CP_WAIT1();
            __syncthreads();
            if (tt == 0 && st > 0) {
                const int ci0 = chunk * 16;
                for (int q = t; q < 392; q += 224) {
                    int which = q >= 196;
                    int rem = which ? q - 196 : q;
                    int s = rem / 49, p = rem - s * 49;
                    const __half* src = (which ? g_a1l : g_a1h) + ((size_t)samp[s] * 49 + p) * 256 + ci0;
                    int pi_ = p / 7, pj_ = p - 7 * pi_;
                    __half* dst = A + s * SPL2 + ((1 + pi_) * 9 + 1 + pj_) * 40 + which * 16;
                    ((uint4*)dst)[0] = ((const uint4*)src)[0];
                    ((uint4*)dst)[1] = ((const uint4*)src)[1];
                }
                __syncthreads();
            }
            if (st + 2 < nst) {
                int st2 = st + 2, ch2 = st2 / nt_taps, tt2 = st2 - ch2 * nt_taps;
                stage_w(w_u32 + (uint32_t)(st2 % 3) * (WSLICE * 8),
                        wcls + ((size_t)ch2 * 25 * 16 + (size_t)tdd[tt2] * 16) * 96, t);
            }
            CP_COMMIT();

            const uint32_t goff = (uint32_t)gof[tt];
            const uint2* wb = W + (st % 3) * WSLICE + lane;
#pragma unroll
            for (int ksub = 0; ksub < 3; ksub++) {
                uint32_t sel = (ksub == 2) ? 32u : 0u;
                uint32_t a0[4], a1[4];
                LDSM4(a0, lb0 + goff + sel);
                LDSM4(a1, lb1 + goff + sel);
                const uint2* wk = wb + ksub * 32;
#pragma unroll
                for (int nt = 0; nt < 8; nt++) {
                    uint2 b = wk[nt * 96];
                    MMA(acc[0][nt], a0, b);
                    MMA(acc[1][nt], a1, b);
                }
            }
        }

        // epilogue this parity -> act2 fp32
#pragma unroll
        for (int mb = 0; mb < 2; mb++) {
#pragma unroll
            for (int nt = 0; nt < 8; nt++) {
                int co = co0 + nt * 8 + n_;
                float2 gg = *(const float2*)(G2 + c * 128 + co);
                float2 bb = *(const float2*)(B2 + c * 128 + co);
                float2 mm = *(const float2*)(M2 + c * 128 + co);
                float2 vv = *(const float2*)(V2 + c * 128 + co);
                float sx = rsqrtf(vv.x + 1e-3f) * gg.x;
                float sy = rsqrtf(vv.y + 1e-3f) * gg.y;
#pragma unroll
                for (int h = 0; h < 2; h++) {
                    int m = mb * 16 + g_ + h * 8;
                    int jx = m >> 2, s = m & 3;
                    if (jx < 7 && sok[s]) {
                        int oi = 2 * wrp + pi, oj = 2 * jx + pj;
                        float2 y;
                        y.x = lrelu((acc[mb][nt][h * 2 + 0] - mm.x) * sx + bb.x);
                        y.y = lrelu((acc[mb][nt][h * 2 + 1] - mm.y) * sy + bb.y);
                        *(float2*)(g_act2 + ((size_t)samp[s] * 196 + oi * 14 + oj) * 128 + co) = y;
                    }
                }
            }
        }
    }
}

// =====================================================================
// conv3: 5x5 s2, 128 -> 1, tanh
// =====================================================================
#define D_IN_SH (196 * C2)
#define D_W_SH  (25 * C2)

__global__ __launch_bounds__(256) void k_conv3(
    const int* __restrict__ labels, const float* __restrict__ K3,
    float* __restrict__ out)
{
    extern __shared__ float sm[];
    float4* in4 = (float4*)sm;
    float4* w4s = (float4*)(sm + D_IN_SH);
    const int b = blockIdx.x;
    const int t = threadIdx.x;
    const int c = labels[b];

    const float4* a2 = (const float4*)(g_act2 + (size_t)b * (196 * C2));
    for (int q = t; q < 196 * 32; q += 256) in4[q] = a2[q];
    const float4* k4 = (const float4*)(K3 + (size_t)c * 25 * C2);
    for (int q = t; q < 25 * 32; q += 256) w4s[q] = k4[q];
    __syncthreads();

    for (int px = t; px < 784; px += 256) {
        const int oi = px / 28, oj = px - oi * 28;
        float acc = 0.f;
        for (int ddi = (oi & 1) ? 0 : 1; ddi < 5; ddi += 2) {
            int ii = (oi + ddi - 3) >> 1;
            if ((unsigned)ii >= 14u) continue;
            for (int ddj = (oj & 1) ? 0 : 1; ddj < 5; ddj += 2) {
                int jj = (oj + ddj - 3) >> 1;
                if ((unsigned)jj >= 14u) continue;
                const float4* ip = in4 + (ii * 14 + jj) * 32;
                const float4* wp = w4s + (ddi * 5 + ddj) * 32;
#pragma unroll 8
                for (int q = 0; q < 32; q++) {
                    float4 a = ip[q], w = wp[q];
                    acc += a.x * w.x + a.y * w.y + a.z * w.z + a.w * w.w;
                }
            }
        }
        out[(size_t)b * 784 + px] = tanhf(acc);
    }
}

// =====================================================================
extern "C" void kernel_launch(void* const* d_in, const int* in_sizes, int n_in,
                              void* d_out, int out_size)
{
    const float* noise = (const float*)d_in[0];
    const int*   labels= (const int*)  d_in[1];
    const float* emb   = (const float*)d_in[2];
    const float* Wd    = (const float*)d_in[3];
    const float* bn1g  = (const float*)d_in[4];
    const float* bn1b  = (const float*)d_in[5];
    const float* bn1m  = (const float*)d_in[6];
    const float* bn1v  = (const float*)d_in[7];
    const float* K1    = (const float*)d_in[8];
    const float* G1    = (const float*)d_in[9];
    const float* B1    = (const float*)d_in[10];
    const float* M1    = (const float*)d_in[11];
    const float* V1    = (const float*)d_in[12];
    const float* K2    = (const float*)d_in[13];
    const float* G2    = (const float*)d_in[14];
    const float* B2    = (const float*)d_in[15];
    const float* M2    = (const float*)d_in[16];
    const float* V2    = (const float*)d_in[17];
    const float* K3    = (const float*)d_in[18];
    float* out = (float*)d_out;

    const int smB = A1_B + 3 * WSLICE * 8;   // 38976 + 18432 = 57408
    const int smC = A2_B + 3 * WSLICE * 8;   // 26144 + 18432 = 44576
    const int smD = (D_IN_SH + D_W_SH) * 4;
    cudaFuncSetAttribute(k_conv1, cudaFuncAttributeMaxDynamicSharedMemorySize, smB);
    cudaFuncSetAttribute(k_conv2, cudaFuncAttributeMaxDynamicSharedMemorySize, smC);
    cudaFuncSetAttribute(k_conv3, cudaFuncAttributeMaxDynamicSharedMemorySize, smD);

    k_bucket<<<1, 512>>>(labels);
    k_packw1<<<dim3(25, 16, 10), 256>>>(K1);
    k_packw2<<<dim3(25, 16, 10), 256>>>(K2);
    k_embw<<<dim3(25, 10), 256>>>(K1, emb);
    k_embe<<<dim3(49, 10), 256>>>(nullptr);
    k_dense<<<dim3(49, 64), 256>>>(noise, labels, emb, Wd, bn1g, bn1b, bn1m, bn1v);
    k_conv1<<<dim3(32, 4, 10), 224, smB>>>(G1, B1, M1, V1);
    k_conv2<<<dim3(32, 2, 10), 224, smC>>>(G2, B2, M2, V2);
    k_conv3<<<BATCH, 256, smD>>>(labels, K3, out);
}

// round 9
// speedup vs baseline: 4.5620x; 1.0182x over previous
#include <cuda_runtime.h>
#include <cuda_fp16.h>
#include <cstdint>

#define BATCH 512
#define NOISE 100
#define EMBD  50
#define NCLS  10
#define C1    256
#define C2    128

typedef unsigned long long ull;

// ---------------- scratch ----------------
__device__ __align__(16) __half g_a0h[BATCH * 49 * 256];
__device__ __align__(16) __half g_a0l[BATCH * 49 * 256];
__device__ __align__(16) __half g_a1h[BATCH * 49 * 256];
__device__ __align__(16) __half g_a1l[BATCH * 49 * 256];
__device__ __align__(16) float  g_act2[BATCH * 196 * C2];
__device__ __align__(16) float  g_embf[NCLS * 49 * 256];
__device__ __align__(16) float  g_embw[NCLS * 25 * 256];
// packed weight fragments: [c][chunk16][tap25][ntile][ksub2][lane32]
__device__ __align__(16) uint2  g_W1[(size_t)NCLS * 16 * 25 * 32 * 2 * 32];
__device__ __align__(16) uint2  g_W2[(size_t)NCLS * 16 * 25 * 16 * 2 * 32];
__device__ int g_perm[BATCH];
__device__ int g_cnt[NCLS];
__device__ int g_off[NCLS];

__device__ __forceinline__ float lrelu(float x) { return x >= 0.f ? x : 0.3f * x; }

__device__ __forceinline__ ull splat2(float a) {
    ull d; unsigned ai = __float_as_uint(a);
    asm("mov.b64 %0, {%1, %1};" : "=l"(d) : "r"(ai));
    return d;
}
__device__ __forceinline__ void ffma2(ull& c, ull a, ull b) {
    asm("fma.rn.f32x2 %0, %1, %2, %3;" : "=l"(c) : "l"(a), "l"(b), "l"(c));
}
__device__ __forceinline__ float2 unpk(ull v) {
    unsigned lo, hi;
    asm("mov.b64 {%0, %1}, %2;" : "=r"(lo), "=r"(hi) : "l"(v));
    return make_float2(__uint_as_float(lo), __uint_as_float(hi));
}

#define CP_COMMIT() asm volatile("cp.async.commit_group;" ::: "memory")
#define CP_WAIT1()  asm volatile("cp.async.wait_group 1;" ::: "memory")
#define CP_WAIT0()  asm volatile("cp.async.wait_group 0;" ::: "memory")

__device__ __forceinline__ void cp16(uint32_t saddr, const void* g) {
    asm volatile("cp.async.cg.shared.global [%0], [%1], 16;" :: "r"(saddr), "l"(g) : "memory");
}

#define LDSM4(a, addr) asm volatile( \
    "ldmatrix.sync.aligned.m8n8.x4.shared.b16 {%0,%1,%2,%3}, [%4];" \
    : "=r"(a[0]), "=r"(a[1]), "=r"(a[2]), "=r"(a[3]) : "r"(addr))

#define MMA(d, a, b) asm volatile( \
    "mma.sync.aligned.m16n8k16.row.col.f32.f16.f16.f32 " \
    "{%0,%1,%2,%3}, {%4,%5,%6,%7}, {%8,%9}, {%0,%1,%2,%3};" \
    : "+f"(d[0]), "+f"(d[1]), "+f"(d[2]), "+f"(d[3]) \
    : "r"(a[0]), "r"(a[1]), "r"(a[2]), "r"(a[3]), "r"(b.x), "r"(b.y))

#define WSLICE 512                      // uint2 per stage (8nt * 2ksub * 32)

// weight stage: 512 uint2 = 4096B = 256 x 16B, 224 threads
__device__ __forceinline__ void stage_w(uint32_t dsm, const uint2* src, int t) {
    for (int q = t; q < 256; q += 224) cp16(dsm + (uint32_t)q * 16u, (const char*)src + q * 16);
}

// =====================================================================
__global__ __launch_bounds__(512) void k_bucket(const int* __restrict__ labels)
{
    __shared__ int scnt[NCLS], scur[NCLS];
    int t = threadIdx.x;
    if (t < NCLS) scnt[t] = 0;
    __syncthreads();
    int c = labels[t];
    atomicAdd(&scnt[c], 1);
    __syncthreads();
    if (t == 0) {
        int run = 0;
        for (int k = 0; k < NCLS; k++) { g_off[k] = run; scur[k] = run; g_cnt[k] = scnt[k]; run += scnt[k]; }
    }
    __syncthreads();
    int pos = atomicAdd(&scur[c], 1);
    g_perm[pos] = t;
}

// =====================================================================
// coalesced weight packing. b-frag lane map (m16n8k16): n = lane>>2,
// k0 = (lane&3)*2; reg0 = {B[k0][n],B[k0+1][n]}, reg1 = {B[k0+8][n],B[k0+9][n]}
// ksub0 = hi, ksub1 = lo  (ksub2 of the split reuses the hi frag in-kernel)
// =====================================================================
#define TP1 257
__global__ __launch_bounds__(256) void k_packw1(const float* __restrict__ K1)
{
    __shared__ float tile[16 * TP1];
    int tap = blockIdx.x, chunk = blockIdx.y, c = blockIdx.z;
    int t = threadIdx.x;
    const float* src = K1 + (((size_t)c * 25 + tap) * 306 + chunk * 16) * 256;
    for (int idx = t; idx < 4096; idx += 256) {
        int r = idx >> 8, col = idx & 255;
        tile[r * TP1 + col] = src[idx];
    }
    __syncthreads();
    int lane = t & 31, wp = t >> 5;
    int k0 = (lane & 3) * 2, nq = lane >> 2;
    for (int nt = wp; nt < 32; nt += 8) {
        int n = nt * 8 + nq;
        float w0 = tile[(k0 + 0) * TP1 + n], w1 = tile[(k0 + 1) * TP1 + n];
        float w8 = tile[(k0 + 8) * TP1 + n], w9 = tile[(k0 + 9) * TP1 + n];
        __half h0 = __float2half(w0), h1 = __float2half(w1);
        __half h8 = __float2half(w8), h9 = __float2half(w9);
        __half2 p0 = __halves2half2(h0, h1), p1 = __halves2half2(h8, h9);
        uint2 hi; hi.x = *(uint32_t*)&p0; hi.y = *(uint32_t*)&p1;
        __half2 q0 = __halves2half2(__float2half(w0 - __half2float(h0)), __float2half(w1 - __half2float(h1)));
        __half2 q1 = __halves2half2(__float2half(w8 - __half2float(h8)), __float2half(w9 - __half2float(h9)));
        uint2 lo; lo.x = *(uint32_t*)&q0; lo.y = *(uint32_t*)&q1;
        size_t base = ((((size_t)c * 16 + chunk) * 25 + tap) * 32 + nt) * 64 + lane;
        g_W1[base] = hi; g_W1[base + 32] = lo;
    }
}

#define TP2 129
__global__ __launch_bounds__(256) void k_packw2(const float* __restrict__ K2)
{
    __shared__ float tile[16 * TP2];
    int tap = blockIdx.x, chunk = blockIdx.y, c = blockIdx.z;
    int t = threadIdx.x;
    const float* src = K2 + (((size_t)c * 25 + tap) * 256 + chunk * 16) * 128;
    for (int idx = t; idx < 2048; idx += 256) {
        int r = idx >> 7, col = idx & 127;
        tile[r * TP2 + col] = src[idx];
    }
    __syncthreads();
    int lane = t & 31, wp = t >> 5;
    int k0 = (lane & 3) * 2, nq = lane >> 2;
    for (int nt = wp; nt < 16; nt += 8) {
        int n = nt * 8 + nq;
        float w0 = tile[(k0 + 0) * TP2 + n], w1 = tile[(k0 + 1) * TP2 + n];
        float w8 = tile[(k0 + 8) * TP2 + n], w9 = tile[(k0 + 9) * TP2 + n];
        __half h0 = __float2half(w0), h1 = __float2half(w1);
        __half h8 = __float2half(w8), h9 = __float2half(w9);
        __half2 p0 = __halves2half2(h0, h1), p1 = __halves2half2(h8, h9);
        uint2 hi; hi.x = *(uint32_t*)&p0; hi.y = *(uint32_t*)&p1;
        __half2 q0 = __halves2half2(__float2half(w0 - __half2float(h0)), __float2half(w1 - __half2float(h1)));
        __half2 q1 = __halves2half2(__float2half(w8 - __half2float(h8)), __float2half(w9 - __half2float(h9)));
        uint2 lo; lo.x = *(uint32_t*)&q0; lo.y = *(uint32_t*)&q1;
        size_t base = ((((size_t)c * 16 + chunk) * 25 + tap) * 16 + nt) * 64 + lane;
        g_W2[base] = hi; g_W2[base + 32] = lo;
    }
}

// =====================================================================
// emb fold (conv1 bias field), fp32
// =====================================================================
__global__ __launch_bounds__(256) void k_embw(
    const float* __restrict__ K1, const float* __restrict__ emb)
{
    __shared__ float es[EMBD];
    int tap = blockIdx.x, c = blockIdx.y, t = threadIdx.x;
    if (t < EMBD) es[t] = emb[c * EMBD + t];
    __syncthreads();
    const float* kb = K1 + (((size_t)c * 25 + tap) * 306 + 256) * 256 + t;
    float acc = 0.f;
#pragma unroll 10
    for (int e = 0; e < EMBD; e++) acc += es[e] * kb[(size_t)e * 256];
    g_embw[((size_t)c * 25 + tap) * 256 + t] = acc;
}

__global__ __launch_bounds__(256) void k_embe(const float* dummy)
{
    int p = blockIdx.x, c = blockIdx.y, t = threadIdx.x;
    int i = p / 7, j = p - 7 * i;
    float acc = 0.f;
    for (int di = 0; di < 5; di++) {
        int ii = i + di - 2; if ((unsigned)ii >= 7u) continue;
        for (int dj = 0; dj < 5; dj++) {
            int jj = j + dj - 2; if ((unsigned)jj >= 7u) continue;
            acc += g_embw[((size_t)c * 25 + di * 5 + dj) * 256 + t];
        }
    }
    g_embf[((size_t)c * 49 + p) * 256 + t] = acc;
}

// =====================================================================
// dense + BN + LReLU -> act0 hi/lo fp16 (f32x2 over sample pairs)
// =====================================================================
__global__ __launch_bounds__(256) void k_dense(
    const float* __restrict__ noise, const int* __restrict__ labels,
    const float* __restrict__ emb,   const float* __restrict__ Wd,
    const float* __restrict__ bn_g,  const float* __restrict__ bn_b,
    const float* __restrict__ bn_m,  const float* __restrict__ bn_v)
{
    __shared__ __align__(8) float2 xs2[150 * 4];
    const int t  = threadIdx.x;
    const int bx = blockIdx.x;
    const int b0 = blockIdx.y * 8;

    for (int idx = t; idx < 8 * 150; idx += 256) {
        int s = idx / 150, k = idx - s * 150;
        int bb = b0 + s;
        float val = (k < NOISE) ? noise[bb * NOISE + k]
                                : emb[labels[bb] * EMBD + (k - NOISE)];
        ((float*)&xs2[k * 4 + (s >> 1)])[s & 1] = val;
    }
    __syncthreads();

    const int j = bx * 256 + t;
    ull acc2[4];
#pragma unroll
    for (int pr = 0; pr < 4; pr++) acc2[pr] = 0ull;
    for (int k = 0; k < 150; k++) {
        ull ws = splat2(Wd[k * 12544 + j]);
#pragma unroll
        for (int pr = 0; pr < 4; pr++) {
            ull a = *(const ull*)&xs2[k * 4 + pr];
            ffma2(acc2[pr], a, ws);
        }
    }
    const float sc = rsqrtf(bn_v[j] + 1e-3f) * bn_g[j];
    const float mm = bn_m[j];
    const float bb = bn_b[j];
#pragma unroll
    for (int pr = 0; pr < 4; pr++) {
        float2 v = unpk(acc2[pr]);
#pragma unroll
        for (int h2 = 0; h2 < 2; h2++) {
            float y = lrelu(((h2 ? v.y : v.x) - mm) * sc + bb);
            __half h = __float2half(y);
            __half l = __float2half(y - __half2float(h));
            size_t o = (size_t)(b0 + pr * 2 + h2) * (49 * 256) + j;
            g_a0h[o] = h; g_a0l[o] = l;
        }
    }
}

// =====================================================================
// conv1: implicit GEMM, 4 samples/CTA, 64 co (8 n-tiles), 7 warps.
// A grid: [4 samples][11x11 padded][hi16|lo16], row = 40 fp16, plane = 121*40+8
// =====================================================================
#define SPL1   (121 * 40 + 8)          // 4848 fp16 per sample plane
#define A1_FP  19488
#define A1_B   (A1_FP * 2)             // 38976 bytes

__global__ __launch_bounds__(224, 2) void k_conv1(
    const float* __restrict__ G1, const float* __restrict__ B1,
    const float* __restrict__ M1, const float* __restrict__ V1)
{
    extern __shared__ __align__(16) char smraw[];
    __half* A = (__half*)smraw;
    uint2*  W = (uint2*)(smraw + A1_B);           // 3 ring buffers of WSLICE

    const int c = blockIdx.z;
    const int n_c = g_cnt[c];
    const int stile = blockIdx.x;
    if (stile * 4 >= n_c) return;
    const int by = blockIdx.y;                    // co quarter
    const int co0 = by * 64;
    const int t = threadIdx.x, lane = t & 31, wrp = t >> 5;
    const int base = g_off[c];

    int samp[4]; bool sok[4];
#pragma unroll
    for (int s = 0; s < 4; s++) {
        int idx = stile * 4 + s;
        sok[s] = idx < n_c;
        samp[s] = g_perm[base + (idx < n_c ? idx : n_c - 1)];
    }

    const uint32_t a_u32 = (uint32_t)__cvta_generic_to_shared(A);
    const uint32_t w_u32 = (uint32_t)__cvta_generic_to_shared(W);

    const int lm = lane & 15;
    const int ljx = lm >> 2, ls = lm & 3;
    const int koff = (lane >> 4) * 8;
    const uint32_t lb0 = a_u32 + (uint32_t)((ls * SPL1 + ljx * 40 + koff) * 2);
    const uint32_t lb1 = a_u32 + (uint32_t)((ls * SPL1 + (ljx + 4) * 40 + koff) * 2);

    for (int q = t; q < A1_FP / 8; q += 224) ((uint4*)A)[q] = make_uint4(0, 0, 0, 0);
    __syncthreads();

    float acc[2][8][4];
#pragma unroll
    for (int mb = 0; mb < 2; mb++)
#pragma unroll
        for (int nt = 0; nt < 8; nt++)
#pragma unroll
            for (int u = 0; u < 4; u++) acc[mb][nt][u] = 0.f;

    const uint2* wbase = g_W1 + (((size_t)c * 16) * 25 * 32 + (size_t)by * 8) * 64;

    // refill chunk 0
    for (int q = t; q < 392; q += 224) {
        int which = q >= 196;
        int rem = which ? q - 196 : q;
        int s = rem / 49, p = rem - s * 49;
        const __half* src = (which ? g_a0l : g_a0h) + ((size_t)samp[s] * 49 + p) * 256;
        int pi_ = p / 7, pj_ = p - 7 * pi_;
        __half* dst = A + s * SPL1 + ((2 + pi_) * 11 + 2 + pj_) * 40 + which * 16;
        ((uint4*)dst)[0] = ((const uint4*)src)[0];
        ((uint4*)dst)[1] = ((const uint4*)src)[1];
    }
    __syncthreads();
    stage_w(w_u32, wbase + 0 * (32 * 64), t); CP_COMMIT();
    stage_w(w_u32 + WSLICE * 8, wbase + 1 * (32 * 64), t); CP_COMMIT();

    for (int st = 0; st < 400; st++) {
        const int chunk = st / 25, tap = st - chunk * 25;
        CP_WAIT1();
        __syncthreads();
        if (tap == 0 && st > 0) {
            const int ci0 = chunk * 16;
            for (int q = t; q < 392; q += 224) {
                int which = q >= 196;
                int rem = which ? q - 196 : q;
                int s = rem / 49, p = rem - s * 49;
                const __half* src = (which ? g_a0l : g_a0h) + ((size_t)samp[s] * 49 + p) * 256 + ci0;
                int pi_ = p / 7, pj_ = p - 7 * pi_;
                __half* dst = A + s * SPL1 + ((2 + pi_) * 11 + 2 + pj_) * 40 + which * 16;
                ((uint4*)dst)[0] = ((const uint4*)src)[0];
                ((uint4*)dst)[1] = ((const uint4*)src)[1];
            }
            __syncthreads();
        }
        if (st + 2 < 400) {
            int st2 = st + 2, ch2 = st2 / 25, tp2 = st2 - ch2 * 25;
            stage_w(w_u32 + (uint32_t)(st2 % 3) * (WSLICE * 8),
                    wbase + ((size_t)ch2 * 25 + tp2) * (32 * 64), t);
        }
        CP_COMMIT();

        const int di = tap / 5, dj = tap - 5 * di;
        const uint32_t goff = (uint32_t)(((wrp + di) * 11 + dj) * 80);
        const uint2* wb = W + (st % 3) * WSLICE + lane;
#pragma unroll
        for (int ksub = 0; ksub < 3; ksub++) {
            uint32_t asel = (ksub == 2) ? 32u : 0u;
            uint32_t boff = (ksub == 1) ? 32u : 0u;
            uint32_t a0[4], a1[4];
            LDSM4(a0, lb0 + goff + asel);
            LDSM4(a1, lb1 + goff + asel);
            const uint2* wk = wb + boff;
#pragma unroll
            for (int nt = 0; nt < 8; nt++) {
                uint2 b = wk[nt * 64];
                MMA(acc[0][nt], a0, b);
                MMA(acc[1][nt], a1, b);
            }
        }
    }

    // epilogue: + E, BN, LReLU -> act1 hi/lo
    const int g_ = lane >> 2;
    const int n_ = (lane & 3) * 2;
#pragma unroll
    for (int mb = 0; mb < 2; mb++) {
#pragma unroll
        for (int nt = 0; nt < 8; nt++) {
            int co = co0 + nt * 8 + n_;
            float2 gg = *(const float2*)(G1 + c * 256 + co);
            float2 bb = *(const float2*)(B1 + c * 256 + co);
            float2 mm = *(const float2*)(M1 + c * 256 + co);
            float2 vv = *(const float2*)(V1 + c * 256 + co);
            float sx = rsqrtf(vv.x + 1e-3f) * gg.x;
            float sy = rsqrtf(vv.y + 1e-3f) * gg.y;
#pragma unroll
            for (int h = 0; h < 2; h++) {
                int m = mb * 16 + g_ + h * 8;
                int jx = m >> 2, s = m & 3;
                if (jx < 7 && sok[s]) {
                    int pos = wrp * 7 + jx;
                    float2 E = *(const float2*)(g_embf + ((size_t)c * 49 + pos) * 256 + co);
                    float y0 = lrelu((acc[mb][nt][h * 2 + 0] + E.x - mm.x) * sx + bb.x);
                    float y1 = lrelu((acc[mb][nt][h * 2 + 1] + E.y - mm.y) * sy + bb.y);
                    __half h0 = __float2half(y0), h1 = __float2half(y1);
                    __half l0 = __float2half(y0 - __half2float(h0));
                    __half l1 = __float2half(y1 - __half2float(h1));
                    size_t o = ((size_t)samp[s] * 49 + pos) * 256 + co;
                    *(__half2*)(g_a1h + o) = __halves2half2(h0, h1);
                    *(__half2*)(g_a1l + o) = __halves2half2(l0, l1);
                }
            }
        }
    }
}

// =====================================================================
// conv2: parity-decomposed implicit GEMM, 4 samples/CTA, 64 co
// =====================================================================
#define SPL2   (81 * 40 + 8)           // 3248
#define A2_FP  13072
#define A2_B   (A2_FP * 2)             // 26144 bytes

__global__ __launch_bounds__(224, 2) void k_conv2(
    const float* __restrict__ G2, const float* __restrict__ B2,
    const float* __restrict__ M2, const float* __restrict__ V2)
{
    extern __shared__ __align__(16) char smraw[];
    __half* A = (__half*)smraw;
    uint2*  W = (uint2*)(smraw + A2_B);

    const int c = blockIdx.z;
    const int n_c = g_cnt[c];
    const int stile = blockIdx.x;
    if (stile * 4 >= n_c) return;
    const int by = blockIdx.y;
    const int co0 = by * 64;
    const int t = threadIdx.x, lane = t & 31, wrp = t >> 5;
    const int base = g_off[c];

    int samp[4]; bool sok[4];
#pragma unroll
    for (int s = 0; s < 4; s++) {
        int idx = stile * 4 + s;
        sok[s] = idx < n_c;
        samp[s] = g_perm[base + (idx < n_c ? idx : n_c - 1)];
    }

    const uint32_t a_u32 = (uint32_t)__cvta_generic_to_shared(A);
    const uint32_t w_u32 = (uint32_t)__cvta_generic_to_shared(W);
    const int lm = lane & 15;
    const int ljx = lm >> 2, ls = lm & 3;
    const int koff = (lane >> 4) * 8;
    const uint32_t lb0 = a_u32 + (uint32_t)((ls * SPL2 + ljx * 40 + koff) * 2);
    const uint32_t lb1 = a_u32 + (uint32_t)((ls * SPL2 + (ljx + 4) * 40 + koff) * 2);

    for (int q = t; q < A2_FP / 8; q += 224) ((uint4*)A)[q] = make_uint4(0, 0, 0, 0);

    const uint2* wcls = g_W2 + ((size_t)c * 16 * 25 * 16 + (size_t)by * 8) * 64;
    const int g_ = lane >> 2;
    const int n_ = (lane & 3) * 2;

    for (int pp = 0; pp < 4; pp++) {
        const int pi = pp >> 1, pj = pp & 1;
        int tdd[9], gof[9], nt_taps = 0;
        {
            int ni = (pi == 0) ? 2 : 3, nj = (pj == 0) ? 2 : 3;
            for (int a = 0; a < ni; a++) {
                int ddi = (pi == 0) ? (1 + 2 * a) : (2 * a);
                int si = (ddi >> 1) - 1;
                for (int b2 = 0; b2 < nj; b2++) {
                    int ddj = (pj == 0) ? (1 + 2 * b2) : (2 * b2);
                    int sj = (ddj >> 1) - 1;
                    tdd[nt_taps] = ddi * 5 + ddj;
                    gof[nt_taps] = ((1 + wrp + si) * 9 + 1 + sj) * 80;
                    nt_taps++;
                }
            }
        }
        const int nst = 16 * nt_taps;

        float acc[2][8][4];
#pragma unroll
        for (int mb = 0; mb < 2; mb++)
#pragma unroll
            for (int nt = 0; nt < 8; nt++)
#pragma unroll
                for (int u = 0; u < 4; u++) acc[mb][nt][u] = 0.f;

        CP_WAIT0();
        __syncthreads();
        for (int q = t; q < 392; q += 224) {
            int which = q >= 196;
            int rem = which ? q - 196 : q;
            int s = rem / 49, p = rem - s * 49;
            const __half* src = (which ? g_a1l : g_a1h) + ((size_t)samp[s] * 49 + p) * 256;
            int pi_ = p / 7, pj_ = p - 7 * pi_;
            __half* dst = A + s * SPL2 + ((1 + pi_) * 9 + 1 + pj_) * 40 + which * 16;
            ((uint4*)dst)[0] = ((const uint4*)src)[0];
            ((uint4*)dst)[1] = ((const uint4*)src)[1];
        }
        __syncthreads();
        stage_w(w_u32, wcls + ((size_t)tdd[0]) * (16 * 64), t); CP_COMMIT();
        {
            int st2 = 1, ch = st2 / nt_taps, tt = st2 - ch * nt_taps;
            stage_w(w_u32 + WSLICE * 8, wcls + ((size_t)ch * 25 + tdd[tt]) * (16 * 64), t);
            CP_COMMIT();
        }

        for (int st = 0; st < nst; st++) {
            const int chunk = st / nt_taps, tt = st - chunk * nt_taps;
            CP_WAIT1();
            __syncthreads();
            if (tt == 0 && st > 0) {
                const int ci0 = chunk * 16;
                for (int q = t; q < 392; q += 224) {
                    int which = q >= 196;
                    int rem = which ? q - 196 : q;
                    int s = rem / 49, p = rem - s * 49;
                    const __half* src = (which ? g_a1l : g_a1h) + ((size_t)samp[s] * 49 + p) * 256 + ci0;
                    int pi_ = p / 7, pj_ = p - 7 * pi_;
                    __half* dst = A + s * SPL2 + ((1 + pi_) * 9 + 1 + pj_) * 40 + which * 16;
                    ((uint4*)dst)[0] = ((const uint4*)src)[0];
                    ((uint4*)dst)[1] = ((const uint4*)src)[1];
                }
                __syncthreads();
            }
            if (st + 2 < nst) {
                int st2 = st + 2, ch2 = st2 / nt_taps, tt2 = st2 - ch2 * nt_taps;
                stage_w(w_u32 + (uint32_t)(st2 % 3) * (WSLICE * 8),
                        wcls + ((size_t)ch2 * 25 + tdd[tt2]) * (16 * 64), t);
            }
            CP_COMMIT();

            const uint32_t goff = (uint32_t)gof[tt];
            const uint2* wb = W + (st % 3) * WSLICE + lane;
#pragma unroll
            for (int ksub = 0; ksub < 3; ksub++) {
                uint32_t asel = (ksub == 2) ? 32u : 0u;
                uint32_t boff = (ksub == 1) ? 32u : 0u;
                uint32_t a0[4], a1[4];
                LDSM4(a0, lb0 + goff + asel);
                LDSM4(a1, lb1 + goff + asel);
                const uint2* wk = wb + boff;
#pragma unroll
                for (int nt = 0; nt < 8; nt++) {
                    uint2 b = wk[nt * 64];
                    MMA(acc[0][nt], a0, b);
                    MMA(acc[1][nt], a1, b);
                }
            }
        }

#pragma unroll
        for (int mb = 0; mb < 2; mb++) {
#pragma unroll
            for (int nt = 0; nt < 8; nt++) {
                int co = co0 + nt * 8 + n_;
                float2 gg = *(const float2*)(G2 + c * 128 + co);
                float2 bb = *(const float2*)(B2 + c * 128 + co);
                float2 mm = *(const float2*)(M2 + c * 128 + co);
                float2 vv = *(const float2*)(V2 + c * 128 + co);
                float sx = rsqrtf(vv.x + 1e-3f) * gg.x;
                float sy = rsqrtf(vv.y + 1e-3f) * gg.y;
#pragma unroll
                for (int h = 0; h < 2; h++) {
                    int m = mb * 16 + g_ + h * 8;
                    int jx = m >> 2, s = m & 3;
                    if (jx < 7 && sok[s]) {
                        int oi = 2 * wrp + pi, oj = 2 * jx + pj;
                        float2 y;
                        y.x = lrelu((acc[mb][nt][h * 2 + 0] - mm.x) * sx + bb.x);
                        y.y = lrelu((acc[mb][nt][h * 2 + 1] - mm.y) * sy + bb.y);
                        *(float2*)(g_act2 + ((size_t)samp[s] * 196 + oi * 14 + oj) * 128 + co) = y;
                    }
                }
            }
        }
    }
}

// =====================================================================
// conv3: 5x5 s2, 128 -> 1, tanh
// =====================================================================
#define D_IN_SH (196 * C2)
#define D_W_SH  (25 * C2)

__global__ __launch_bounds__(256) void k_conv3(
    const int* __restrict__ labels, const float* __restrict__ K3,
    float* __restrict__ out)
{
    extern __shared__ float sm[];
    float4* in4 = (float4*)sm;
    float4* w4s = (float4*)(sm + D_IN_SH);
    const int b = blockIdx.x;
    const int t = threadIdx.x;
    const int c = labels[b];

    const float4* a2 = (const float4*)(g_act2 + (size_t)b * (196 * C2));
    for (int q = t; q < 196 * 32; q += 256) in4[q] = a2[q];
    const float4* k4 = (const float4*)(K3 + (size_t)c * 25 * C2);
    for (int q = t; q < 25 * 32; q += 256) w4s[q] = k4[q];
    __syncthreads();

    for (int px = t; px < 784; px += 256) {
        const int oi = px / 28, oj = px - oi * 28;
        float acc = 0.f;
        for (int ddi = (oi & 1) ? 0 : 1; ddi < 5; ddi += 2) {
            int ii = (oi + ddi - 3) >> 1;
            if ((unsigned)ii >= 14u) continue;
            for (int ddj = (oj & 1) ? 0 : 1; ddj < 5; ddj += 2) {
                int jj = (oj + ddj - 3) >> 1;
                if ((unsigned)jj >= 14u) continue;
                const float4* ip = in4 + (ii * 14 + jj) * 32;
                const float4* wp = w4s + (ddi * 5 + ddj) * 32;
#pragma unroll 8
                for (int q = 0; q < 32; q++) {
                    float4 a = ip[q], w = wp[q];
                    acc += a.x * w.x + a.y * w.y + a.z * w.z + a.w * w.w;
                }
            }
        }
        out[(size_t)b * 784 + px] = tanhf(acc);
    }
}

// =====================================================================
extern "C" void kernel_launch(void* const* d_in, const int* in_sizes, int n_in,
                              void* d_out, int out_size)
{
    const float* noise = (const float*)d_in[0];
    const int*   labels= (const int*)  d_in[1];
    const float* emb   = (const float*)d_in[2];
    const float* Wd    = (const float*)d_in[3];
    const float* bn1g  = (const float*)d_in[4];
    const float* bn1b  = (const float*)d_in[5];
    const float* bn1m  = (const float*)d_in[6];
    const float* bn1v  = (const float*)d_in[7];
    const float* K1    = (const float*)d_in[8];
    const float* G1    = (const float*)d_in[9];
    const float* B1    = (const float*)d_in[10];
    const float* M1    = (const float*)d_in[11];
    const float* V1    = (const float*)d_in[12];
    const float* K2    = (const float*)d_in[13];
    const float* G2    = (const float*)d_in[14];
    const float* B2    = (const float*)d_in[15];
    const float* M2    = (const float*)d_in[16];
    const float* V2    = (const float*)d_in[17];
    const float* K3    = (const float*)d_in[18];
    float* out = (float*)d_out;

    const int smB = A1_B + 3 * WSLICE * 8;   // 38976 + 12288 = 51264
    const int smC = A2_B + 3 * WSLICE * 8;   // 26144 + 12288 = 38432
    const int smD = (D_IN_SH + D_W_SH) * 4;
    cudaFuncSetAttribute(k_conv1, cudaFuncAttributeMaxDynamicSharedMemorySize, smB);
    cudaFuncSetAttribute(k_conv2, cudaFuncAttributeMaxDynamicSharedMemorySize, smC);
    cudaFuncSetAttribute(k_conv3, cudaFuncAttributeMaxDynamicSharedMemorySize, smD);

    k_bucket<<<1, 512>>>(labels);
    k_packw1<<<dim3(25, 16, 10), 256>>>(K1);
    k_packw2<<<dim3(25, 16, 10), 256>>>(K2);
    k_embw<<<dim3(25, 10), 256>>>(K1, emb);
    k_embe<<<dim3(49, 10), 256>>>(nullptr);
    k_dense<<<dim3(49, 64), 256>>>(noise, labels, emb, Wd, bn1g, bn1b, bn1m, bn1v);
    k_conv1<<<dim3(32, 4, 10), 224, smB>>>(G1, B1, M1, V1);
    k_conv2<<<dim3(32, 2, 10), 224, smC>>>(G2, B2, M2, V2);
    k_conv3<<<BATCH, 256, smD>>>(labels, K3, out);
}

// round 10
// speedup vs baseline: 4.8487x; 1.0628x over previous
#include <cuda_runtime.h>
#include <cuda_fp16.h>
#include <cstdint>

#define BATCH 512
#define NOISE 100
#define EMBD  50
#define NCLS  10
#define C1    256
#define C2    128

typedef unsigned long long ull;

// ---------------- scratch ----------------
__device__ __align__(16) __half g_a0h[BATCH * 49 * 256];
__device__ __align__(16) __half g_a0l[BATCH * 49 * 256];
__device__ __align__(16) __half g_a1h[BATCH * 49 * 256];
__device__ __align__(16) __half g_a1l[BATCH * 49 * 256];
__device__ __align__(16) float  g_act2[BATCH * 196 * C2];
__device__ __align__(16) float  g_embf[NCLS * 49 * 256];
// packed weight fragments: [c][chunk16][tap25][ntile][ksub2][lane32]
__device__ __align__(16) uint2  g_W1[(size_t)NCLS * 16 * 25 * 32 * 2 * 32];
__device__ __align__(16) uint2  g_W2[(size_t)NCLS * 16 * 25 * 16 * 2 * 32];
__device__ int g_perm[BATCH];
__device__ int g_cnt[NCLS];
__device__ int g_off[NCLS];

__device__ __forceinline__ float lrelu(float x) { return x >= 0.f ? x : 0.3f * x; }

__device__ __forceinline__ ull splat2(float a) {
    ull d; unsigned ai = __float_as_uint(a);
    asm("mov.b64 %0, {%1, %1};" : "=l"(d) : "r"(ai));
    return d;
}
__device__ __forceinline__ void ffma2(ull& c, ull a, ull b) {
    asm("fma.rn.f32x2 %0, %1, %2, %3;" : "=l"(c) : "l"(a), "l"(b), "l"(c));
}
__device__ __forceinline__ float2 unpk(ull v) {
    unsigned lo, hi;
    asm("mov.b64 {%0, %1}, %2;" : "=r"(lo), "=r"(hi) : "l"(v));
    return make_float2(__uint_as_float(lo), __uint_as_float(hi));
}

#define CP_COMMIT() asm volatile("cp.async.commit_group;" ::: "memory")
#define CP_WAIT0()  asm volatile("cp.async.wait_group 0;" ::: "memory")

__device__ __forceinline__ void cp16(uint32_t saddr, const void* g) {
    asm volatile("cp.async.cg.shared.global [%0], [%1], 16;" :: "r"(saddr), "l"(g) : "memory");
}

#define LDSM4(a, addr) asm volatile( \
    "ldmatrix.sync.aligned.m8n8.x4.shared.b16 {%0,%1,%2,%3}, [%4];" \
    : "=r"(a[0]), "=r"(a[1]), "=r"(a[2]), "=r"(a[3]) : "r"(addr))

#define MMA(d, a, b) asm volatile( \
    "mma.sync.aligned.m16n8k16.row.col.f32.f16.f16.f32 " \
    "{%0,%1,%2,%3}, {%4,%5,%6,%7}, {%8,%9}, {%0,%1,%2,%3};" \
    : "+f"(d[0]), "+f"(d[1]), "+f"(d[2]), "+f"(d[3]) \
    : "r"(a[0]), "r"(a[1]), "r"(a[2]), "r"(a[3]), "r"(b.x), "r"(b.y))

// one tap slice = 8nt * 2ksub * 32 lanes = 512 uint2 = 4 KB
__device__ __forceinline__ void stage_w(uint32_t dsm, const uint2* src, int t) {
    for (int q = t; q < 256; q += 224) cp16(dsm + (uint32_t)q * 16u, (const char*)src + q * 16);
}

// =====================================================================
__global__ __launch_bounds__(512) void k_bucket(const int* __restrict__ labels)
{
    __shared__ int scnt[NCLS], scur[NCLS];
    int t = threadIdx.x;
    if (t < NCLS) scnt[t] = 0;
    __syncthreads();
    int c = labels[t];
    atomicAdd(&scnt[c], 1);
    __syncthreads();
    if (t == 0) {
        int run = 0;
        for (int k = 0; k < NCLS; k++) { g_off[k] = run; scur[k] = run; g_cnt[k] = scnt[k]; run += scnt[k]; }
    }
    __syncthreads();
    int pos = atomicAdd(&scur[c], 1);
    g_perm[pos] = t;
}

// =====================================================================
// dense + BN + LReLU -> act0 hi/lo fp16 (f32x2 over sample pairs)
// =====================================================================
__global__ __launch_bounds__(256) void k_dense(
    const float* __restrict__ noise, const int* __restrict__ labels,
    const float* __restrict__ emb,   const float* __restrict__ Wd,
    const float* __restrict__ bn_g,  const float* __restrict__ bn_b,
    const float* __restrict__ bn_m,  const float* __restrict__ bn_v)
{
    __shared__ __align__(8) float2 xs2[150 * 4];
    const int t  = threadIdx.x;
    const int bx = blockIdx.x;
    const int b0 = blockIdx.y * 8;

    for (int idx = t; idx < 8 * 150; idx += 256) {
        int s = idx / 150, k = idx - s * 150;
        int bb = b0 + s;
        float val = (k < NOISE) ? noise[bb * NOISE + k]
                                : emb[labels[bb] * EMBD + (k - NOISE)];
        ((float*)&xs2[k * 4 + (s >> 1)])[s & 1] = val;
    }
    __syncthreads();

    const int j = bx * 256 + t;
    ull acc2[4];
#pragma unroll
    for (int pr = 0; pr < 4; pr++) acc2[pr] = 0ull;
    for (int k = 0; k < 150; k++) {
        ull ws = splat2(Wd[k * 12544 + j]);
#pragma unroll
        for (int pr = 0; pr < 4; pr++) {
            ull a = *(const ull*)&xs2[k * 4 + pr];
            ffma2(acc2[pr], a, ws);
        }
    }
    const float sc = rsqrtf(bn_v[j] + 1e-3f) * bn_g[j];
    const float mm = bn_m[j];
    const float bb = bn_b[j];
#pragma unroll
    for (int pr = 0; pr < 4; pr++) {
        float2 v = unpk(acc2[pr]);
#pragma unroll
        for (int h2 = 0; h2 < 2; h2++) {
            float y = lrelu(((h2 ? v.y : v.x) - mm) * sc + bb);
            __half h = __float2half(y);
            __half l = __float2half(y - __half2float(h));
            size_t o = (size_t)(b0 + pr * 2 + h2) * (49 * 256) + j;
            g_a0h[o] = h; g_a0l[o] = l;
        }
    }
}

// =====================================================================
// coalesced weight packing (hi + lo fragments)
// =====================================================================
#define TP1 257
__global__ __launch_bounds__(256) void k_packw1(const float* __restrict__ K1)
{
    __shared__ float tile[16 * TP1];
    int tap = blockIdx.x, chunk = blockIdx.y, c = blockIdx.z;
    int t = threadIdx.x;
    const float* src = K1 + (((size_t)c * 25 + tap) * 306 + chunk * 16) * 256;
    for (int idx = t; idx < 4096; idx += 256) {
        int r = idx >> 8, col = idx & 255;
        tile[r * TP1 + col] = src[idx];
    }
    __syncthreads();
    int lane = t & 31, wp = t >> 5;
    int k0 = (lane & 3) * 2, nq = lane >> 2;
    for (int nt = wp; nt < 32; nt += 8) {
        int n = nt * 8 + nq;
        float w0 = tile[(k0 + 0) * TP1 + n], w1 = tile[(k0 + 1) * TP1 + n];
        float w8 = tile[(k0 + 8) * TP1 + n], w9 = tile[(k0 + 9) * TP1 + n];
        __half h0 = __float2half(w0), h1 = __float2half(w1);
        __half h8 = __float2half(w8), h9 = __float2half(w9);
        __half2 p0 = __halves2half2(h0, h1), p1 = __halves2half2(h8, h9);
        uint2 hi; hi.x = *(uint32_t*)&p0; hi.y = *(uint32_t*)&p1;
        __half2 q0 = __halves2half2(__float2half(w0 - __half2float(h0)), __float2half(w1 - __half2float(h1)));
        __half2 q1 = __halves2half2(__float2half(w8 - __half2float(h8)), __float2half(w9 - __half2float(h9)));
        uint2 lo; lo.x = *(uint32_t*)&q0; lo.y = *(uint32_t*)&q1;
        size_t base = ((((size_t)c * 16 + chunk) * 25 + tap) * 32 + nt) * 64 + lane;
        g_W1[base] = hi; g_W1[base + 32] = lo;
    }
}

#define TP2 129
__global__ __launch_bounds__(256) void k_packw2(const float* __restrict__ K2)
{
    __shared__ float tile[16 * TP2];
    int tap = blockIdx.x, chunk = blockIdx.y, c = blockIdx.z;
    int t = threadIdx.x;
    const float* src = K2 + (((size_t)c * 25 + tap) * 256 + chunk * 16) * 128;
    for (int idx = t; idx < 2048; idx += 256) {
        int r = idx >> 7, col = idx & 127;
        tile[r * TP2 + col] = src[idx];
    }
    __syncthreads();
    int lane = t & 31, wp = t >> 5;
    int k0 = (lane & 3) * 2, nq = lane >> 2;
    for (int nt = wp; nt < 16; nt += 8) {
        int n = nt * 8 + nq;
        float w0 = tile[(k0 + 0) * TP2 + n], w1 = tile[(k0 + 1) * TP2 + n];
        float w8 = tile[(k0 + 8) * TP2 + n], w9 = tile[(k0 + 9) * TP2 + n];
        __half h0 = __float2half(w0), h1 = __float2half(w1);
        __half h8 = __float2half(w8), h9 = __float2half(w9);
        __half2 p0 = __halves2half2(h0, h1), p1 = __halves2half2(h8, h9);
        uint2 hi; hi.x = *(uint32_t*)&p0; hi.y = *(uint32_t*)&p1;
        __half2 q0 = __halves2half2(__float2half(w0 - __half2float(h0)), __float2half(w1 - __half2float(h1)));
        __half2 q1 = __halves2half2(__float2half(w8 - __half2float(h8)), __float2half(w9 - __half2float(h9)));
        uint2 lo; lo.x = *(uint32_t*)&q0; lo.y = *(uint32_t*)&q1;
        size_t base = ((((size_t)c * 16 + chunk) * 25 + tap) * 16 + nt) * 64 + lane;
        g_W2[base] = hi; g_W2[base + 32] = lo;
    }
}

// =====================================================================
// fused emb fold: per-class conv1 bias field (one block per class)
// =====================================================================
__global__ __launch_bounds__(256) void k_emb(
    const float* __restrict__ K1, const float* __restrict__ emb)
{
    __shared__ float es[EMBD];
    __shared__ float tw[25][256];
    int c = blockIdx.x, t = threadIdx.x;
    if (t < EMBD) es[t] = emb[c * EMBD + t];
    __syncthreads();
    for (int tap = 0; tap < 25; tap++) {
        const float* kb = K1 + (((size_t)c * 25 + tap) * 306 + 256) * 256 + t;
        float acc = 0.f;
#pragma unroll 10
        for (int e = 0; e < EMBD; e++) acc += es[e] * kb[(size_t)e * 256];
        tw[tap][t] = acc;
    }
    __syncthreads();
    for (int p = 0; p < 49; p++) {
        int i = p / 7, j = p - 7 * i;
        float acc = 0.f;
        for (int di = 0; di < 5; di++) {
            int ii = i + di - 2; if ((unsigned)ii >= 7u) continue;
            for (int dj = 0; dj < 5; dj++) {
                int jj = j + dj - 2; if ((unsigned)jj >= 7u) continue;
                acc += tw[di * 5 + dj][t];
            }
        }
        g_embf[((size_t)c * 49 + p) * 256 + t] = acc;
    }
}

// =====================================================================
// conv1: implicit GEMM, 4 samples/CTA, 64 co, 7 warps, burst-staged weights
// A grid: [4 samples][11x11 padded][hi16|lo16], row = 40 fp16
// burst = 5 taps (one kernel row), 80 bursts total
// =====================================================================
#define SPL1   (121 * 40 + 8)
#define A1_FP  19488
#define A1_B   (A1_FP * 2)             // 38976 bytes
#define WB1    2560                     // uint2 per burst buffer (5 taps x 512)

__global__ __launch_bounds__(224, 2) void k_conv1(
    const float* __restrict__ G1, const float* __restrict__ B1,
    const float* __restrict__ M1, const float* __restrict__ V1)
{
    extern __shared__ __align__(16) char smraw[];
    __half* A = (__half*)smraw;
    uint2*  W = (uint2*)(smraw + A1_B);

    const int c = blockIdx.z;
    const int n_c = g_cnt[c];
    const int stile = blockIdx.x;
    if (stile * 4 >= n_c) return;
    const int by = blockIdx.y;
    const int co0 = by * 64;
    const int t = threadIdx.x, lane = t & 31, wrp = t >> 5;
    const int base = g_off[c];

    int samp[4]; bool sok[4];
#pragma unroll
    for (int s = 0; s < 4; s++) {
        int idx = stile * 4 + s;
        sok[s] = idx < n_c;
        samp[s] = g_perm[base + (idx < n_c ? idx : n_c - 1)];
    }

    const uint32_t a_u32 = (uint32_t)__cvta_generic_to_shared(A);
    const uint32_t w_u32 = (uint32_t)__cvta_generic_to_shared(W);

    const int lm = lane & 15;
    const int ljx = lm >> 2, ls = lm & 3;
    const int koff = (lane >> 4) * 8;
    const uint32_t lb0 = a_u32 + (uint32_t)((ls * SPL1 + ljx * 40 + koff) * 2);
    const uint32_t lb1 = a_u32 + (uint32_t)((ls * SPL1 + (ljx + 4) * 40 + koff) * 2);

    for (int q = t; q < A1_FP / 8; q += 224) ((uint4*)A)[q] = make_uint4(0, 0, 0, 0);
    __syncthreads();

    float acc[2][8][4];
#pragma unroll
    for (int mb = 0; mb < 2; mb++)
#pragma unroll
        for (int nt = 0; nt < 8; nt++)
#pragma unroll
            for (int u = 0; u < 4; u++) acc[mb][nt][u] = 0.f;

    const uint2* wbase = g_W1 + (((size_t)c * 16) * 25 * 32 + (size_t)by * 8) * 64;

    // refill chunk 0
    for (int q = t; q < 392; q += 224) {
        int which = q >= 196;
        int rem = which ? q - 196 : q;
        int s = rem / 49, p = rem - s * 49;
        const __half* src = (which ? g_a0l : g_a0h) + ((size_t)samp[s] * 49 + p) * 256;
        int pi_ = p / 7, pj_ = p - 7 * pi_;
        __half* dst = A + s * SPL1 + ((2 + pi_) * 11 + 2 + pj_) * 40 + which * 16;
        ((uint4*)dst)[0] = ((const uint4*)src)[0];
        ((uint4*)dst)[1] = ((const uint4*)src)[1];
    }
    // prefetch burst 0 (chunk 0, taps 0..4)
    for (int tp = 0; tp < 5; tp++)
        stage_w(w_u32 + (uint32_t)tp * 4096u, wbase + (size_t)tp * (32 * 64), t);
    CP_COMMIT();

    int bi = 0;
    for (int chunk = 0; chunk < 16; chunk++) {
        for (int di = 0; di < 5; di++) {
            CP_WAIT0();
            __syncthreads();
            if (di == 0 && chunk > 0) {
                const int ci0 = chunk * 16;
                for (int q = t; q < 392; q += 224) {
                    int which = q >= 196;
                    int rem = which ? q - 196 : q;
                    int s = rem / 49, p = rem - s * 49;
                    const __half* src = (which ? g_a0l : g_a0h) + ((size_t)samp[s] * 49 + p) * 256 + ci0;
                    int pi_ = p / 7, pj_ = p - 7 * pi_;
                    __half* dst = A + s * SPL1 + ((2 + pi_) * 11 + 2 + pj_) * 40 + which * 16;
                    ((uint4*)dst)[0] = ((const uint4*)src)[0];
                    ((uint4*)dst)[1] = ((const uint4*)src)[1];
                }
                __syncthreads();
            }
            if (bi + 1 < 80) {
                int nb = bi + 1, nch = nb / 5, ndi = nb - nch * 5;
                uint32_t dst = w_u32 + (uint32_t)(nb & 1) * (WB1 * 8);
                for (int tp = 0; tp < 5; tp++)
                    stage_w(dst + (uint32_t)tp * 4096u,
                            wbase + ((size_t)nch * 25 + ndi * 5 + tp) * (32 * 64), t);
            }
            CP_COMMIT();

            const uint2* wburst = W + (bi & 1) * WB1;
#pragma unroll
            for (int dj = 0; dj < 5; dj++) {
                const uint32_t goff = (uint32_t)(((wrp + di) * 11 + dj) * 80);
                const uint2* wb = wburst + dj * 512 + lane;
#pragma unroll
                for (int ksub = 0; ksub < 3; ksub++) {
                    uint32_t asel = (ksub == 2) ? 32u : 0u;
                    const uint2* wk = wb + ((ksub == 1) ? 32 : 0);
                    uint32_t a0[4], a1[4];
                    LDSM4(a0, lb0 + goff + asel);
                    LDSM4(a1, lb1 + goff + asel);
#pragma unroll
                    for (int nt = 0; nt < 8; nt++) {
                        uint2 b = wk[nt * 64];
                        MMA(acc[0][nt], a0, b);
                        MMA(acc[1][nt], a1, b);
                    }
                }
            }
            bi++;
        }
    }

    // epilogue: + E, BN, LReLU -> act1 hi/lo
    const int g_ = lane >> 2;
    const int n_ = (lane & 3) * 2;
#pragma unroll
    for (int mb = 0; mb < 2; mb++) {
#pragma unroll
        for (int nt = 0; nt < 8; nt++) {
            int co = co0 + nt * 8 + n_;
            float2 gg = *(const float2*)(G1 + c * 256 + co);
            float2 bb = *(const float2*)(B1 + c * 256 + co);
            float2 mm = *(const float2*)(M1 + c * 256 + co);
            float2 vv = *(const float2*)(V1 + c * 256 + co);
            float sx = rsqrtf(vv.x + 1e-3f) * gg.x;
            float sy = rsqrtf(vv.y + 1e-3f) * gg.y;
#pragma unroll
            for (int h = 0; h < 2; h++) {
                int m = mb * 16 + g_ + h * 8;
                int jx = m >> 2, s = m & 3;
                if (jx < 7 && sok[s]) {
                    int pos = wrp * 7 + jx;
                    float2 E = *(const float2*)(g_embf + ((size_t)c * 49 + pos) * 256 + co);
                    float y0 = lrelu((acc[mb][nt][h * 2 + 0] + E.x - mm.x) * sx + bb.x);
                    float y1 = lrelu((acc[mb][nt][h * 2 + 1] + E.y - mm.y) * sy + bb.y);
                    __half h0 = __float2half(y0), h1 = __float2half(y1);
                    __half l0 = __float2half(y0 - __half2float(h0));
                    __half l1 = __float2half(y1 - __half2float(h1));
                    size_t o = ((size_t)samp[s] * 49 + pos) * 256 + co;
                    *(__half2*)(g_a1h + o) = __halves2half2(h0, h1);
                    *(__half2*)(g_a1l + o) = __halves2half2(l0, l1);
                }
            }
        }
    }
}

// =====================================================================
// conv2: parity-decomposed implicit GEMM, 4 samples/CTA, 64 co,
// burst = all taps of one parity for one ci chunk (4..9 taps)
// =====================================================================
#define SPL2   (81 * 40 + 8)
#define A2_FP  13072
#define A2_B   (A2_FP * 2)             // 26144 bytes
#define WB2    4608                     // uint2 per burst buffer (9 taps x 512 max)

__global__ __launch_bounds__(224, 2) void k_conv2(
    const float* __restrict__ G2, const float* __restrict__ B2,
    const float* __restrict__ M2, const float* __restrict__ V2)
{
    extern __shared__ __align__(16) char smraw[];
    __half* A = (__half*)smraw;
    uint2*  W = (uint2*)(smraw + A2_B);

    const int c = blockIdx.z;
    const int n_c = g_cnt[c];
    const int stile = blockIdx.x;
    if (stile * 4 >= n_c) return;
    const int by = blockIdx.y;
    const int co0 = by * 64;
    const int t = threadIdx.x, lane = t & 31, wrp = t >> 5;
    const int base = g_off[c];

    int samp[4]; bool sok[4];
#pragma unroll
    for (int s = 0; s < 4; s++) {
        int idx = stile * 4 + s;
        sok[s] = idx < n_c;
        samp[s] = g_perm[base + (idx < n_c ? idx : n_c - 1)];
    }

    const uint32_t a_u32 = (uint32_t)__cvta_generic_to_shared(A);
    const uint32_t w_u32 = (uint32_t)__cvta_generic_to_shared(W);
    const int lm = lane & 15;
    const int ljx = lm >> 2, ls = lm & 3;
    const int koff = (lane >> 4) * 8;
    const uint32_t lb0 = a_u32 + (uint32_t)((ls * SPL2 + ljx * 40 + koff) * 2);
    const uint32_t lb1 = a_u32 + (uint32_t)((ls * SPL2 + (ljx + 4) * 40 + koff) * 2);

    for (int q = t; q < A2_FP / 8; q += 224) ((uint4*)A)[q] = make_uint4(0, 0, 0, 0);
    __syncthreads();

    const uint2* wcls = g_W2 + ((size_t)c * 16 * 25 * 16 + (size_t)by * 8) * 64;
    const int g_ = lane >> 2;
    const int n_ = (lane & 3) * 2;

    for (int pp = 0; pp < 4; pp++) {
        const int pi = pp >> 1, pj = pp & 1;
        const int ni = (pi == 0) ? 2 : 3, nj = (pj == 0) ? 2 : 3;

        float acc[2][8][4];
#pragma unroll
        for (int mb = 0; mb < 2; mb++)
#pragma unroll
            for (int nt = 0; nt < 8; nt++)
#pragma unroll
                for (int u = 0; u < 4; u++) acc[mb][nt][u] = 0.f;

        // prefetch chunk 0 taps of this parity into buffer 0
        {
            int tc = 0;
            for (int ui = 0; ui < ni; ui++) {
                int ddi = (pi == 0) ? (1 + 2 * ui) : (2 * ui);
                for (int uj = 0; uj < nj; uj++) {
                    int ddj = (pj == 0) ? (1 + 2 * uj) : (2 * uj);
                    stage_w(w_u32 + (uint32_t)tc * 4096u,
                            wcls + (size_t)(ddi * 5 + ddj) * (16 * 64), t);
                    tc++;
                }
            }
        }
        CP_COMMIT();

        for (int chunk = 0; chunk < 16; chunk++) {
            CP_WAIT0();
            __syncthreads();
            {
                const int ci0 = chunk * 16;
                for (int q = t; q < 392; q += 224) {
                    int which = q >= 196;
                    int rem = which ? q - 196 : q;
                    int s = rem / 49, p = rem - s * 49;
                    const __half* src = (which ? g_a1l : g_a1h) + ((size_t)samp[s] * 49 + p) * 256 + ci0;
                    int pi_ = p / 7, pj_ = p - 7 * pi_;
                    __half* dst = A + s * SPL2 + ((1 + pi_) * 9 + 1 + pj_) * 40 + which * 16;
                    ((uint4*)dst)[0] = ((const uint4*)src)[0];
                    ((uint4*)dst)[1] = ((const uint4*)src)[1];
                }
            }
            __syncthreads();
            if (chunk < 15) {
                uint32_t dst = w_u32 + (uint32_t)((chunk + 1) & 1) * (WB2 * 8);
                const uint2* wch = wcls + (size_t)(chunk + 1) * 25 * (16 * 64);
                int tc = 0;
                for (int ui = 0; ui < ni; ui++) {
                    int ddi = (pi == 0) ? (1 + 2 * ui) : (2 * ui);
                    for (int uj = 0; uj < nj; uj++) {
                        int ddj = (pj == 0) ? (1 + 2 * uj) : (2 * uj);
                        stage_w(dst + (uint32_t)tc * 4096u,
                                wch + (size_t)(ddi * 5 + ddj) * (16 * 64), t);
                        tc++;
                    }
                }
            }
            CP_COMMIT();

            const uint2* wburst = W + (chunk & 1) * WB2;
            int tc = 0;
            for (int ui = 0; ui < ni; ui++) {
                int ddi = (pi == 0) ? (1 + 2 * ui) : (2 * ui);
                int si = (ddi >> 1) - 1;
                for (int uj = 0; uj < nj; uj++) {
                    int ddj = (pj == 0) ? (1 + 2 * uj) : (2 * uj);
                    int sj = (ddj >> 1) - 1;
                    const uint32_t goff = (uint32_t)(((1 + wrp + si) * 9 + 1 + sj) * 80);
                    const uint2* wb = wburst + tc * 512 + lane;
#pragma unroll
                    for (int ksub = 0; ksub < 3; ksub++) {
                        uint32_t asel = (ksub == 2) ? 32u : 0u;
                        const uint2* wk = wb + ((ksub == 1) ? 32 : 0);
                        uint32_t a0[4], a1[4];
                        LDSM4(a0, lb0 + goff + asel);
                        LDSM4(a1, lb1 + goff + asel);
#pragma unroll
                        for (int nt = 0; nt < 8; nt++) {
                            uint2 b = wk[nt * 64];
                            MMA(acc[0][nt], a0, b);
                            MMA(acc[1][nt], a1, b);
                        }
                    }
                    tc++;
                }
            }
        }

        // epilogue this parity -> act2 fp32
#pragma unroll
        for (int mb = 0; mb < 2; mb++) {
#pragma unroll
            for (int nt = 0; nt < 8; nt++) {
                int co = co0 + nt * 8 + n_;
                float2 gg = *(const float2*)(G2 + c * 128 + co);
                float2 bb = *(const float2*)(B2 + c * 128 + co);
                float2 mm = *(const float2*)(M2 + c * 128 + co);
                float2 vv = *(const float2*)(V2 + c * 128 + co);
                float sx = rsqrtf(vv.x + 1e-3f) * gg.x;
                float sy = rsqrtf(vv.y + 1e-3f) * gg.y;
#pragma unroll
                for (int h = 0; h < 2; h++) {
                    int m = mb * 16 + g_ + h * 8;
                    int jx = m >> 2, s = m & 3;
                    if (jx < 7 && sok[s]) {
                        int oi = 2 * wrp + pi, oj = 2 * jx + pj;
                        float2 y;
                        y.x = lrelu((acc[mb][nt][h * 2 + 0] - mm.x) * sx + bb.x);
                        y.y = lrelu((acc[mb][nt][h * 2 + 1] - mm.y) * sy + bb.y);
                        *(float2*)(g_act2 + ((size_t)samp[s] * 196 + oi * 14 + oj) * 128 + co) = y;
                    }
                }
            }
        }
    }
}

// =====================================================================
// conv3: 5x5 s2, 128 -> 1, tanh
// =====================================================================
#define D_IN_SH (196 * C2)
#define D_W_SH  (25 * C2)

__global__ __launch_bounds__(256) void k_conv3(
    const int* __restrict__ labels, const float* __restrict__ K3,
    float* __restrict__ out)
{
    extern __shared__ float sm[];
    float4* in4 = (float4*)sm;
    float4* w4s = (float4*)(sm + D_IN_SH);
    const int b = blockIdx.x;
    const int t = threadIdx.x;
    const int c = labels[b];

    const float4* a2 = (const float4*)(g_act2 + (size_t)b * (196 * C2));
    for (int q = t; q < 196 * 32; q += 256) in4[q] = a2[q];
    const float4* k4 = (const float4*)(K3 + (size_t)c * 25 * C2);
    for (int q = t; q < 25 * 32; q += 256) w4s[q] = k4[q];
    __syncthreads();

    for (int px = t; px < 784; px += 256) {
        const int oi = px / 28, oj = px - oi * 28;
        float acc = 0.f;
        for (int ddi = (oi & 1) ? 0 : 1; ddi < 5; ddi += 2) {
            int ii = (oi + ddi - 3) >> 1;
            if ((unsigned)ii >= 14u) continue;
            for (int ddj = (oj & 1) ? 0 : 1; ddj < 5; ddj += 2) {
                int jj = (oj + ddj - 3) >> 1;
                if ((unsigned)jj >= 14u) continue;
                const float4* ip = in4 + (ii * 14 + jj) * 32;
                const float4* wp = w4s + (ddi * 5 + ddj) * 32;
#pragma unroll 8
                for (int q = 0; q < 32; q++) {
                    float4 a = ip[q], w = wp[q];
                    acc += a.x * w.x + a.y * w.y + a.z * w.z + a.w * w.w;
                }
            }
        }
        out[(size_t)b * 784 + px] = tanhf(acc);
    }
}

// =====================================================================
extern "C" void kernel_launch(void* const* d_in, const int* in_sizes, int n_in,
                              void* d_out, int out_size)
{
    const float* noise = (const float*)d_in[0];
    const int*   labels= (const int*)  d_in[1];
    const float* emb   = (const float*)d_in[2];
    const float* Wd    = (const float*)d_in[3];
    const float* bn1g  = (const float*)d_in[4];
    const float* bn1b  = (const float*)d_in[5];
    const float* bn1m  = (const float*)d_in[6];
    const float* bn1v  = (const float*)d_in[7];
    const float* K1    = (const float*)d_in[8];
    const float* G1    = (const float*)d_in[9];
    const float* B1    = (const float*)d_in[10];
    const float* M1    = (const float*)d_in[11];
    const float* V1    = (const float*)d_in[12];
    const float* K2    = (const float*)d_in[13];
    const float* G2    = (const float*)d_in[14];
    const float* B2    = (const float*)d_in[15];
    const float* M2    = (const float*)d_in[16];
    const float* V2    = (const float*)d_in[17];
    const float* K3    = (const float*)d_in[18];
    float* out = (float*)d_out;

    const int smB = A1_B + 2 * WB1 * 8;   // 38976 + 40960 = 79936
    const int smC = A2_B + 2 * WB2 * 8;   // 26144 + 73728 = 99872
    const int smD = (D_IN_SH + D_W_SH) * 4;
    cudaFuncSetAttribute(k_conv1, cudaFuncAttributeMaxDynamicSharedMemorySize, smB);
    cudaFuncSetAttribute(k_conv2, cudaFuncAttributeMaxDynamicSharedMemorySize, smC);
    cudaFuncSetAttribute(k_conv3, cudaFuncAttributeMaxDynamicSharedMemorySize, smD);

    k_bucket<<<1, 512>>>(labels);
    k_dense<<<dim3(49, 64), 256>>>(noise, labels, emb, Wd, bn1g, bn1b, bn1m, bn1v);
    k_packw1<<<dim3(25, 16, 10), 256>>>(K1);
    k_packw2<<<dim3(25, 16, 10), 256>>>(K2);
    k_emb<<<10, 256>>>(K1, emb);
    k_conv1<<<dim3(32, 4, 10), 224, smB>>>(G1, B1, M1, V1);
    k_conv2<<<dim3(32, 2, 10), 224, smC>>>(G2, B2, M2, V2);
    k_conv3<<<BATCH, 256, smD>>>(labels, K3, out);
}

// round 11
// speedup vs baseline: 6.2778x; 1.2948x over previous
#include <cuda_runtime.h>
#include <cuda_fp16.h>
#include <cstdint>

#define BATCH 512
#define NOISE 100
#define EMBD  50
#define NCLS  10
#define C1    256
#define C2    128

typedef unsigned long long ull;

// ---------------- scratch ----------------
__device__ __align__(16) __half g_a0[BATCH * 49 * 256];
__device__ __align__(16) __half g_a1[BATCH * 49 * 256];
__device__ __align__(16) float  g_act2[BATCH * 196 * C2];
__device__ __align__(16) float  g_embf[NCLS * 49 * 256];
// packed weight fragments: [c][chunk16][tap25][ntile][ksub2][lane32]
__device__ __align__(16) uint2  g_W1[(size_t)NCLS * 16 * 25 * 32 * 2 * 32];
__device__ __align__(16) uint2  g_W2[(size_t)NCLS * 16 * 25 * 16 * 2 * 32];
__device__ int g_perm[BATCH];
__device__ int g_cnt[NCLS];
__device__ int g_off[NCLS];

__device__ __forceinline__ float lrelu(float x) { return x >= 0.f ? x : 0.3f * x; }

__device__ __forceinline__ ull splat2(float a) {
    ull d; unsigned ai = __float_as_uint(a);
    asm("mov.b64 %0, {%1, %1};" : "=l"(d) : "r"(ai));
    return d;
}
__device__ __forceinline__ void ffma2(ull& c, ull a, ull b) {
    asm("fma.rn.f32x2 %0, %1, %2, %3;" : "=l"(c) : "l"(a), "l"(b), "l"(c));
}
__device__ __forceinline__ float2 unpk(ull v) {
    unsigned lo, hi;
    asm("mov.b64 {%0, %1}, %2;" : "=r"(lo), "=r"(hi) : "l"(v));
    return make_float2(__uint_as_float(lo), __uint_as_float(hi));
}

#define CP_COMMIT() asm volatile("cp.async.commit_group;" ::: "memory")
#define CP_WAIT0()  asm volatile("cp.async.wait_group 0;" ::: "memory")

__device__ __forceinline__ void cp16(uint32_t saddr, const void* g) {
    asm volatile("cp.async.cg.shared.global [%0], [%1], 16;" :: "r"(saddr), "l"(g) : "memory");
}

#define LDSM4(a, addr) asm volatile( \
    "ldmatrix.sync.aligned.m8n8.x4.shared.b16 {%0,%1,%2,%3}, [%4];" \
    : "=r"(a[0]), "=r"(a[1]), "=r"(a[2]), "=r"(a[3]) : "r"(addr))

#define MMA(d, a, b) asm volatile( \
    "mma.sync.aligned.m16n8k16.row.col.f32.f16.f16.f32 " \
    "{%0,%1,%2,%3}, {%4,%5,%6,%7}, {%8,%9}, {%0,%1,%2,%3};" \
    : "+f"(d[0]), "+f"(d[1]), "+f"(d[2]), "+f"(d[3]) \
    : "r"(a[0]), "r"(a[1]), "r"(a[2]), "r"(a[3]), "r"(b.x), "r"(b.y))

// one tap slice = 8nt * 2ksub * 32 lanes = 512 uint2 = 4 KB
__device__ __forceinline__ void stage_w(uint32_t dsm, const uint2* src, int t) {
    for (int q = t; q < 256; q += 224) cp16(dsm + (uint32_t)q * 16u, (const char*)src + q * 16);
}

// =====================================================================
__global__ __launch_bounds__(512) void k_bucket(const int* __restrict__ labels)
{
    __shared__ int scnt[NCLS], scur[NCLS];
    int t = threadIdx.x;
    if (t < NCLS) scnt[t] = 0;
    __syncthreads();
    int c = labels[t];
    atomicAdd(&scnt[c], 1);
    __syncthreads();
    if (t == 0) {
        int run = 0;
        for (int k = 0; k < NCLS; k++) { g_off[k] = run; scur[k] = run; g_cnt[k] = scnt[k]; run += scnt[k]; }
    }
    __syncthreads();
    int pos = atomicAdd(&scur[c], 1);
    g_perm[pos] = t;
}

// =====================================================================
// dense + BN + LReLU -> act0 fp16
// =====================================================================
__global__ __launch_bounds__(256) void k_dense(
    const float* __restrict__ noise, const int* __restrict__ labels,
    const float* __restrict__ emb,   const float* __restrict__ Wd,
    const float* __restrict__ bn_g,  const float* __restrict__ bn_b,
    const float* __restrict__ bn_m,  const float* __restrict__ bn_v)
{
    __shared__ __align__(8) float2 xs2[150 * 4];
    const int t  = threadIdx.x;
    const int bx = blockIdx.x;
    const int b0 = blockIdx.y * 8;

    for (int idx = t; idx < 8 * 150; idx += 256) {
        int s = idx / 150, k = idx - s * 150;
        int bb = b0 + s;
        float val = (k < NOISE) ? noise[bb * NOISE + k]
                                : emb[labels[bb] * EMBD + (k - NOISE)];
        ((float*)&xs2[k * 4 + (s >> 1)])[s & 1] = val;
    }
    __syncthreads();

    const int j = bx * 256 + t;
    ull acc2[4];
#pragma unroll
    for (int pr = 0; pr < 4; pr++) acc2[pr] = 0ull;
    for (int k = 0; k < 150; k++) {
        ull ws = splat2(Wd[k * 12544 + j]);
#pragma unroll
        for (int pr = 0; pr < 4; pr++) {
            ull a = *(const ull*)&xs2[k * 4 + pr];
            ffma2(acc2[pr], a, ws);
        }
    }
    const float sc = rsqrtf(bn_v[j] + 1e-3f) * bn_g[j];
    const float mm = bn_m[j];
    const float bb = bn_b[j];
#pragma unroll
    for (int pr = 0; pr < 4; pr++) {
        float2 v = unpk(acc2[pr]);
#pragma unroll
        for (int h2 = 0; h2 < 2; h2++) {
            float y = lrelu(((h2 ? v.y : v.x) - mm) * sc + bb);
            g_a0[(size_t)(b0 + pr * 2 + h2) * (49 * 256) + j] = __float2half(y);
        }
    }
}

// =====================================================================
// coalesced weight packing (hi + lo fragments, W exact 2-term split)
// =====================================================================
#define TP1 257
__global__ __launch_bounds__(256) void k_packw1(const float* __restrict__ K1)
{
    __shared__ float tile[16 * TP1];
    int tap = blockIdx.x, chunk = blockIdx.y, c = blockIdx.z;
    int t = threadIdx.x;
    const float* src = K1 + (((size_t)c * 25 + tap) * 306 + chunk * 16) * 256;
    for (int idx = t; idx < 4096; idx += 256) {
        int r = idx >> 8, col = idx & 255;
        tile[r * TP1 + col] = src[idx];
    }
    __syncthreads();
    int lane = t & 31, wp = t >> 5;
    int k0 = (lane & 3) * 2, nq = lane >> 2;
    for (int nt = wp; nt < 32; nt += 8) {
        int n = nt * 8 + nq;
        float w0 = tile[(k0 + 0) * TP1 + n], w1 = tile[(k0 + 1) * TP1 + n];
        float w8 = tile[(k0 + 8) * TP1 + n], w9 = tile[(k0 + 9) * TP1 + n];
        __half h0 = __float2half(w0), h1 = __float2half(w1);
        __half h8 = __float2half(w8), h9 = __float2half(w9);
        __half2 p0 = __halves2half2(h0, h1), p1 = __halves2half2(h8, h9);
        uint2 hi; hi.x = *(uint32_t*)&p0; hi.y = *(uint32_t*)&p1;
        __half2 q0 = __halves2half2(__float2half(w0 - __half2float(h0)), __float2half(w1 - __half2float(h1)));
        __half2 q1 = __halves2half2(__float2half(w8 - __half2float(h8)), __float2half(w9 - __half2float(h9)));
        uint2 lo; lo.x = *(uint32_t*)&q0; lo.y = *(uint32_t*)&q1;
        size_t base = ((((size_t)c * 16 + chunk) * 25 + tap) * 32 + nt) * 64 + lane;
        g_W1[base] = hi; g_W1[base + 32] = lo;
    }
}

#define TP2 129
__global__ __launch_bounds__(256) void k_packw2(const float* __restrict__ K2)
{
    __shared__ float tile[16 * TP2];
    int tap = blockIdx.x, chunk = blockIdx.y, c = blockIdx.z;
    int t = threadIdx.x;
    const float* src = K2 + (((size_t)c * 25 + tap) * 256 + chunk * 16) * 128;
    for (int idx = t; idx < 2048; idx += 256) {
        int r = idx >> 7, col = idx & 127;
        tile[r * TP2 + col] = src[idx];
    }
    __syncthreads();
    int lane = t & 31, wp = t >> 5;
    int k0 = (lane & 3) * 2, nq = lane >> 2;
    for (int nt = wp; nt < 16; nt += 8) {
        int n = nt * 8 + nq;
        float w0 = tile[(k0 + 0) * TP2 + n], w1 = tile[(k0 + 1) * TP2 + n];
        float w8 = tile[(k0 + 8) * TP2 + n], w9 = tile[(k0 + 9) * TP2 + n];
        __half h0 = __float2half(w0), h1 = __float2half(w1);
        __half h8 = __float2half(w8), h9 = __float2half(w9);
        __half2 p0 = __halves2half2(h0, h1), p1 = __halves2half2(h8, h9);
        uint2 hi; hi.x = *(uint32_t*)&p0; hi.y = *(uint32_t*)&p1;
        __half2 q0 = __halves2half2(__float2half(w0 - __half2float(h0)), __float2half(w1 - __half2float(h1)));
        __half2 q1 = __halves2half2(__float2half(w8 - __half2float(h8)), __float2half(w9 - __half2float(h9)));
        uint2 lo; lo.x = *(uint32_t*)&q0; lo.y = *(uint32_t*)&q1;
        size_t base = ((((size_t)c * 16 + chunk) * 25 + tap) * 16 + nt) * 64 + lane;
        g_W2[base] = hi; g_W2[base + 32] = lo;
    }
}

// =====================================================================
// fused emb fold: per-class conv1 bias field
// =====================================================================
__global__ __launch_bounds__(256) void k_emb(
    const float* __restrict__ K1, const float* __restrict__ emb)
{
    __shared__ float es[EMBD];
    __shared__ float tw[25][256];
    int c = blockIdx.x, t = threadIdx.x;
    if (t < EMBD) es[t] = emb[c * EMBD + t];
    __syncthreads();
    for (int tap = 0; tap < 25; tap++) {
        const float* kb = K1 + (((size_t)c * 25 + tap) * 306 + 256) * 256 + t;
        float acc = 0.f;
#pragma unroll 10
        for (int e = 0; e < EMBD; e++) acc += es[e] * kb[(size_t)e * 256];
        tw[tap][t] = acc;
    }
    __syncthreads();
    for (int p = 0; p < 49; p++) {
        int i = p / 7, j = p - 7 * i;
        float acc = 0.f;
        for (int di = 0; di < 5; di++) {
            int ii = i + di - 2; if ((unsigned)ii >= 7u) continue;
            for (int dj = 0; dj < 5; dj++) {
                int jj = j + dj - 2; if ((unsigned)jj >= 7u) continue;
                acc += tw[di * 5 + dj][t];
            }
        }
        g_embf[((size_t)c * 49 + p) * 256 + t] = acc;
    }
}

// =====================================================================
// conv1: implicit GEMM, 4 samples/CTA, 64 co, 7 warps, burst-staged weights
// A grid: [4 samples][11x11 padded] rows of 16 fp16 (k chunk), row pitch 24
// halves (48B = 3 x 16B units), plane 2960 halves (5920B = 370 units, ≡2 mod 8)
// -> conflict-free ldmatrix phases. burst = 5 taps, 80 bursts total.
// =====================================================================
#define SPL1   2960
#define A1_FP  (4 * SPL1)              // 11840 halves
#define A1_B   (A1_FP * 2)             // 23680 bytes
#define WB1    2560                     // uint2 per burst buffer (5 taps x 512)

__global__ __launch_bounds__(224, 2) void k_conv1(
    const float* __restrict__ G1, const float* __restrict__ B1,
    const float* __restrict__ M1, const float* __restrict__ V1)
{
    extern __shared__ __align__(16) char smraw[];
    __half* A = (__half*)smraw;
    uint2*  W = (uint2*)(smraw + A1_B);

    const int c = blockIdx.z;
    const int n_c = g_cnt[c];
    const int stile = blockIdx.x;
    if (stile * 4 >= n_c) return;
    const int by = blockIdx.y;
    const int co0 = by * 64;
    const int t = threadIdx.x, lane = t & 31, wrp = t >> 5;
    const int base = g_off[c];

    int samp[4]; bool sok[4];
#pragma unroll
    for (int s = 0; s < 4; s++) {
        int idx = stile * 4 + s;
        sok[s] = idx < n_c;
        samp[s] = g_perm[base + (idx < n_c ? idx : n_c - 1)];
    }

    const uint32_t a_u32 = (uint32_t)__cvta_generic_to_shared(A);
    const uint32_t w_u32 = (uint32_t)__cvta_generic_to_shared(W);

    const int lm = lane & 15;
    const int ljx = lm >> 2, ls = lm & 3;
    const int koff = (lane >> 4) * 8;
    const uint32_t lb0 = a_u32 + (uint32_t)((ls * SPL1 + ljx * 24 + koff) * 2);
    const uint32_t lb1 = a_u32 + (uint32_t)((ls * SPL1 + (ljx + 4) * 24 + koff) * 2);

    for (int q = t; q < A1_FP / 8; q += 224) ((uint4*)A)[q] = make_uint4(0, 0, 0, 0);
    __syncthreads();

    float acc[2][8][4];
#pragma unroll
    for (int mb = 0; mb < 2; mb++)
#pragma unroll
        for (int nt = 0; nt < 8; nt++)
#pragma unroll
            for (int u = 0; u < 4; u++) acc[mb][nt][u] = 0.f;

    const uint2* wbase = g_W1 + (((size_t)c * 16) * 25 * 32 + (size_t)by * 8) * 64;

    // refill chunk 0
    for (int q = t; q < 196; q += 224) {
        int s = q / 49, p = q - s * 49;
        const __half* src = g_a0 + ((size_t)samp[s] * 49 + p) * 256;
        int pi_ = p / 7, pj_ = p - 7 * pi_;
        __half* dst = A + s * SPL1 + ((2 + pi_) * 11 + 2 + pj_) * 24;
        ((uint4*)dst)[0] = ((const uint4*)src)[0];
        ((uint4*)dst)[1] = ((const uint4*)src)[1];
    }
    // prefetch burst 0 (chunk 0, taps 0..4)
    for (int tp = 0; tp < 5; tp++)
        stage_w(w_u32 + (uint32_t)tp * 4096u, wbase + (size_t)tp * (32 * 64), t);
    CP_COMMIT();

    int bi = 0;
    for (int chunk = 0; chunk < 16; chunk++) {
        for (int di = 0; di < 5; di++) {
            CP_WAIT0();
            __syncthreads();
            // prefetch next burst first (overlaps A refill LDGs)
            if (bi + 1 < 80) {
                int nb = bi + 1, nch = nb / 5, ndi = nb - nch * 5;
                uint32_t dst = w_u32 + (uint32_t)(nb & 1) * (WB1 * 8);
                for (int tp = 0; tp < 5; tp++)
                    stage_w(dst + (uint32_t)tp * 4096u,
                            wbase + ((size_t)nch * 25 + ndi * 5 + tp) * (32 * 64), t);
            }
            CP_COMMIT();
            if (di == 0 && chunk > 0) {
                const int ci0 = chunk * 16;
                for (int q = t; q < 196; q += 224) {
                    int s = q / 49, p = q - s * 49;
                    const __half* src = g_a0 + ((size_t)samp[s] * 49 + p) * 256 + ci0;
                    int pi_ = p / 7, pj_ = p - 7 * pi_;
                    __half* dst = A + s * SPL1 + ((2 + pi_) * 11 + 2 + pj_) * 24;
                    ((uint4*)dst)[0] = ((const uint4*)src)[0];
                    ((uint4*)dst)[1] = ((const uint4*)src)[1];
                }
                __syncthreads();
            }

            const uint2* wburst = W + (bi & 1) * WB1;
#pragma unroll
            for (int dj = 0; dj < 5; dj++) {
                const uint32_t goff = (uint32_t)(((wrp + di) * 11 + dj) * 48);
                uint32_t a0[4], a1[4];
                LDSM4(a0, lb0 + goff);
                LDSM4(a1, lb1 + goff);
                const uint2* wb = wburst + dj * 512 + lane;
#pragma unroll
                for (int ksub = 0; ksub < 2; ksub++) {
                    const uint2* wk = wb + ksub * 32;
#pragma unroll
                    for (int nt = 0; nt < 8; nt++) {
                        uint2 b = wk[nt * 64];
                        MMA(acc[0][nt], a0, b);
                        MMA(acc[1][nt], a1, b);
                    }
                }
            }
            bi++;
        }
    }

    // epilogue: + E, BN, LReLU -> act1 fp16
    const int g_ = lane >> 2;
    const int n_ = (lane & 3) * 2;
#pragma unroll
    for (int mb = 0; mb < 2; mb++) {
#pragma unroll
        for (int nt = 0; nt < 8; nt++) {
            int co = co0 + nt * 8 + n_;
            float2 gg = *(const float2*)(G1 + c * 256 + co);
            float2 bb = *(const float2*)(B1 + c * 256 + co);
            float2 mm = *(const float2*)(M1 + c * 256 + co);
            float2 vv = *(const float2*)(V1 + c * 256 + co);
            float sx = rsqrtf(vv.x + 1e-3f) * gg.x;
            float sy = rsqrtf(vv.y + 1e-3f) * gg.y;
#pragma unroll
            for (int h = 0; h < 2; h++) {
                int m = mb * 16 + g_ + h * 8;
                int jx = m >> 2, s = m & 3;
                if (jx < 7 && sok[s]) {
                    int pos = wrp * 7 + jx;
                    float2 E = *(const float2*)(g_embf + ((size_t)c * 49 + pos) * 256 + co);
                    float y0 = lrelu((acc[mb][nt][h * 2 + 0] + E.x - mm.x) * sx + bb.x);
                    float y1 = lrelu((acc[mb][nt][h * 2 + 1] + E.y - mm.y) * sy + bb.y);
                    *(__half2*)(g_a1 + ((size_t)samp[s] * 49 + pos) * 256 + co) =
                        __halves2half2(__float2half(y0), __float2half(y1));
                }
            }
        }
    }
}

// =====================================================================
// conv2: parity-decomposed implicit GEMM, 4 samples/CTA, 64 co
// A grid: [4][9x9 padded] rows of 16 fp16, pitch 24 halves, plane 2000 halves
// =====================================================================
#define SPL2   2000
#define A2_FP  (4 * SPL2)              // 8000 halves
#define A2_B   (A2_FP * 2)             // 16000 bytes
#define WB2    4608                     // uint2 per burst buffer (9 taps x 512 max)

__global__ __launch_bounds__(224, 2) void k_conv2(
    const float* __restrict__ G2, const float* __restrict__ B2,
    const float* __restrict__ M2, const float* __restrict__ V2)
{
    extern __shared__ __align__(16) char smraw[];
    __half* A = (__half*)smraw;
    uint2*  W = (uint2*)(smraw + A2_B);

    const int c = blockIdx.z;
    const int n_c = g_cnt[c];
    const int stile = blockIdx.x;
    if (stile * 4 >= n_c) return;
    const int by = blockIdx.y;
    const int co0 = by * 64;
    const int t = threadIdx.x, lane = t & 31, wrp = t >> 5;
    const int base = g_off[c];

    int samp[4]; bool sok[4];
#pragma unroll
    for (int s = 0; s < 4; s++) {
        int idx = stile * 4 + s;
        sok[s] = idx < n_c;
        samp[s] = g_perm[base + (idx < n_c ? idx : n_c - 1)];
    }

    const uint32_t a_u32 = (uint32_t)__cvta_generic_to_shared(A);
    const uint32_t w_u32 = (uint32_t)__cvta_generic_to_shared(W);
    const int lm = lane & 15;
    const int ljx = lm >> 2, ls = lm & 3;
    const int koff = (lane >> 4) * 8;
    const uint32_t lb0 = a_u32 + (uint32_t)((ls * SPL2 + ljx * 24 + koff) * 2);
    const uint32_t lb1 = a_u32 + (uint32_t)((ls * SPL2 + (ljx + 4) * 24 + koff) * 2);

    for (int q = t; q < A2_FP / 8; q += 224) ((uint4*)A)[q] = make_uint4(0, 0, 0, 0);
    __syncthreads();

    const uint2* wcls = g_W2 + ((size_t)c * 16 * 25 * 16 + (size_t)by * 8) * 64;
    const int g_ = lane >> 2;
    const int n_ = (lane & 3) * 2;

    for (int pp = 0; pp < 4; pp++) {
        const int pi = pp >> 1, pj = pp & 1;
        const int ni = (pi == 0) ? 2 : 3, nj = (pj == 0) ? 2 : 3;

        float acc[2][8][4];
#pragma unroll
        for (int mb = 0; mb < 2; mb++)
#pragma unroll
            for (int nt = 0; nt < 8; nt++)
#pragma unroll
                for (int u = 0; u < 4; u++) acc[mb][nt][u] = 0.f;

        // prefetch chunk 0 taps of this parity into buffer 0
        {
            int tc = 0;
            for (int ui = 0; ui < ni; ui++) {
                int ddi = (pi == 0) ? (1 + 2 * ui) : (2 * ui);
                for (int uj = 0; uj < nj; uj++) {
                    int ddj = (pj == 0) ? (1 + 2 * uj) : (2 * uj);
                    stage_w(w_u32 + (uint32_t)tc * 4096u,
                            wcls + (size_t)(ddi * 5 + ddj) * (16 * 64), t);
                    tc++;
                }
            }
        }
        CP_COMMIT();

        for (int chunk = 0; chunk < 16; chunk++) {
            CP_WAIT0();
            __syncthreads();
            if (chunk < 15) {
                uint32_t dst = w_u32 + (uint32_t)((chunk + 1) & 1) * (WB2 * 8);
                const uint2* wch = wcls + (size_t)(chunk + 1) * 25 * (16 * 64);
                int tc = 0;
                for (int ui = 0; ui < ni; ui++) {
                    int ddi = (pi == 0) ? (1 + 2 * ui) : (2 * ui);
                    for (int uj = 0; uj < nj; uj++) {
                        int ddj = (pj == 0) ? (1 + 2 * uj) : (2 * uj);
                        stage_w(dst + (uint32_t)tc * 4096u,
                                wch + (size_t)(ddi * 5 + ddj) * (16 * 64), t);
                        tc++;
                    }
                }
            }
            CP_COMMIT();
            {
                const int ci0 = chunk * 16;
                for (int q = t; q < 196; q += 224) {
                    int s = q / 49, p = q - s * 49;
                    const __half* src = g_a1 + ((size_t)samp[s] * 49 + p) * 256 + ci0;
                    int pi_ = p / 7, pj_ = p - 7 * pi_;
                    __half* dst = A + s * SPL2 + ((1 + pi_) * 9 + 1 + pj_) * 24;
                    ((uint4*)dst)[0] = ((const uint4*)src)[0];
                    ((uint4*)dst)[1] = ((const uint4*)src)[1];
                }
            }
            __syncthreads();

            const uint2* wburst = W + (chunk & 1) * WB2;
            int tc = 0;
            for (int ui = 0; ui < ni; ui++) {
                int ddi = (pi == 0) ? (1 + 2 * ui) : (2 * ui);
                int si = (ddi >> 1) - 1;
                for (int uj = 0; uj < nj; uj++) {
                    int ddj = (pj == 0) ? (1 + 2 * uj) : (2 * uj);
                    int sj = (ddj >> 1) - 1;
                    const uint32_t goff = (uint32_t)(((1 + wrp + si) * 9 + 1 + sj) * 48);
                    uint32_t a0[4], a1[4];
                    LDSM4(a0, lb0 + goff);
                    LDSM4(a1, lb1 + goff);
                    const uint2* wb = wburst + tc * 512 + lane;
#pragma unroll
                    for (int ksub = 0; ksub < 2; ksub++) {
                        const uint2* wk = wb + ksub * 32;
#pragma unroll
                        for (int nt = 0; nt < 8; nt++) {
                            uint2 b = wk[nt * 64];
                            MMA(acc[0][nt], a0, b);
                            MMA(acc[1][nt], a1, b);
                        }
                    }
                    tc++;
                }
            }
        }

        // epilogue this parity -> act2 fp32
#pragma unroll
        for (int mb = 0; mb < 2; mb++) {
#pragma unroll
            for (int nt = 0; nt < 8; nt++) {
                int co = co0 + nt * 8 + n_;
                float2 gg = *(const float2*)(G2 + c * 128 + co);
                float2 bb = *(const float2*)(B2 + c * 128 + co);
                float2 mm = *(const float2*)(M2 + c * 128 + co);
                float2 vv = *(const float2*)(V2 + c * 128 + co);
                float sx = rsqrtf(vv.x + 1e-3f) * gg.x;
                float sy = rsqrtf(vv.y + 1e-3f) * gg.y;
#pragma unroll
                for (int h = 0; h < 2; h++) {
                    int m = mb * 16 + g_ + h * 8;
                    int jx = m >> 2, s = m & 3;
                    if (jx < 7 && sok[s]) {
                        int oi = 2 * wrp + pi, oj = 2 * jx + pj;
                        float2 y;
                        y.x = lrelu((acc[mb][nt][h * 2 + 0] - mm.x) * sx + bb.x);
                        y.y = lrelu((acc[mb][nt][h * 2 + 1] - mm.y) * sy + bb.y);
                        *(float2*)(g_act2 + ((size_t)samp[s] * 196 + oi * 14 + oj) * 128 + co) = y;
                    }
                }
            }
        }
    }
}

// =====================================================================
// conv3: 5x5 s2, 128 -> 1, tanh
// =====================================================================
#define D_IN_SH (196 * C2)
#define D_W_SH  (25 * C2)

__global__ __launch_bounds__(256) void k_conv3(
    const int* __restrict__ labels, const float* __restrict__ K3,
    float* __restrict__ out)
{
    extern __shared__ float sm[];
    float4* in4 = (float4*)sm;
    float4* w4s = (float4*)(sm + D_IN_SH);
    const int b = blockIdx.x;
    const int t = threadIdx.x;
    const int c = labels[b];

    const float4* a2 = (const float4*)(g_act2 + (size_t)b * (196 * C2));
    for (int q = t; q < 196 * 32; q += 256) in4[q] = a2[q];
    const float4* k4 = (const float4*)(K3 + (size_t)c * 25 * C2);
    for (int q = t; q < 25 * 32; q += 256) w4s[q] = k4[q];
    __syncthreads();

    for (int px = t; px < 784; px += 256) {
        const int oi = px / 28, oj = px - oi * 28;
        float acc = 0.f;
        for (int ddi = (oi & 1) ? 0 : 1; ddi < 5; ddi += 2) {
            int ii = (oi + ddi - 3) >> 1;
            if ((unsigned)ii >= 14u) continue;
            for (int ddj = (oj & 1) ? 0 : 1; ddj < 5; ddj += 2) {
                int jj = (oj + ddj - 3) >> 1;
                if ((unsigned)jj >= 14u) continue;
                const float4* ip = in4 + (ii * 14 + jj) * 32;
                const float4* wp = w4s + (ddi * 5 + ddj) * 32;
#pragma unroll 8
                for (int q = 0; q < 32; q++) {
                    float4 a = ip[q], w = wp[q];
                    acc += a.x * w.x + a.y * w.y + a.z * w.z + a.w * w.w;
                }
            }
        }
        out[(size_t)b * 784 + px] = tanhf(acc);
    }
}

// =====================================================================
extern "C" void kernel_launch(void* const* d_in, const int* in_sizes, int n_in,
                              void* d_out, int out_size)
{
    const float* noise = (const float*)d_in[0];
    const int*   labels= (const int*)  d_in[1];
    const float* emb   = (const float*)d_in[2];
    const float* Wd    = (const float*)d_in[3];
    const float* bn1g  = (const float*)d_in[4];
    const float* bn1b  = (const float*)d_in[5];
    const float* bn1m  = (const float*)d_in[6];
    const float* bn1v  = (const float*)d_in[7];
    const float* K1    = (const float*)d_in[8];
    const float* G1    = (const float*)d_in[9];
    const float* B1    = (const float*)d_in[10];
    const float* M1    = (const float*)d_in[11];
    const float* V1    = (const float*)d_in[12];
    const float* K2    = (const float*)d_in[13];
    const float* G2    = (const float*)d_in[14];
    const float* B2    = (const float*)d_in[15];
    const float* M2    = (const float*)d_in[16];
    const float* V2    = (const float*)d_in[17];
    const float* K3    = (const float*)d_in[18];
    float* out = (float*)d_out;

    const int smB = A1_B + 2 * WB1 * 8;   // 23680 + 40960 = 64640
    const int smC = A2_B + 2 * WB2 * 8;   // 16000 + 73728 = 89728
    const int smD = (D_IN_SH + D_W_SH) * 4;
    cudaFuncSetAttribute(k_conv1, cudaFuncAttributeMaxDynamicSharedMemorySize, smB);
    cudaFuncSetAttribute(k_conv2, cudaFuncAttributeMaxDynamicSharedMemorySize, smC);
    cudaFuncSetAttribute(k_conv3, cudaFuncAttributeMaxDynamicSharedMemorySize, smD);

    k_bucket<<<1, 512>>>(labels);
    k_dense<<<dim3(49, 64), 256>>>(noise, labels, emb, Wd, bn1g, bn1b, bn1m, bn1v);
    k_packw1<<<dim3(25, 16, 10), 256>>>(K1);
    k_packw2<<<dim3(25, 16, 10), 256>>>(K2);
    k_emb<<<10, 256>>>(K1, emb);
    k_conv1<<<dim3(32, 4, 10), 224, smB>>>(G1, B1, M1, V1);
    k_conv2<<<dim3(32, 2, 10), 224, smC>>>(G2, B2, M2, V2);
    k_conv3<<<BATCH, 256, smD>>>(labels, K3, out);
}

// round 12
// speedup vs baseline: 9.7912x; 1.5597x over previous
#include <cuda_runtime.h>
#include <cuda_fp16.h>
#include <cstdint>

#define BATCH 512
#define NOISE 100
#define EMBD  50
#define NCLS  10
#define C1    256
#define C2    128

typedef unsigned long long ull;

// ---------------- scratch ----------------
__device__ __align__(16) __half g_a0[BATCH * 49 * 256];
__device__ __align__(16) __half g_a1[BATCH * 49 * 256];
__device__ __align__(16) __half g_a2[BATCH * 196 * C2];
__device__ __align__(16) float  g_embf[NCLS * 49 * 256];
// packed weight fragments (fp16 hi only): [c][chunk16][tap25][ntile][lane32]
__device__ __align__(16) uint2  g_W1[(size_t)NCLS * 16 * 25 * 32 * 32];
__device__ __align__(16) uint2  g_W2[(size_t)NCLS * 16 * 25 * 16 * 32];
__device__ int g_perm[BATCH];
__device__ int g_cnt[NCLS];
__device__ int g_off[NCLS];

__device__ __forceinline__ float lrelu(float x) { return x >= 0.f ? x : 0.3f * x; }

__device__ __forceinline__ ull splat2(float a) {
    ull d; unsigned ai = __float_as_uint(a);
    asm("mov.b64 %0, {%1, %1};" : "=l"(d) : "r"(ai));
    return d;
}
__device__ __forceinline__ void ffma2(ull& c, ull a, ull b) {
    asm("fma.rn.f32x2 %0, %1, %2, %3;" : "=l"(c) : "l"(a), "l"(b), "l"(c));
}
__device__ __forceinline__ float2 unpk(ull v) {
    unsigned lo, hi;
    asm("mov.b64 {%0, %1}, %2;" : "=r"(lo), "=r"(hi) : "l"(v));
    return make_float2(__uint_as_float(lo), __uint_as_float(hi));
}

#define CP_COMMIT() asm volatile("cp.async.commit_group;" ::: "memory")
#define CP_WAIT0()  asm volatile("cp.async.wait_group 0;" ::: "memory")

__device__ __forceinline__ void cp16(uint32_t saddr, const void* g) {
    asm volatile("cp.async.cg.shared.global [%0], [%1], 16;" :: "r"(saddr), "l"(g) : "memory");
}

#define LDSM4(a, addr) asm volatile( \
    "ldmatrix.sync.aligned.m8n8.x4.shared.b16 {%0,%1,%2,%3}, [%4];" \
    : "=r"(a[0]), "=r"(a[1]), "=r"(a[2]), "=r"(a[3]) : "r"(addr))

#define MMA(d, a, b) asm volatile( \
    "mma.sync.aligned.m16n8k16.row.col.f32.f16.f16.f32 " \
    "{%0,%1,%2,%3}, {%4,%5,%6,%7}, {%8,%9}, {%0,%1,%2,%3};" \
    : "+f"(d[0]), "+f"(d[1]), "+f"(d[2]), "+f"(d[3]) \
    : "r"(a[0]), "r"(a[1]), "r"(a[2]), "r"(a[3]), "r"(b.x), "r"(b.y))

// one tap slice = 8nt * 32 lanes = 256 uint2 = 2 KB
__device__ __forceinline__ void stage_w(uint32_t dsm, const uint2* src, int t) {
    for (int q = t; q < 128; q += 224) cp16(dsm + (uint32_t)q * 16u, (const char*)src + q * 16);
}

// =====================================================================
__global__ __launch_bounds__(512) void k_bucket(const int* __restrict__ labels)
{
    __shared__ int scnt[NCLS], scur[NCLS];
    int t = threadIdx.x;
    if (t < NCLS) scnt[t] = 0;
    __syncthreads();
    int c = labels[t];
    atomicAdd(&scnt[c], 1);
    __syncthreads();
    if (t == 0) {
        int run = 0;
        for (int k = 0; k < NCLS; k++) { g_off[k] = run; scur[k] = run; g_cnt[k] = scnt[k]; run += scnt[k]; }
    }
    __syncthreads();
    int pos = atomicAdd(&scur[c], 1);
    g_perm[pos] = t;
}

// =====================================================================
// dense + BN + LReLU -> act0 fp16
// =====================================================================
__global__ __launch_bounds__(256) void k_dense(
    const float* __restrict__ noise, const int* __restrict__ labels,
    const float* __restrict__ emb,   const float* __restrict__ Wd,
    const float* __restrict__ bn_g,  const float* __restrict__ bn_b,
    const float* __restrict__ bn_m,  const float* __restrict__ bn_v)
{
    __shared__ __align__(8) float2 xs2[150 * 4];
    const int t  = threadIdx.x;
    const int bx = blockIdx.x;
    const int b0 = blockIdx.y * 8;

    for (int idx = t; idx < 8 * 150; idx += 256) {
        int s = idx / 150, k = idx - s * 150;
        int bb = b0 + s;
        float val = (k < NOISE) ? noise[bb * NOISE + k]
                                : emb[labels[bb] * EMBD + (k - NOISE)];
        ((float*)&xs2[k * 4 + (s >> 1)])[s & 1] = val;
    }
    __syncthreads();

    const int j = bx * 256 + t;
    ull acc2[4];
#pragma unroll
    for (int pr = 0; pr < 4; pr++) acc2[pr] = 0ull;
    for (int k = 0; k < 150; k++) {
        ull ws = splat2(Wd[k * 12544 + j]);
#pragma unroll
        for (int pr = 0; pr < 4; pr++) {
            ull a = *(const ull*)&xs2[k * 4 + pr];
            ffma2(acc2[pr], a, ws);
        }
    }
    const float sc = rsqrtf(bn_v[j] + 1e-3f) * bn_g[j];
    const float mm = bn_m[j];
    const float bb = bn_b[j];
#pragma unroll
    for (int pr = 0; pr < 4; pr++) {
        float2 v = unpk(acc2[pr]);
#pragma unroll
        for (int h2 = 0; h2 < 2; h2++) {
            float y = lrelu(((h2 ? v.y : v.x) - mm) * sc + bb);
            g_a0[(size_t)(b0 + pr * 2 + h2) * (49 * 256) + j] = __float2half(y);
        }
    }
}

// =====================================================================
// coalesced weight packing (fp16 hi fragments only)
// =====================================================================
#define TP1 257
__global__ __launch_bounds__(256) void k_packw1(const float* __restrict__ K1)
{
    __shared__ float tile[16 * TP1];
    int tap = blockIdx.x, chunk = blockIdx.y, c = blockIdx.z;
    int t = threadIdx.x;
    const float* src = K1 + (((size_t)c * 25 + tap) * 306 + chunk * 16) * 256;
    for (int idx = t; idx < 4096; idx += 256) {
        int r = idx >> 8, col = idx & 255;
        tile[r * TP1 + col] = src[idx];
    }
    __syncthreads();
    int lane = t & 31, wp = t >> 5;
    int k0 = (lane & 3) * 2, nq = lane >> 2;
    for (int nt = wp; nt < 32; nt += 8) {
        int n = nt * 8 + nq;
        __half2 p0 = __halves2half2(__float2half(tile[(k0 + 0) * TP1 + n]),
                                    __float2half(tile[(k0 + 1) * TP1 + n]));
        __half2 p1 = __halves2half2(__float2half(tile[(k0 + 8) * TP1 + n]),
                                    __float2half(tile[(k0 + 9) * TP1 + n]));
        uint2 hi; hi.x = *(uint32_t*)&p0; hi.y = *(uint32_t*)&p1;
        g_W1[((((size_t)c * 16 + chunk) * 25 + tap) * 32 + nt) * 32 + lane] = hi;
    }
}

#define TP2 129
__global__ __launch_bounds__(256) void k_packw2(const float* __restrict__ K2)
{
    __shared__ float tile[16 * TP2];
    int tap = blockIdx.x, chunk = blockIdx.y, c = blockIdx.z;
    int t = threadIdx.x;
    const float* src = K2 + (((size_t)c * 25 + tap) * 256 + chunk * 16) * 128;
    for (int idx = t; idx < 2048; idx += 256) {
        int r = idx >> 7, col = idx & 127;
        tile[r * TP2 + col] = src[idx];
    }
    __syncthreads();
    int lane = t & 31, wp = t >> 5;
    int k0 = (lane & 3) * 2, nq = lane >> 2;
    for (int nt = wp; nt < 16; nt += 8) {
        int n = nt * 8 + nq;
        __half2 p0 = __halves2half2(__float2half(tile[(k0 + 0) * TP2 + n]),
                                    __float2half(tile[(k0 + 1) * TP2 + n]));
        __half2 p1 = __halves2half2(__float2half(tile[(k0 + 8) * TP2 + n]),
                                    __float2half(tile[(k0 + 9) * TP2 + n]));
        uint2 hi; hi.x = *(uint32_t*)&p0; hi.y = *(uint32_t*)&p1;
        g_W2[((((size_t)c * 16 + chunk) * 25 + tap) * 16 + nt) * 32 + lane] = hi;
    }
}

// =====================================================================
// fused emb fold: per-class conv1 bias field
// =====================================================================
__global__ __launch_bounds__(256) void k_emb(
    const float* __restrict__ K1, const float* __restrict__ emb)
{
    __shared__ float es[EMBD];
    __shared__ float tw[25][256];
    int c = blockIdx.x, t = threadIdx.x;
    if (t < EMBD) es[t] = emb[c * EMBD + t];
    __syncthreads();
    for (int tap = 0; tap < 25; tap++) {
        const float* kb = K1 + (((size_t)c * 25 + tap) * 306 + 256) * 256 + t;
        float acc = 0.f;
#pragma unroll 10
        for (int e = 0; e < EMBD; e++) acc += es[e] * kb[(size_t)e * 256];
        tw[tap][t] = acc;
    }
    __syncthreads();
    for (int p = 0; p < 49; p++) {
        int i = p / 7, j = p - 7 * i;
        float acc = 0.f;
        for (int di = 0; di < 5; di++) {
            int ii = i + di - 2; if ((unsigned)ii >= 7u) continue;
            for (int dj = 0; dj < 5; dj++) {
                int jj = j + dj - 2; if ((unsigned)jj >= 7u) continue;
                acc += tw[di * 5 + dj][t];
            }
        }
        g_embf[((size_t)c * 49 + p) * 256 + t] = acc;
    }
}

// =====================================================================
// conv1: implicit GEMM, 4 samples/CTA, 64 co, 7 warps, burst-staged weights
// A grid: [4 samples][11x11 padded], row pitch 24 halves, plane 2960 halves
// (conflict-free ldmatrix). burst = 5 taps, 80 bursts.
// =====================================================================
#define SPL1   2960
#define A1_FP  (4 * SPL1)
#define A1_B   (A1_FP * 2)             // 23680 bytes
#define WB1    1280                     // uint2 per burst buffer (5 taps x 256)

__global__ __launch_bounds__(224, 2) void k_conv1(
    const float* __restrict__ G1, const float* __restrict__ B1,
    const float* __restrict__ M1, const float* __restrict__ V1)
{
    extern __shared__ __align__(16) char smraw[];
    __half* A = (__half*)smraw;
    uint2*  W = (uint2*)(smraw + A1_B);

    const int c = blockIdx.z;
    const int n_c = g_cnt[c];
    const int stile = blockIdx.x;
    if (stile * 4 >= n_c) return;
    const int by = blockIdx.y;
    const int co0 = by * 64;
    const int t = threadIdx.x, lane = t & 31, wrp = t >> 5;
    const int base = g_off[c];

    int samp[4]; bool sok[4];
#pragma unroll
    for (int s = 0; s < 4; s++) {
        int idx = stile * 4 + s;
        sok[s] = idx < n_c;
        samp[s] = g_perm[base + (idx < n_c ? idx : n_c - 1)];
    }

    const uint32_t a_u32 = (uint32_t)__cvta_generic_to_shared(A);
    const uint32_t w_u32 = (uint32_t)__cvta_generic_to_shared(W);

    const int lm = lane & 15;
    const int ljx = lm >> 2, ls = lm & 3;
    const int koff = (lane >> 4) * 8;
    const uint32_t lb0 = a_u32 + (uint32_t)((ls * SPL1 + ljx * 24 + koff) * 2);
    const uint32_t lb1 = a_u32 + (uint32_t)((ls * SPL1 + (ljx + 4) * 24 + koff) * 2);

    for (int q = t; q < A1_FP / 8; q += 224) ((uint4*)A)[q] = make_uint4(0, 0, 0, 0);
    __syncthreads();

    float acc[2][8][4];
#pragma unroll
    for (int mb = 0; mb < 2; mb++)
#pragma unroll
        for (int nt = 0; nt < 8; nt++)
#pragma unroll
            for (int u = 0; u < 4; u++) acc[mb][nt][u] = 0.f;

    const uint2* wbase = g_W1 + ((size_t)c * 16 * 25 * 32 + (size_t)by * 8) * 32;

    // refill chunk 0
    for (int q = t; q < 196; q += 224) {
        int s = q / 49, p = q - s * 49;
        const __half* src = g_a0 + ((size_t)samp[s] * 49 + p) * 256;
        int pi_ = p / 7, pj_ = p - 7 * pi_;
        __half* dst = A + s * SPL1 + ((2 + pi_) * 11 + 2 + pj_) * 24;
        ((uint4*)dst)[0] = ((const uint4*)src)[0];
        ((uint4*)dst)[1] = ((const uint4*)src)[1];
    }
    // prefetch burst 0
    for (int tp = 0; tp < 5; tp++)
        stage_w(w_u32 + (uint32_t)tp * 2048u, wbase + (size_t)tp * 1024, t);
    CP_COMMIT();

    int bi = 0;
    for (int chunk = 0; chunk < 16; chunk++) {
        for (int di = 0; di < 5; di++) {
            CP_WAIT0();
            __syncthreads();
            if (bi + 1 < 80) {
                int nb = bi + 1, nch = nb / 5, ndi = nb - nch * 5;
                uint32_t dst = w_u32 + (uint32_t)(nb & 1) * (WB1 * 8);
                for (int tp = 0; tp < 5; tp++)
                    stage_w(dst + (uint32_t)tp * 2048u,
                            wbase + ((size_t)nch * 25 + ndi * 5 + tp) * 1024, t);
            }
            CP_COMMIT();
            if (di == 0 && chunk > 0) {
                const int ci0 = chunk * 16;
                for (int q = t; q < 196; q += 224) {
                    int s = q / 49, p = q - s * 49;
                    const __half* src = g_a0 + ((size_t)samp[s] * 49 + p) * 256 + ci0;
                    int pi_ = p / 7, pj_ = p - 7 * pi_;
                    __half* dst = A + s * SPL1 + ((2 + pi_) * 11 + 2 + pj_) * 24;
                    ((uint4*)dst)[0] = ((const uint4*)src)[0];
                    ((uint4*)dst)[1] = ((const uint4*)src)[1];
                }
                __syncthreads();
            }

            const uint2* wburst = W + (bi & 1) * WB1;
#pragma unroll
            for (int dj = 0; dj < 5; dj++) {
                const uint32_t goff = (uint32_t)(((wrp + di) * 11 + dj) * 48);
                uint32_t a0[4], a1[4];
                LDSM4(a0, lb0 + goff);
                LDSM4(a1, lb1 + goff);
                const uint2* wb = wburst + dj * 256 + lane;
#pragma unroll
                for (int nt = 0; nt < 8; nt++) {
                    uint2 b = wb[nt * 32];
                    MMA(acc[0][nt], a0, b);
                    MMA(acc[1][nt], a1, b);
                }
            }
            bi++;
        }
    }

    // epilogue: + E, BN, LReLU -> act1 fp16
    const int g_ = lane >> 2;
    const int n_ = (lane & 3) * 2;
#pragma unroll
    for (int mb = 0; mb < 2; mb++) {
#pragma unroll
        for (int nt = 0; nt < 8; nt++) {
            int co = co0 + nt * 8 + n_;
            float2 gg = *(const float2*)(G1 + c * 256 + co);
            float2 bb = *(const float2*)(B1 + c * 256 + co);
            float2 mm = *(const float2*)(M1 + c * 256 + co);
            float2 vv = *(const float2*)(V1 + c * 256 + co);
            float sx = rsqrtf(vv.x + 1e-3f) * gg.x;
            float sy = rsqrtf(vv.y + 1e-3f) * gg.y;
#pragma unroll
            for (int h = 0; h < 2; h++) {
                int m = mb * 16 + g_ + h * 8;
                int jx = m >> 2, s = m & 3;
                if (jx < 7 && sok[s]) {
                    int pos = wrp * 7 + jx;
                    float2 E = *(const float2*)(g_embf + ((size_t)c * 49 + pos) * 256 + co);
                    float y0 = lrelu((acc[mb][nt][h * 2 + 0] + E.x - mm.x) * sx + bb.x);
                    float y1 = lrelu((acc[mb][nt][h * 2 + 1] + E.y - mm.y) * sy + bb.y);
                    *(__half2*)(g_a1 + ((size_t)samp[s] * 49 + pos) * 256 + co) =
                        __halves2half2(__float2half(y0), __float2half(y1));
                }
            }
        }
    }
}

// =====================================================================
// conv2: parity-decomposed implicit GEMM, 4 samples/CTA, 64 co
// =====================================================================
#define SPL2   2000
#define A2_FP  (4 * SPL2)
#define A2_B   (A2_FP * 2)             // 16000 bytes
#define WB2    2304                     // uint2 per burst buffer (9 taps x 256 max)

__global__ __launch_bounds__(224, 2) void k_conv2(
    const float* __restrict__ G2, const float* __restrict__ B2,
    const float* __restrict__ M2, const float* __restrict__ V2)
{
    extern __shared__ __align__(16) char smraw[];
    __half* A = (__half*)smraw;
    uint2*  W = (uint2*)(smraw + A2_B);

    const int c = blockIdx.z;
    const int n_c = g_cnt[c];
    const int stile = blockIdx.x;
    if (stile * 4 >= n_c) return;
    const int by = blockIdx.y;
    const int co0 = by * 64;
    const int t = threadIdx.x, lane = t & 31, wrp = t >> 5;
    const int base = g_off[c];

    int samp[4]; bool sok[4];
#pragma unroll
    for (int s = 0; s < 4; s++) {
        int idx = stile * 4 + s;
        sok[s] = idx < n_c;
        samp[s] = g_perm[base + (idx < n_c ? idx : n_c - 1)];
    }

    const uint32_t a_u32 = (uint32_t)__cvta_generic_to_shared(A);
    const uint32_t w_u32 = (uint32_t)__cvta_generic_to_shared(W);
    const int lm = lane & 15;
    const int ljx = lm >> 2, ls = lm & 3;
    const int koff = (lane >> 4) * 8;
    const uint32_t lb0 = a_u32 + (uint32_t)((ls * SPL2 + ljx * 24 + koff) * 2);
    const uint32_t lb1 = a_u32 + (uint32_t)((ls * SPL2 + (ljx + 4) * 24 + koff) * 2);

    for (int q = t; q < A2_FP / 8; q += 224) ((uint4*)A)[q] = make_uint4(0, 0, 0, 0);
    __syncthreads();

    const uint2* wcls = g_W2 + ((size_t)c * 16 * 25 * 16 + (size_t)by * 8) * 32;
    const int g_ = lane >> 2;
    const int n_ = (lane & 3) * 2;

    for (int pp = 0; pp < 4; pp++) {
        const int pi = pp >> 1, pj = pp & 1;
        const int ni = (pi == 0) ? 2 : 3, nj = (pj == 0) ? 2 : 3;

        float acc[2][8][4];
#pragma unroll
        for (int mb = 0; mb < 2; mb++)
#pragma unroll
            for (int nt = 0; nt < 8; nt++)
#pragma unroll
                for (int u = 0; u < 4; u++) acc[mb][nt][u] = 0.f;

        // prefetch chunk 0 taps of this parity into buffer 0
        {
            int tc = 0;
            for (int ui = 0; ui < ni; ui++) {
                int ddi = (pi == 0) ? (1 + 2 * ui) : (2 * ui);
                for (int uj = 0; uj < nj; uj++) {
                    int ddj = (pj == 0) ? (1 + 2 * uj) : (2 * uj);
                    stage_w(w_u32 + (uint32_t)tc * 2048u,
                            wcls + (size_t)(ddi * 5 + ddj) * 512, t);
                    tc++;
                }
            }
        }
        CP_COMMIT();

        for (int chunk = 0; chunk < 16; chunk++) {
            CP_WAIT0();
            __syncthreads();
            if (chunk < 15) {
                uint32_t dst = w_u32 + (uint32_t)((chunk + 1) & 1) * (WB2 * 8);
                const uint2* wch = wcls + (size_t)(chunk + 1) * 25 * 512;
                int tc = 0;
                for (int ui = 0; ui < ni; ui++) {
                    int ddi = (pi == 0) ? (1 + 2 * ui) : (2 * ui);
                    for (int uj = 0; uj < nj; uj++) {
                        int ddj = (pj == 0) ? (1 + 2 * uj) : (2 * uj);
                        stage_w(dst + (uint32_t)tc * 2048u,
                                wch + (size_t)(ddi * 5 + ddj) * 512, t);
                        tc++;
                    }
                }
            }
            CP_COMMIT();
            {
                const int ci0 = chunk * 16;
                for (int q = t; q < 196; q += 224) {
                    int s = q / 49, p = q - s * 49;
                    const __half* src = g_a1 + ((size_t)samp[s] * 49 + p) * 256 + ci0;
                    int pi_ = p / 7, pj_ = p - 7 * pi_;
                    __half* dst = A + s * SPL2 + ((1 + pi_) * 9 + 1 + pj_) * 24;
                    ((uint4*)dst)[0] = ((const uint4*)src)[0];
                    ((uint4*)dst)[1] = ((const uint4*)src)[1];
                }
            }
            __syncthreads();

            const uint2* wburst = W + (chunk & 1) * WB2;
            int tc = 0;
            for (int ui = 0; ui < ni; ui++) {
                int ddi = (pi == 0) ? (1 + 2 * ui) : (2 * ui);
                int si = (ddi >> 1) - 1;
                for (int uj = 0; uj < nj; uj++) {
                    int ddj = (pj == 0) ? (1 + 2 * uj) : (2 * uj);
                    int sj = (ddj >> 1) - 1;
                    const uint32_t goff = (uint32_t)(((1 + wrp + si) * 9 + 1 + sj) * 48);
                    uint32_t a0[4], a1[4];
                    LDSM4(a0, lb0 + goff);
                    LDSM4(a1, lb1 + goff);
                    const uint2* wb = wburst + tc * 256 + lane;
#pragma unroll
                    for (int nt = 0; nt < 8; nt++) {
                        uint2 b = wb[nt * 32];
                        MMA(acc[0][nt], a0, b);
                        MMA(acc[1][nt], a1, b);
                    }
                    tc++;
                }
            }
        }

        // epilogue this parity -> act2 fp16
#pragma unroll
        for (int mb = 0; mb < 2; mb++) {
#pragma unroll
            for (int nt = 0; nt < 8; nt++) {
                int co = co0 + nt * 8 + n_;
                float2 gg = *(const float2*)(G2 + c * 128 + co);
                float2 bb = *(const float2*)(B2 + c * 128 + co);
                float2 mm = *(const float2*)(M2 + c * 128 + co);
                float2 vv = *(const float2*)(V2 + c * 128 + co);
                float sx = rsqrtf(vv.x + 1e-3f) * gg.x;
                float sy = rsqrtf(vv.y + 1e-3f) * gg.y;
#pragma unroll
                for (int h = 0; h < 2; h++) {
                    int m = mb * 16 + g_ + h * 8;
                    int jx = m >> 2, s = m & 3;
                    if (jx < 7 && sok[s]) {
                        int oi = 2 * wrp + pi, oj = 2 * jx + pj;
                        float y0 = lrelu((acc[mb][nt][h * 2 + 0] - mm.x) * sx + bb.x);
                        float y1 = lrelu((acc[mb][nt][h * 2 + 1] - mm.y) * sy + bb.y);
                        *(__half2*)(g_a2 + ((size_t)samp[s] * 196 + oi * 14 + oj) * 128 + co) =
                            __halves2half2(__float2half(y0), __float2half(y1));
                    }
                }
            }
        }
    }
}

// =====================================================================
// conv3: 5x5 s2, 128 -> 1, tanh (fp16 inputs)
// =====================================================================
#define D_IN_B (196 * C2 * 2)          // 50176 bytes
#define D_W_B  (25 * C2 * 4)           // 12800 bytes

__global__ __launch_bounds__(256, 2) void k_conv3(
    const int* __restrict__ labels, const float* __restrict__ K3,
    float* __restrict__ out)
{
    extern __shared__ __align__(16) char smraw[];
    __half* in_h = (__half*)smraw;
    float*  w_s  = (float*)(smraw + D_IN_B);
    const int b = blockIdx.x;
    const int t = threadIdx.x;
    const int c = labels[b];

    const uint4* a2 = (const uint4*)(g_a2 + (size_t)b * (196 * C2));
    for (int q = t; q < 196 * 16; q += 256) ((uint4*)in_h)[q] = a2[q];
    const float4* k4 = (const float4*)(K3 + (size_t)c * 25 * C2);
    for (int q = t; q < 25 * 32; q += 256) ((float4*)w_s)[q] = k4[q];
    __syncthreads();

    for (int px = t; px < 784; px += 256) {
        const int oi = px / 28, oj = px - oi * 28;
        float acc = 0.f;
        for (int ddi = (oi & 1) ? 0 : 1; ddi < 5; ddi += 2) {
            int ii = (oi + ddi - 3) >> 1;
            if ((unsigned)ii >= 14u) continue;
            for (int ddj = (oj & 1) ? 0 : 1; ddj < 5; ddj += 2) {
                int jj = (oj + ddj - 3) >> 1;
                if ((unsigned)jj >= 14u) continue;
                const __half2* ip = (const __half2*)(in_h + (ii * 14 + jj) * C2);
                const float2* wp = (const float2*)(w_s + (ddi * 5 + ddj) * C2);
#pragma unroll 16
                for (int q = 0; q < 64; q++) {
                    float2 a = __half22float2(ip[q]);
                    float2 w = wp[q];
                    acc += a.x * w.x + a.y * w.y;
                }
            }
        }
        out[(size_t)b * 784 + px] = tanhf(acc);
    }
}

// =====================================================================
extern "C" void kernel_launch(void* const* d_in, const int* in_sizes, int n_in,
                              void* d_out, int out_size)
{
    const float* noise = (const float*)d_in[0];
    const int*   labels= (const int*)  d_in[1];
    const float* emb   = (const float*)d_in[2];
    const float* Wd    = (const float*)d_in[3];
    const float* bn1g  = (const float*)d_in[4];
    const float* bn1b  = (const float*)d_in[5];
    const float* bn1m  = (const float*)d_in[6];
    const float* bn1v  = (const float*)d_in[7];
    const float* K1    = (const float*)d_in[8];
    const float* G1    = (const float*)d_in[9];
    const float* B1    = (const float*)d_in[10];
    const float* M1    = (const float*)d_in[11];
    const float* V1    = (const float*)d_in[12];
    const float* K2    = (const float*)d_in[13];
    const float* G2    = (const float*)d_in[14];
    const float* B2    = (const float*)d_in[15];
    const float* M2    = (const float*)d_in[16];
    const float* V2    = (const float*)d_in[17];
    const float* K3    = (const float*)d_in[18];
    float* out = (float*)d_out;

    const int smB = A1_B + 2 * WB1 * 8;   // 23680 + 20480 = 44160
    const int smC = A2_B + 2 * WB2 * 8;   // 16000 + 36864 = 52864
    const int smD = D_IN_B + D_W_B;       // 62976
    cudaFuncSetAttribute(k_conv1, cudaFuncAttributeMaxDynamicSharedMemorySize, smB);
    cudaFuncSetAttribute(k_conv2, cudaFuncAttributeMaxDynamicSharedMemorySize, smC);
    cudaFuncSetAttribute(k_conv3, cudaFuncAttributeMaxDynamicSharedMemorySize, smD);

    k_bucket<<<1, 512>>>(labels);
    k_dense<<<dim3(49, 64), 256>>>(noise, labels, emb, Wd, bn1g, bn1b, bn1m, bn1v);
    k_packw1<<<dim3(25, 16, 10), 256>>>(K1);
    k_packw2<<<dim3(25, 16, 10), 256>>>(K2);
    k_emb<<<10, 256>>>(K1, emb);
    k_conv1<<<dim3(32, 4, 10), 224, smB>>>(G1, B1, M1, V1);
    k_conv2<<<dim3(32, 2, 10), 224, smC>>>(G2, B2, M2, V2);
    k_conv3<<<BATCH, 256, smD>>>(labels, K3, out);
}

// round 13
// speedup vs baseline: 10.3697x; 1.0591x over previous
#include <cuda_runtime.h>
#include <cuda_fp16.h>
#include <cstdint>

#define BATCH 512
#define NOISE 100
#define EMBD  50
#define NCLS  10
#define C1    256
#define C2    128

typedef unsigned long long ull;

// ---------------- scratch ----------------
__device__ __align__(16) __half g_a0[BATCH * 49 * 256];
__device__ __align__(16) __half g_a1[BATCH * 49 * 256];
__device__ __align__(16) __half g_a2[BATCH * 196 * C2];
__device__ __align__(16) float  g_embf[NCLS * 49 * 256];
__device__ __align__(16) float  g_embw[NCLS * 25 * 256];
// packed weight fragments (fp16): [c][chunk16][tap25][ntile][lane32]
__device__ __align__(16) uint2  g_W1[(size_t)NCLS * 16 * 25 * 32 * 32];
__device__ __align__(16) uint2  g_W2[(size_t)NCLS * 16 * 25 * 16 * 32];
__device__ int g_perm[BATCH];
__device__ int g_cnt[NCLS];
__device__ int g_off[NCLS];

__device__ __forceinline__ float lrelu(float x) { return x >= 0.f ? x : 0.3f * x; }

__device__ __forceinline__ ull splat2(float a) {
    ull d; unsigned ai = __float_as_uint(a);
    asm("mov.b64 %0, {%1, %1};" : "=l"(d) : "r"(ai));
    return d;
}
__device__ __forceinline__ void ffma2(ull& c, ull a, ull b) {
    asm("fma.rn.f32x2 %0, %1, %2, %3;" : "=l"(c) : "l"(a), "l"(b), "l"(c));
}
__device__ __forceinline__ float2 unpk(ull v) {
    unsigned lo, hi;
    asm("mov.b64 {%0, %1}, %2;" : "=r"(lo), "=r"(hi) : "l"(v));
    return make_float2(__uint_as_float(lo), __uint_as_float(hi));
}

#define LDSM4(a, addr) asm volatile( \
    "ldmatrix.sync.aligned.m8n8.x4.shared.b16 {%0,%1,%2,%3}, [%4];" \
    : "=r"(a[0]), "=r"(a[1]), "=r"(a[2]), "=r"(a[3]) : "r"(addr))

#define MMA(d, a, b) asm volatile( \
    "mma.sync.aligned.m16n8k16.row.col.f32.f16.f16.f32 " \
    "{%0,%1,%2,%3}, {%4,%5,%6,%7}, {%8,%9}, {%0,%1,%2,%3};" \
    : "+f"(d[0]), "+f"(d[1]), "+f"(d[2]), "+f"(d[3]) \
    : "r"(a[0]), "r"(a[1]), "r"(a[2]), "r"(a[3]), "r"(b.x), "r"(b.y))

// =====================================================================
__global__ __launch_bounds__(512) void k_bucket(const int* __restrict__ labels)
{
    __shared__ int scnt[NCLS], scur[NCLS];
    int t = threadIdx.x;
    if (t < NCLS) scnt[t] = 0;
    __syncthreads();
    int c = labels[t];
    atomicAdd(&scnt[c], 1);
    __syncthreads();
    if (t == 0) {
        int run = 0;
        for (int k = 0; k < NCLS; k++) { g_off[k] = run; scur[k] = run; g_cnt[k] = scnt[k]; run += scnt[k]; }
    }
    __syncthreads();
    int pos = atomicAdd(&scur[c], 1);
    g_perm[pos] = t;
}

// =====================================================================
// dense + BN + LReLU -> act0 fp16
// =====================================================================
__global__ __launch_bounds__(256) void k_dense(
    const float* __restrict__ noise, const int* __restrict__ labels,
    const float* __restrict__ emb,   const float* __restrict__ Wd,
    const float* __restrict__ bn_g,  const float* __restrict__ bn_b,
    const float* __restrict__ bn_m,  const float* __restrict__ bn_v)
{
    __shared__ __align__(8) float2 xs2[150 * 4];
    const int t  = threadIdx.x;
    const int bx = blockIdx.x;
    const int b0 = blockIdx.y * 8;

    for (int idx = t; idx < 8 * 150; idx += 256) {
        int s = idx / 150, k = idx - s * 150;
        int bb = b0 + s;
        float val = (k < NOISE) ? noise[bb * NOISE + k]
                                : emb[labels[bb] * EMBD + (k - NOISE)];
        ((float*)&xs2[k * 4 + (s >> 1)])[s & 1] = val;
    }
    __syncthreads();

    const int j = bx * 256 + t;
    ull acc2[4];
#pragma unroll
    for (int pr = 0; pr < 4; pr++) acc2[pr] = 0ull;
    for (int k = 0; k < 150; k++) {
        ull ws = splat2(Wd[k * 12544 + j]);
#pragma unroll
        for (int pr = 0; pr < 4; pr++) {
            ull a = *(const ull*)&xs2[k * 4 + pr];
            ffma2(acc2[pr], a, ws);
        }
    }
    const float sc = rsqrtf(bn_v[j] + 1e-3f) * bn_g[j];
    const float mm = bn_m[j];
    const float bb = bn_b[j];
#pragma unroll
    for (int pr = 0; pr < 4; pr++) {
        float2 v = unpk(acc2[pr]);
#pragma unroll
        for (int h2 = 0; h2 < 2; h2++) {
            float y = lrelu(((h2 ? v.y : v.x) - mm) * sc + bb);
            g_a0[(size_t)(b0 + pr * 2 + h2) * (49 * 256) + j] = __float2half(y);
        }
    }
}

// =====================================================================
// coalesced weight packing (fp16 fragments)
// =====================================================================
#define TP1 257
__global__ __launch_bounds__(256) void k_packw1(const float* __restrict__ K1)
{
    __shared__ float tile[16 * TP1];
    int tap = blockIdx.x, chunk = blockIdx.y, c = blockIdx.z;
    int t = threadIdx.x;
    const float* src = K1 + (((size_t)c * 25 + tap) * 306 + chunk * 16) * 256;
    for (int idx = t; idx < 4096; idx += 256) {
        int r = idx >> 8, col = idx & 255;
        tile[r * TP1 + col] = src[idx];
    }
    __syncthreads();
    int lane = t & 31, wp = t >> 5;
    int k0 = (lane & 3) * 2, nq = lane >> 2;
    for (int nt = wp; nt < 32; nt += 8) {
        int n = nt * 8 + nq;
        __half2 p0 = __halves2half2(__float2half(tile[(k0 + 0) * TP1 + n]),
                                    __float2half(tile[(k0 + 1) * TP1 + n]));
        __half2 p1 = __halves2half2(__float2half(tile[(k0 + 8) * TP1 + n]),
                                    __float2half(tile[(k0 + 9) * TP1 + n]));
        uint2 hi; hi.x = *(uint32_t*)&p0; hi.y = *(uint32_t*)&p1;
        g_W1[((((size_t)c * 16 + chunk) * 25 + tap) * 32 + nt) * 32 + lane] = hi;
    }
}

#define TP2 129
__global__ __launch_bounds__(256) void k_packw2(const float* __restrict__ K2)
{
    __shared__ float tile[16 * TP2];
    int tap = blockIdx.x, chunk = blockIdx.y, c = blockIdx.z;
    int t = threadIdx.x;
    const float* src = K2 + (((size_t)c * 25 + tap) * 256 + chunk * 16) * 128;
    for (int idx = t; idx < 2048; idx += 256) {
        int r = idx >> 7, col = idx & 127;
        tile[r * TP2 + col] = src[idx];
    }
    __syncthreads();
    int lane = t & 31, wp = t >> 5;
    int k0 = (lane & 3) * 2, nq = lane >> 2;
    for (int nt = wp; nt < 16; nt += 8) {
        int n = nt * 8 + nq;
        __half2 p0 = __halves2half2(__float2half(tile[(k0 + 0) * TP2 + n]),
                                    __float2half(tile[(k0 + 1) * TP2 + n]));
        __half2 p1 = __halves2half2(__float2half(tile[(k0 + 8) * TP2 + n]),
                                    __float2half(tile[(k0 + 9) * TP2 + n]));
        uint2 hi; hi.x = *(uint32_t*)&p0; hi.y = *(uint32_t*)&p1;
        g_W2[((((size_t)c * 16 + chunk) * 25 + tap) * 16 + nt) * 32 + lane] = hi;
    }
}

// =====================================================================
// emb fold (split two-kernel version — wide grids, latency-tolerant)
// =====================================================================
__global__ __launch_bounds__(256) void k_embw(
    const float* __restrict__ K1, const float* __restrict__ emb)
{
    __shared__ float es[EMBD];
    int tap = blockIdx.x, c = blockIdx.y, t = threadIdx.x;
    if (t < EMBD) es[t] = emb[c * EMBD + t];
    __syncthreads();
    const float* kb = K1 + (((size_t)c * 25 + tap) * 306 + 256) * 256 + t;
    float acc = 0.f;
#pragma unroll 10
    for (int e = 0; e < EMBD; e++) acc += es[e] * kb[(size_t)e * 256];
    g_embw[((size_t)c * 25 + tap) * 256 + t] = acc;
}

__global__ __launch_bounds__(256) void k_embe(const float* dummy)
{
    int p = blockIdx.x, c = blockIdx.y, t = threadIdx.x;
    int i = p / 7, j = p - 7 * i;
    float acc = 0.f;
    for (int di = 0; di < 5; di++) {
        int ii = i + di - 2; if ((unsigned)ii >= 7u) continue;
        for (int dj = 0; dj < 5; dj++) {
            int jj = j + dj - 2; if ((unsigned)jj >= 7u) continue;
            acc += g_embw[((size_t)c * 25 + di * 5 + dj) * 256 + t];
        }
    }
    g_embf[((size_t)c * 49 + p) * 256 + t] = acc;
}

// =====================================================================
// conv1: implicit GEMM, 4 samples/CTA, 64 co, 7 warps.
// A in smem (conflict-free ldmatrix layout); B fragments via direct LDG
// (warp-uniform -> L1 broadcast; whole packed W fits L2). Barriers only
// at the 16 A-chunk refills.
// =====================================================================
#define SPL1   2960
#define A1_FP  (4 * SPL1)
#define A1_B   (A1_FP * 2)             // 23680 bytes

__global__ __launch_bounds__(224, 2) void k_conv1(
    const float* __restrict__ G1, const float* __restrict__ B1,
    const float* __restrict__ M1, const float* __restrict__ V1)
{
    extern __shared__ __align__(16) char smraw[];
    __half* A = (__half*)smraw;

    const int c = blockIdx.z;
    const int n_c = g_cnt[c];
    const int stile = blockIdx.x;
    if (stile * 4 >= n_c) return;
    const int by = blockIdx.y;
    const int co0 = by * 64;
    const int t = threadIdx.x, lane = t & 31, wrp = t >> 5;
    const int base = g_off[c];

    int samp[4]; bool sok[4];
#pragma unroll
    for (int s = 0; s < 4; s++) {
        int idx = stile * 4 + s;
        sok[s] = idx < n_c;
        samp[s] = g_perm[base + (idx < n_c ? idx : n_c - 1)];
    }

    const uint32_t a_u32 = (uint32_t)__cvta_generic_to_shared(A);
    const int lm = lane & 15;
    const int ljx = lm >> 2, ls = lm & 3;
    const int koff = (lane >> 4) * 8;
    const uint32_t lb0 = a_u32 + (uint32_t)((ls * SPL1 + ljx * 24 + koff) * 2);
    const uint32_t lb1 = a_u32 + (uint32_t)((ls * SPL1 + (ljx + 4) * 24 + koff) * 2);

    for (int q = t; q < A1_FP / 8; q += 224) ((uint4*)A)[q] = make_uint4(0, 0, 0, 0);

    float acc[2][8][4];
#pragma unroll
    for (int mb = 0; mb < 2; mb++)
#pragma unroll
        for (int nt = 0; nt < 8; nt++)
#pragma unroll
            for (int u = 0; u < 4; u++) acc[mb][nt][u] = 0.f;

    // per-lane weight pointer base (by co-tile slice of 8 nt)
    const uint2* wbase = g_W1 + ((size_t)c * 16 * 25 * 32 + (size_t)by * 8) * 32 + lane;

    for (int chunk = 0; chunk < 16; chunk++) {
        const int ci0 = chunk * 16;
        __syncthreads();
        for (int q = t; q < 196; q += 224) {
            int s = q / 49, p = q - s * 49;
            const __half* src = g_a0 + ((size_t)samp[s] * 49 + p) * 256 + ci0;
            int pi_ = p / 7, pj_ = p - 7 * pi_;
            __half* dst = A + s * SPL1 + ((2 + pi_) * 11 + 2 + pj_) * 24;
            ((uint4*)dst)[0] = ((const uint4*)src)[0];
            ((uint4*)dst)[1] = ((const uint4*)src)[1];
        }
        __syncthreads();

        const uint2* wch = wbase + (size_t)chunk * 25 * 1024;
#pragma unroll
        for (int di = 0; di < 5; di++) {
#pragma unroll
            for (int dj = 0; dj < 5; dj++) {
                const uint32_t goff = (uint32_t)(((wrp + di) * 11 + dj) * 48);
                uint32_t a0[4], a1[4];
                LDSM4(a0, lb0 + goff);
                LDSM4(a1, lb1 + goff);
                const uint2* wt = wch + (di * 5 + dj) * 1024;
                uint2 bfr[8];
#pragma unroll
                for (int nt = 0; nt < 8; nt++) bfr[nt] = __ldg(wt + nt * 32);
#pragma unroll
                for (int nt = 0; nt < 8; nt++) {
                    MMA(acc[0][nt], a0, bfr[nt]);
                    MMA(acc[1][nt], a1, bfr[nt]);
                }
            }
        }
    }

    // epilogue: + E, BN, LReLU -> act1 fp16
    const int g_ = lane >> 2;
    const int n_ = (lane & 3) * 2;
#pragma unroll
    for (int mb = 0; mb < 2; mb++) {
#pragma unroll
        for (int nt = 0; nt < 8; nt++) {
            int co = co0 + nt * 8 + n_;
            float2 gg = *(const float2*)(G1 + c * 256 + co);
            float2 bb = *(const float2*)(B1 + c * 256 + co);
            float2 mm = *(const float2*)(M1 + c * 256 + co);
            float2 vv = *(const float2*)(V1 + c * 256 + co);
            float sx = rsqrtf(vv.x + 1e-3f) * gg.x;
            float sy = rsqrtf(vv.y + 1e-3f) * gg.y;
#pragma unroll
            for (int h = 0; h < 2; h++) {
                int m = mb * 16 + g_ + h * 8;
                int jx = m >> 2, s = m & 3;
                if (jx < 7 && sok[s]) {
                    int pos = wrp * 7 + jx;
                    float2 E = *(const float2*)(g_embf + ((size_t)c * 49 + pos) * 256 + co);
                    float y0 = lrelu((acc[mb][nt][h * 2 + 0] + E.x - mm.x) * sx + bb.x);
                    float y1 = lrelu((acc[mb][nt][h * 2 + 1] + E.y - mm.y) * sy + bb.y);
                    *(__half2*)(g_a1 + ((size_t)samp[s] * 49 + pos) * 256 + co) =
                        __halves2half2(__float2half(y0), __float2half(y1));
                }
            }
        }
    }
}

// =====================================================================
// conv2: parity-decomposed implicit GEMM, 4 samples/CTA, 64 co, LDG weights
// =====================================================================
#define SPL2   2000
#define A2_FP  (4 * SPL2)
#define A2_B   (A2_FP * 2)             // 16000 bytes

__global__ __launch_bounds__(224, 2) void k_conv2(
    const float* __restrict__ G2, const float* __restrict__ B2,
    const float* __restrict__ M2, const float* __restrict__ V2)
{
    extern __shared__ __align__(16) char smraw[];
    __half* A = (__half*)smraw;

    const int c = blockIdx.z;
    const int n_c = g_cnt[c];
    const int stile = blockIdx.x;
    if (stile * 4 >= n_c) return;
    const int by = blockIdx.y;
    const int co0 = by * 64;
    const int t = threadIdx.x, lane = t & 31, wrp = t >> 5;
    const int base = g_off[c];

    int samp[4]; bool sok[4];
#pragma unroll
    for (int s = 0; s < 4; s++) {
        int idx = stile * 4 + s;
        sok[s] = idx < n_c;
        samp[s] = g_perm[base + (idx < n_c ? idx : n_c - 1)];
    }

    const uint32_t a_u32 = (uint32_t)__cvta_generic_to_shared(A);
    const int lm = lane & 15;
    const int ljx = lm >> 2, ls = lm & 3;
    const int koff = (lane >> 4) * 8;
    const uint32_t lb0 = a_u32 + (uint32_t)((ls * SPL2 + ljx * 24 + koff) * 2);
    const uint32_t lb1 = a_u32 + (uint32_t)((ls * SPL2 + (ljx + 4) * 24 + koff) * 2);

    for (int q = t; q < A2_FP / 8; q += 224) ((uint4*)A)[q] = make_uint4(0, 0, 0, 0);

    const uint2* wcls = g_W2 + ((size_t)c * 16 * 25 * 16 + (size_t)by * 8) * 32 + lane;
    const int g_ = lane >> 2;
    const int n_ = (lane & 3) * 2;

    // acc for all 4 parities is too many regs; loop parity outer, chunk inner.
    for (int pp = 0; pp < 4; pp++) {
        const int pi = pp >> 1, pj = pp & 1;
        const int ni = (pi == 0) ? 2 : 3, nj = (pj == 0) ? 2 : 3;

        float acc[2][8][4];
#pragma unroll
        for (int mb = 0; mb < 2; mb++)
#pragma unroll
            for (int nt = 0; nt < 8; nt++)
#pragma unroll
                for (int u = 0; u < 4; u++) acc[mb][nt][u] = 0.f;

        for (int chunk = 0; chunk < 16; chunk++) {
            const int ci0 = chunk * 16;
            __syncthreads();
            for (int q = t; q < 196; q += 224) {
                int s = q / 49, p = q - s * 49;
                const __half* src = g_a1 + ((size_t)samp[s] * 49 + p) * 256 + ci0;
                int pi_ = p / 7, pj_ = p - 7 * pi_;
                __half* dst = A + s * SPL2 + ((1 + pi_) * 9 + 1 + pj_) * 24;
                ((uint4*)dst)[0] = ((const uint4*)src)[0];
                ((uint4*)dst)[1] = ((const uint4*)src)[1];
            }
            __syncthreads();

            const uint2* wch = wcls + (size_t)chunk * 25 * 512;
            for (int ui = 0; ui < ni; ui++) {
                int ddi = (pi == 0) ? (1 + 2 * ui) : (2 * ui);
                int si = (ddi >> 1) - 1;
                for (int uj = 0; uj < nj; uj++) {
                    int ddj = (pj == 0) ? (1 + 2 * uj) : (2 * uj);
                    int sj = (ddj >> 1) - 1;
                    const uint32_t goff = (uint32_t)(((1 + wrp + si) * 9 + 1 + sj) * 48);
                    uint32_t a0[4], a1[4];
                    LDSM4(a0, lb0 + goff);
                    LDSM4(a1, lb1 + goff);
                    const uint2* wt = wch + (ddi * 5 + ddj) * 512;
                    uint2 bfr[8];
#pragma unroll
                    for (int nt = 0; nt < 8; nt++) bfr[nt] = __ldg(wt + nt * 32);
#pragma unroll
                    for (int nt = 0; nt < 8; nt++) {
                        MMA(acc[0][nt], a0, bfr[nt]);
                        MMA(acc[1][nt], a1, bfr[nt]);
                    }
                }
            }
        }

        // epilogue this parity -> act2 fp16
#pragma unroll
        for (int mb = 0; mb < 2; mb++) {
#pragma unroll
            for (int nt = 0; nt < 8; nt++) {
                int co = co0 + nt * 8 + n_;
                float2 gg = *(const float2*)(G2 + c * 128 + co);
                float2 bb = *(const float2*)(B2 + c * 128 + co);
                float2 mm = *(const float2*)(M2 + c * 128 + co);
                float2 vv = *(const float2*)(V2 + c * 128 + co);
                float sx = rsqrtf(vv.x + 1e-3f) * gg.x;
                float sy = rsqrtf(vv.y + 1e-3f) * gg.y;
#pragma unroll
                for (int h = 0; h < 2; h++) {
                    int m = mb * 16 + g_ + h * 8;
                    int jx = m >> 2, s = m & 3;
                    if (jx < 7 && sok[s]) {
                        int oi = 2 * wrp + pi, oj = 2 * jx + pj;
                        float y0 = lrelu((acc[mb][nt][h * 2 + 0] - mm.x) * sx + bb.x);
                        float y1 = lrelu((acc[mb][nt][h * 2 + 1] - mm.y) * sy + bb.y);
                        *(__half2*)(g_a2 + ((size_t)samp[s] * 196 + oi * 14 + oj) * 128 + co) =
                            __halves2half2(__float2half(y0), __float2half(y1));
                    }
                }
            }
        }
    }
}

// =====================================================================
// conv3: 5x5 s2, 128 -> 1, tanh (fp16 inputs)
// =====================================================================
#define D_IN_B (196 * C2 * 2)          // 50176 bytes
#define D_W_B  (25 * C2 * 4)           // 12800 bytes

__global__ __launch_bounds__(256, 2) void k_conv3(
    const int* __restrict__ labels, const float* __restrict__ K3,
    float* __restrict__ out)
{
    extern __shared__ __align__(16) char smraw[];
    __half* in_h = (__half*)smraw;
    float*  w_s  = (float*)(smraw + D_IN_B);
    const int b = blockIdx.x;
    const int t = threadIdx.x;
    const int c = labels[b];

    const uint4* a2 = (const uint4*)(g_a2 + (size_t)b * (196 * C2));
    for (int q = t; q < 196 * 16; q += 256) ((uint4*)in_h)[q] = a2[q];
    const float4* k4 = (const float4*)(K3 + (size_t)c * 25 * C2);
    for (int q = t; q < 25 * 32; q += 256) ((float4*)w_s)[q] = k4[q];
    __syncthreads();

    for (int px = t; px < 784; px += 256) {
        const int oi = px / 28, oj = px - oi * 28;
        float acc = 0.f;
        for (int ddi = (oi & 1) ? 0 : 1; ddi < 5; ddi += 2) {
            int ii = (oi + ddi - 3) >> 1;
            if ((unsigned)ii >= 14u) continue;
            for (int ddj = (oj & 1) ? 0 : 1; ddj < 5; ddj += 2) {
                int jj = (oj + ddj - 3) >> 1;
                if ((unsigned)jj >= 14u) continue;
                const __half2* ip = (const __half2*)(in_h + (ii * 14 + jj) * C2);
                const float2* wp = (const float2*)(w_s + (ddi * 5 + ddj) * C2);
#pragma unroll 16
                for (int q = 0; q < 64; q++) {
                    float2 a = __half22float2(ip[q]);
                    float2 w = wp[q];
                    acc += a.x * w.x + a.y * w.y;
                }
            }
        }
        out[(size_t)b * 784 + px] = tanhf(acc);
    }
}

// =====================================================================
extern "C" void kernel_launch(void* const* d_in, const int* in_sizes, int n_in,
                              void* d_out, int out_size)
{
    const float* noise = (const float*)d_in[0];
    const int*   labels= (const int*)  d_in[1];
    const float* emb   = (const float*)d_in[2];
    const float* Wd    = (const float*)d_in[3];
    const float* bn1g  = (const float*)d_in[4];
    const float* bn1b  = (const float*)d_in[5];
    const float* bn1m  = (const float*)d_in[6];
    const float* bn1v  = (const float*)d_in[7];
    const float* K1    = (const float*)d_in[8];
    const float* G1    = (const float*)d_in[9];
    const float* B1    = (const float*)d_in[10];
    const float* M1    = (const float*)d_in[11];
    const float* V1    = (const float*)d_in[12];
    const float* K2    = (const float*)d_in[13];
    const float* G2    = (const float*)d_in[14];
    const float* B2    = (const float*)d_in[15];
    const float* M2    = (const float*)d_in[16];
    const float* V2    = (const float*)d_in[17];
    const float* K3    = (const float*)d_in[18];
    float* out = (float*)d_out;

    const int smB = A1_B;                 // 23680
    const int smC = A2_B;                 // 16000
    const int smD = D_IN_B + D_W_B;       // 62976
    cudaFuncSetAttribute(k_conv1, cudaFuncAttributeMaxDynamicSharedMemorySize, smB);
    cudaFuncSetAttribute(k_conv2, cudaFuncAttributeMaxDynamicSharedMemorySize, smC);
    cudaFuncSetAttribute(k_conv3, cudaFuncAttributeMaxDynamicSharedMemorySize, smD);

    // order keeps conv1 at profile launch index 5 (-s 5 -c 1)
    k_dense<<<dim3(49, 64), 256>>>(noise, labels, emb, Wd, bn1g, bn1b, bn1m, bn1v);
    k_bucket<<<1, 512>>>(labels);
    k_packw1<<<dim3(25, 16, 10), 256>>>(K1);
    k_embw<<<dim3(25, 10), 256>>>(K1, emb);
    k_embe<<<dim3(49, 10), 256>>>(nullptr);
    k_conv1<<<dim3(32, 4, 10), 224, smB>>>(G1, B1, M1, V1);
    k_packw2<<<dim3(25, 16, 10), 256>>>(K2);
    k_conv2<<<dim3(32, 2, 10), 224, smC>>>(G2, B2, M2, V2);
    k_conv3<<<BATCH, 256, smD>>>(labels, K3, out);
}

// round 14
// speedup vs baseline: 11.2180x; 1.0818x over previous
#include <cuda_runtime.h>
#include <cuda_fp16.h>
#include <cstdint>

#define BATCH 512
#define NOISE 100
#define EMBD  50
#define NCLS  10
#define C1    256
#define C2    128

typedef unsigned long long ull;

// ---------------- scratch ----------------
__device__ __align__(16) __half g_a0[BATCH * 49 * 256];
__device__ __align__(16) __half g_a1[BATCH * 49 * 256];
__device__ __align__(16) __half g_a2[BATCH * 196 * C2];
__device__ __align__(16) float  g_embf[NCLS * 49 * 256];
__device__ __align__(16) float  g_embw[NCLS * 25 * 256];
// pair-packed weight fragments: uint4 = {frag(nt=2p) , frag(nt=2p+1)} per lane
// g_W1: [c][chunk16][tap25][ntp16][lane32]   g_W2: [c][chunk16][tap25][ntp8][lane32]
__device__ __align__(16) uint4  g_W1[(size_t)NCLS * 16 * 25 * 16 * 32];
__device__ __align__(16) uint4  g_W2[(size_t)NCLS * 16 * 25 * 8 * 32];
__device__ int g_perm[BATCH];
__device__ int g_cnt[NCLS];
__device__ int g_off[NCLS];

__device__ __forceinline__ float lrelu(float x) { return x >= 0.f ? x : 0.3f * x; }

__device__ __forceinline__ ull splat2(float a) {
    ull d; unsigned ai = __float_as_uint(a);
    asm("mov.b64 %0, {%1, %1};" : "=l"(d) : "r"(ai));
    return d;
}
__device__ __forceinline__ void ffma2(ull& c, ull a, ull b) {
    asm("fma.rn.f32x2 %0, %1, %2, %3;" : "=l"(c) : "l"(a), "l"(b), "l"(c));
}
__device__ __forceinline__ float2 unpk(ull v) {
    unsigned lo, hi;
    asm("mov.b64 {%0, %1}, %2;" : "=r"(lo), "=r"(hi) : "l"(v));
    return make_float2(__uint_as_float(lo), __uint_as_float(hi));
}

#define LDSM4(a, addr) asm volatile( \
    "ldmatrix.sync.aligned.m8n8.x4.shared.b16 {%0,%1,%2,%3}, [%4];" \
    : "=r"(a[0]), "=r"(a[1]), "=r"(a[2]), "=r"(a[3]) : "r"(addr))

#define MMA2(d, a, bx_, by_) asm volatile( \
    "mma.sync.aligned.m16n8k16.row.col.f32.f16.f16.f32 " \
    "{%0,%1,%2,%3}, {%4,%5,%6,%7}, {%8,%9}, {%0,%1,%2,%3};" \
    : "+f"(d[0]), "+f"(d[1]), "+f"(d[2]), "+f"(d[3]) \
    : "r"(a[0]), "r"(a[1]), "r"(a[2]), "r"(a[3]), "r"(bx_), "r"(by_))

__device__ __forceinline__ uint32_t h2pack(float a, float b) {
    __half2 p = __halves2half2(__float2half(a), __float2half(b));
    return *(uint32_t*)&p;
}

// =====================================================================
__global__ __launch_bounds__(512) void k_bucket(const int* __restrict__ labels)
{
    __shared__ int scnt[NCLS], scur[NCLS];
    int t = threadIdx.x;
    if (t < NCLS) scnt[t] = 0;
    __syncthreads();
    int c = labels[t];
    atomicAdd(&scnt[c], 1);
    __syncthreads();
    if (t == 0) {
        int run = 0;
        for (int k = 0; k < NCLS; k++) { g_off[k] = run; scur[k] = run; g_cnt[k] = scnt[k]; run += scnt[k]; }
    }
    __syncthreads();
    int pos = atomicAdd(&scur[c], 1);
    g_perm[pos] = t;
}

// =====================================================================
// dense + BN + LReLU -> act0 fp16
// =====================================================================
__global__ __launch_bounds__(256) void k_dense(
    const float* __restrict__ noise, const int* __restrict__ labels,
    const float* __restrict__ emb,   const float* __restrict__ Wd,
    const float* __restrict__ bn_g,  const float* __restrict__ bn_b,
    const float* __restrict__ bn_m,  const float* __restrict__ bn_v)
{
    __shared__ __align__(8) float2 xs2[150 * 4];
    const int t  = threadIdx.x;
    const int bx = blockIdx.x;
    const int b0 = blockIdx.y * 8;

    for (int idx = t; idx < 8 * 150; idx += 256) {
        int s = idx / 150, k = idx - s * 150;
        int bb = b0 + s;
        float val = (k < NOISE) ? noise[bb * NOISE + k]
                                : emb[labels[bb] * EMBD + (k - NOISE)];
        ((float*)&xs2[k * 4 + (s >> 1)])[s & 1] = val;
    }
    __syncthreads();

    const int j = bx * 256 + t;
    ull acc2[4];
#pragma unroll
    for (int pr = 0; pr < 4; pr++) acc2[pr] = 0ull;
    for (int k = 0; k < 150; k++) {
        ull ws = splat2(Wd[k * 12544 + j]);
#pragma unroll
        for (int pr = 0; pr < 4; pr++) {
            ull a = *(const ull*)&xs2[k * 4 + pr];
            ffma2(acc2[pr], a, ws);
        }
    }
    const float sc = rsqrtf(bn_v[j] + 1e-3f) * bn_g[j];
    const float mm = bn_m[j];
    const float bb = bn_b[j];
#pragma unroll
    for (int pr = 0; pr < 4; pr++) {
        float2 v = unpk(acc2[pr]);
#pragma unroll
        for (int h2 = 0; h2 < 2; h2++) {
            float y = lrelu(((h2 ? v.y : v.x) - mm) * sc + bb);
            g_a0[(size_t)(b0 + pr * 2 + h2) * (49 * 256) + j] = __float2half(y);
        }
    }
}

// =====================================================================
// coalesced weight packing (fp16, pair-packed uint4 fragments)
// =====================================================================
#define TP1 260
__global__ __launch_bounds__(256) void k_packw1(const float* __restrict__ K1)
{
    __shared__ float tile[16 * TP1];
    int tap = blockIdx.x, chunk = blockIdx.y, c = blockIdx.z;
    int t = threadIdx.x;
    const float* src = K1 + (((size_t)c * 25 + tap) * 306 + chunk * 16) * 256;
    for (int idx = t; idx < 1024; idx += 256) {
        int r = idx >> 6, c4 = idx & 63;
        *(float4*)&tile[r * TP1 + c4 * 4] = ((const float4*)src)[idx];
    }
    __syncthreads();
    int lane = t & 31, wp = t >> 5;
    int k0 = (lane & 3) * 2, nq = lane >> 2;
    for (int ntp = wp; ntp < 16; ntp += 8) {
        int nA = ntp * 16 + nq;
        int nB = nA + 8;
        uint4 o;
        o.x = h2pack(tile[(k0 + 0) * TP1 + nA], tile[(k0 + 1) * TP1 + nA]);
        o.y = h2pack(tile[(k0 + 8) * TP1 + nA], tile[(k0 + 9) * TP1 + nA]);
        o.z = h2pack(tile[(k0 + 0) * TP1 + nB], tile[(k0 + 1) * TP1 + nB]);
        o.w = h2pack(tile[(k0 + 8) * TP1 + nB], tile[(k0 + 9) * TP1 + nB]);
        g_W1[((((size_t)c * 16 + chunk) * 25 + tap) * 16 + ntp) * 32 + lane] = o;
    }
}

#define TP2 132
__global__ __launch_bounds__(256) void k_packw2(const float* __restrict__ K2)
{
    __shared__ float tile[16 * TP2];
    int tap = blockIdx.x, chunk = blockIdx.y, c = blockIdx.z;
    int t = threadIdx.x;
    const float* src = K2 + (((size_t)c * 25 + tap) * 256 + chunk * 16) * 128;
    for (int idx = t; idx < 512; idx += 256) {
        int r = idx >> 5, c4 = idx & 31;
        *(float4*)&tile[r * TP2 + c4 * 4] = ((const float4*)src)[idx];
    }
    __syncthreads();
    int lane = t & 31, wp = t >> 5;
    int k0 = (lane & 3) * 2, nq = lane >> 2;
    if (wp < 8) {
        int ntp = wp;
        int nA = ntp * 16 + nq;
        int nB = nA + 8;
        uint4 o;
        o.x = h2pack(tile[(k0 + 0) * TP2 + nA], tile[(k0 + 1) * TP2 + nA]);
        o.y = h2pack(tile[(k0 + 8) * TP2 + nA], tile[(k0 + 9) * TP2 + nA]);
        o.z = h2pack(tile[(k0 + 0) * TP2 + nB], tile[(k0 + 1) * TP2 + nB]);
        o.w = h2pack(tile[(k0 + 8) * TP2 + nB], tile[(k0 + 9) * TP2 + nB]);
        g_W2[((((size_t)c * 16 + chunk) * 25 + tap) * 8 + ntp) * 32 + lane] = o;
    }
}

// =====================================================================
// emb fold
// =====================================================================
__global__ __launch_bounds__(256) void k_embw(
    const float* __restrict__ K1, const float* __restrict__ emb)
{
    __shared__ float es[EMBD];
    int tap = blockIdx.x, c = blockIdx.y, t = threadIdx.x;
    if (t < EMBD) es[t] = emb[c * EMBD + t];
    __syncthreads();
    const float* kb = K1 + (((size_t)c * 25 + tap) * 306 + 256) * 256 + t;
    float acc = 0.f;
#pragma unroll 10
    for (int e = 0; e < EMBD; e++) acc += es[e] * kb[(size_t)e * 256];
    g_embw[((size_t)c * 25 + tap) * 256 + t] = acc;
}

__global__ __launch_bounds__(256) void k_embe(const float* dummy)
{
    int p = blockIdx.x, c = blockIdx.y, t = threadIdx.x;
    int i = p / 7, j = p - 7 * i;
    float acc = 0.f;
    for (int di = 0; di < 5; di++) {
        int ii = i + di - 2; if ((unsigned)ii >= 7u) continue;
        for (int dj = 0; dj < 5; dj++) {
            int jj = j + dj - 2; if ((unsigned)jj >= 7u) continue;
            acc += g_embw[((size_t)c * 25 + di * 5 + dj) * 256 + t];
        }
    }
    g_embf[((size_t)c * 49 + p) * 256 + t] = acc;
}

// =====================================================================
// conv1: implicit GEMM, 4 samples/CTA, 64 co, 7 warps; pair-packed LDG.128 weights
// =====================================================================
#define SPL1   2960
#define A1_FP  (4 * SPL1)
#define A1_B   (A1_FP * 2)             // 23680 bytes

__global__ __launch_bounds__(224, 2) void k_conv1(
    const float* __restrict__ G1, const float* __restrict__ B1,
    const float* __restrict__ M1, const float* __restrict__ V1)
{
    extern __shared__ __align__(16) char smraw[];
    __half* A = (__half*)smraw;

    const int c = blockIdx.z;
    const int n_c = g_cnt[c];
    const int stile = blockIdx.x;
    if (stile * 4 >= n_c) return;
    const int by = blockIdx.y;
    const int co0 = by * 64;
    const int t = threadIdx.x, lane = t & 31, wrp = t >> 5;
    const int base = g_off[c];

    int samp[4]; bool sok[4];
#pragma unroll
    for (int s = 0; s < 4; s++) {
        int idx = stile * 4 + s;
        sok[s] = idx < n_c;
        samp[s] = g_perm[base + (idx < n_c ? idx : n_c - 1)];
    }

    const uint32_t a_u32 = (uint32_t)__cvta_generic_to_shared(A);
    const int lm = lane & 15;
    const int ljx = lm >> 2, ls = lm & 3;
    const int koff = (lane >> 4) * 8;
    const uint32_t lb0 = a_u32 + (uint32_t)((ls * SPL1 + ljx * 24 + koff) * 2);
    const uint32_t lb1 = a_u32 + (uint32_t)((ls * SPL1 + (ljx + 4) * 24 + koff) * 2);

    for (int q = t; q < A1_FP / 8; q += 224) ((uint4*)A)[q] = make_uint4(0, 0, 0, 0);

    float acc[2][8][4];
#pragma unroll
    for (int mb = 0; mb < 2; mb++)
#pragma unroll
        for (int nt = 0; nt < 8; nt++)
#pragma unroll
            for (int u = 0; u < 4; u++) acc[mb][nt][u] = 0.f;

    // per-lane pair-packed weight base: CTA covers ntp [by*4, by*4+4)
    const uint4* wbase = g_W1 + ((size_t)c * 16 * 25 * 16 + (size_t)by * 4) * 32 + lane;

    for (int chunk = 0; chunk < 16; chunk++) {
        const int ci0 = chunk * 16;
        __syncthreads();
        for (int q = t; q < 196; q += 224) {
            int s = q / 49, p = q - s * 49;
            const __half* src = g_a0 + ((size_t)samp[s] * 49 + p) * 256 + ci0;
            int pi_ = p / 7, pj_ = p - 7 * pi_;
            __half* dst = A + s * SPL1 + ((2 + pi_) * 11 + 2 + pj_) * 24;
            ((uint4*)dst)[0] = ((const uint4*)src)[0];
            ((uint4*)dst)[1] = ((const uint4*)src)[1];
        }
        __syncthreads();

        const uint4* wch = wbase + (size_t)chunk * 25 * 16 * 32;
#pragma unroll
        for (int di = 0; di < 5; di++) {
#pragma unroll
            for (int dj = 0; dj < 5; dj++) {
                const uint32_t goff = (uint32_t)(((wrp + di) * 11 + dj) * 48);
                uint32_t a0[4], a1[4];
                LDSM4(a0, lb0 + goff);
                LDSM4(a1, lb1 + goff);
                const uint4* wt = wch + (di * 5 + dj) * (16 * 32);
                uint4 bf[4];
#pragma unroll
                for (int p = 0; p < 4; p++) bf[p] = __ldg(wt + p * 32);
#pragma unroll
                for (int p = 0; p < 4; p++) {
                    MMA2(acc[0][2 * p + 0], a0, bf[p].x, bf[p].y);
                    MMA2(acc[1][2 * p + 0], a1, bf[p].x, bf[p].y);
                    MMA2(acc[0][2 * p + 1], a0, bf[p].z, bf[p].w);
                    MMA2(acc[1][2 * p + 1], a1, bf[p].z, bf[p].w);
                }
            }
        }
    }

    // epilogue: + E, BN, LReLU -> act1 fp16
    const int g_ = lane >> 2;
    const int n_ = (lane & 3) * 2;
#pragma unroll
    for (int mb = 0; mb < 2; mb++) {
#pragma unroll
        for (int nt = 0; nt < 8; nt++) {
            int co = co0 + nt * 8 + n_;
            float2 gg = *(const float2*)(G1 + c * 256 + co);
            float2 bb = *(const float2*)(B1 + c * 256 + co);
            float2 mm = *(const float2*)(M1 + c * 256 + co);
            float2 vv = *(const float2*)(V1 + c * 256 + co);
            float sx = rsqrtf(vv.x + 1e-3f) * gg.x;
            float sy = rsqrtf(vv.y + 1e-3f) * gg.y;
#pragma unroll
            for (int h = 0; h < 2; h++) {
                int m = mb * 16 + g_ + h * 8;
                int jx = m >> 2, s = m & 3;
                if (jx < 7 && sok[s]) {
                    int pos = wrp * 7 + jx;
                    float2 E = *(const float2*)(g_embf + ((size_t)c * 49 + pos) * 256 + co);
                    float y0 = lrelu((acc[mb][nt][h * 2 + 0] + E.x - mm.x) * sx + bb.x);
                    float y1 = lrelu((acc[mb][nt][h * 2 + 1] + E.y - mm.y) * sy + bb.y);
                    *(__half2*)(g_a1 + ((size_t)samp[s] * 49 + pos) * 256 + co) =
                        __halves2half2(__float2half(y0), __float2half(y1));
                }
            }
        }
    }
}

// =====================================================================
// conv2: parity-decomposed implicit GEMM, 4 samples/CTA, 64 co, LDG.128 weights
// =====================================================================
#define SPL2   2000
#define A2_FP  (4 * SPL2)
#define A2_B   (A2_FP * 2)             // 16000 bytes

__global__ __launch_bounds__(224, 2) void k_conv2(
    const float* __restrict__ G2, const float* __restrict__ B2,
    const float* __restrict__ M2, const float* __restrict__ V2)
{
    extern __shared__ __align__(16) char smraw[];
    __half* A = (__half*)smraw;

    const int c = blockIdx.z;
    const int n_c = g_cnt[c];
    const int stile = blockIdx.x;
    if (stile * 4 >= n_c) return;
    const int by = blockIdx.y;
    const int co0 = by * 64;
    const int t = threadIdx.x, lane = t & 31, wrp = t >> 5;
    const int base = g_off[c];

    int samp[4]; bool sok[4];
#pragma unroll
    for (int s = 0; s < 4; s++) {
        int idx = stile * 4 + s;
        sok[s] = idx < n_c;
        samp[s] = g_perm[base + (idx < n_c ? idx : n_c - 1)];
    }

    const uint32_t a_u32 = (uint32_t)__cvta_generic_to_shared(A);
    const int lm = lane & 15;
    const int ljx = lm >> 2, ls = lm & 3;
    const int koff = (lane >> 4) * 8;
    const uint32_t lb0 = a_u32 + (uint32_t)((ls * SPL2 + ljx * 24 + koff) * 2);
    const uint32_t lb1 = a_u32 + (uint32_t)((ls * SPL2 + (ljx + 4) * 24 + koff) * 2);

    for (int q = t; q < A2_FP / 8; q += 224) ((uint4*)A)[q] = make_uint4(0, 0, 0, 0);

    const uint4* wcls = g_W2 + ((size_t)c * 16 * 25 * 8 + (size_t)by * 4) * 32 + lane;
    const int g_ = lane >> 2;
    const int n_ = (lane & 3) * 2;

    for (int pp = 0; pp < 4; pp++) {
        const int pi = pp >> 1, pj = pp & 1;
        const int ni = (pi == 0) ? 2 : 3, nj = (pj == 0) ? 2 : 3;

        float acc[2][8][4];
#pragma unroll
        for (int mb = 0; mb < 2; mb++)
#pragma unroll
            for (int nt = 0; nt < 8; nt++)
#pragma unroll
                for (int u = 0; u < 4; u++) acc[mb][nt][u] = 0.f;

        for (int chunk = 0; chunk < 16; chunk++) {
            const int ci0 = chunk * 16;
            __syncthreads();
            for (int q = t; q < 196; q += 224) {
                int s = q / 49, p = q - s * 49;
                const __half* src = g_a1 + ((size_t)samp[s] * 49 + p) * 256 + ci0;
                int pi_ = p / 7, pj_ = p - 7 * pi_;
                __half* dst = A + s * SPL2 + ((1 + pi_) * 9 + 1 + pj_) * 24;
                ((uint4*)dst)[0] = ((const uint4*)src)[0];
                ((uint4*)dst)[1] = ((const uint4*)src)[1];
            }
            __syncthreads();

            const uint4* wch = wcls + (size_t)chunk * 25 * 8 * 32;
            for (int ui = 0; ui < ni; ui++) {
                int ddi = (pi == 0) ? (1 + 2 * ui) : (2 * ui);
                int si = (ddi >> 1) - 1;
                for (int uj = 0; uj < nj; uj++) {
                    int ddj = (pj == 0) ? (1 + 2 * uj) : (2 * uj);
                    int sj = (ddj >> 1) - 1;
                    const uint32_t goff = (uint32_t)(((1 + wrp + si) * 9 + 1 + sj) * 48);
                    uint32_t a0[4], a1[4];
                    LDSM4(a0, lb0 + goff);
                    LDSM4(a1, lb1 + goff);
                    const uint4* wt = wch + (ddi * 5 + ddj) * (8 * 32);
                    uint4 bf[4];
#pragma unroll
                    for (int p = 0; p < 4; p++) bf[p] = __ldg(wt + p * 32);
#pragma unroll
                    for (int p = 0; p < 4; p++) {
                        MMA2(acc[0][2 * p + 0], a0, bf[p].x, bf[p].y);
                        MMA2(acc[1][2 * p + 0], a1, bf[p].x, bf[p].y);
                        MMA2(acc[0][2 * p + 1], a0, bf[p].z, bf[p].w);
                        MMA2(acc[1][2 * p + 1], a1, bf[p].z, bf[p].w);
                    }
                }
            }
        }

        // epilogue this parity -> act2 fp16
#pragma unroll
        for (int mb = 0; mb < 2; mb++) {
#pragma unroll
            for (int nt = 0; nt < 8; nt++) {
                int co = co0 + nt * 8 + n_;
                float2 gg = *(const float2*)(G2 + c * 128 + co);
                float2 bb = *(const float2*)(B2 + c * 128 + co);
                float2 mm = *(const float2*)(M2 + c * 128 + co);
                float2 vv = *(const float2*)(V2 + c * 128 + co);
                float sx = rsqrtf(vv.x + 1e-3f) * gg.x;
                float sy = rsqrtf(vv.y + 1e-3f) * gg.y;
#pragma unroll
                for (int h = 0; h < 2; h++) {
                    int m = mb * 16 + g_ + h * 8;
                    int jx = m >> 2, s = m & 3;
                    if (jx < 7 && sok[s]) {
                        int oi = 2 * wrp + pi, oj = 2 * jx + pj;
                        float y0 = lrelu((acc[mb][nt][h * 2 + 0] - mm.x) * sx + bb.x);
                        float y1 = lrelu((acc[mb][nt][h * 2 + 1] - mm.y) * sy + bb.y);
                        *(__half2*)(g_a2 + ((size_t)samp[s] * 196 + oi * 14 + oj) * 128 + co) =
                            __halves2half2(__float2half(y0), __float2half(y1));
                    }
                }
            }
        }
    }
}

// =====================================================================
// conv3: 5x5 s2, 128 -> 1, tanh (fp16 inputs)
// =====================================================================
#define D_IN_B (196 * C2 * 2)          // 50176 bytes
#define D_W_B  (25 * C2 * 4)           // 12800 bytes

__global__ __launch_bounds__(256, 2) void k_conv3(
    const int* __restrict__ labels, const float* __restrict__ K3,
    float* __restrict__ out)
{
    extern __shared__ __align__(16) char smraw[];
    __half* in_h = (__half*)smraw;
    float*  w_s  = (float*)(smraw + D_IN_B);
    const int b = blockIdx.x;
    const int t = threadIdx.x;
    const int c = labels[b];

    const uint4* a2 = (const uint4*)(g_a2 + (size_t)b * (196 * C2));
    for (int q = t; q < 196 * 16; q += 256) ((uint4*)in_h)[q] = a2[q];
    const float4* k4 = (const float4*)(K3 + (size_t)c * 25 * C2);
    for (int q = t; q < 25 * 32; q += 256) ((float4*)w_s)[q] = k4[q];
    __syncthreads();

    for (int px = t; px < 784; px += 256) {
        const int oi = px / 28, oj = px - oi * 28;
        float acc = 0.f;
        for (int ddi = (oi & 1) ? 0 : 1; ddi < 5; ddi += 2) {
            int ii = (oi + ddi - 3) >> 1;
            if ((unsigned)ii >= 14u) continue;
            for (int ddj = (oj & 1) ? 0 : 1; ddj < 5; ddj += 2) {
                int jj = (oj + ddj - 3) >> 1;
                if ((unsigned)jj >= 14u) continue;
                const __half2* ip = (const __half2*)(in_h + (ii * 14 + jj) * C2);
                const float2* wp = (const float2*)(w_s + (ddi * 5 + ddj) * C2);
#pragma unroll 16
                for (int q = 0; q < 64; q++) {
                    float2 a = __half22float2(ip[q]);
                    float2 w = wp[q];
                    acc += a.x * w.x + a.y * w.y;
                }
            }
        }
        out[(size_t)b * 784 + px] = tanhf(acc);
    }
}

// =====================================================================
extern "C" void kernel_launch(void* const* d_in, const int* in_sizes, int n_in,
                              void* d_out, int out_size)
{
    const float* noise = (const float*)d_in[0];
    const int*   labels= (const int*)  d_in[1];
    const float* emb   = (const float*)d_in[2];
    const float* Wd    = (const float*)d_in[3];
    const float* bn1g  = (const float*)d_in[4];
    const float* bn1b  = (const float*)d_in[5];
    const float* bn1m  = (const float*)d_in[6];
    const float* bn1v  = (const float*)d_in[7];
    const float* K1    = (const float*)d_in[8];
    const float* G1    = (const float*)d_in[9];
    const float* B1    = (const float*)d_in[10];
    const float* M1    = (const float*)d_in[11];
    const float* V1    = (const float*)d_in[12];
    const float* K2    = (const float*)d_in[13];
    const float* G2    = (const float*)d_in[14];
    const float* B2    = (const float*)d_in[15];
    const float* M2    = (const float*)d_in[16];
    const float* V2    = (const float*)d_in[17];
    const float* K3    = (const float*)d_in[18];
    float* out = (float*)d_out;

    const int smB = A1_B;                 // 23680
    const int smC = A2_B;                 // 16000
    const int smD = D_IN_B + D_W_B;       // 62976
    cudaFuncSetAttribute(k_conv1, cudaFuncAttributeMaxDynamicSharedMemorySize, smB);
    cudaFuncSetAttribute(k_conv2, cudaFuncAttributeMaxDynamicSharedMemorySize, smC);
    cudaFuncSetAttribute(k_conv3, cudaFuncAttributeMaxDynamicSharedMemorySize, smD);

    k_dense<<<dim3(49, 64), 256>>>(noise, labels, emb, Wd, bn1g, bn1b, bn1m, bn1v);
    k_bucket<<<1, 512>>>(labels);
    k_packw1<<<dim3(25, 16, 10), 256>>>(K1);
    k_embw<<<dim3(25, 10), 256>>>(K1, emb);
    k_embe<<<dim3(49, 10), 256>>>(nullptr);
    k_conv1<<<dim3(32, 4, 10), 224, smB>>>(G1, B1, M1, V1);
    k_packw2<<<dim3(25, 16, 10), 256>>>(K2);
    k_conv2<<<dim3(32, 2, 10), 224, smC>>>(G2, B2, M2, V2);
    k_conv3<<<BATCH, 256, smD>>>(labels, K3, out);
}